// round 10
// baseline (speedup 1.0000x reference)
#include <cuda_runtime.h>
#include <cuda_bf16.h>
#include <cstdint>

#define DIM     1024
#define NHEADS  16
#define HDIM    64
#define SEQ     2048
#define BATCH   4
#define NTOK    (BATCH * SEQ)          // 8192
// SCALE * log2(e) folded into Q so softmax uses exp2
#define QSCALE  0.18033688011112042f
#define NEGBIG  -1e9f

// -------- scratch (device globals: allocation-free) --------
__device__ __nv_bfloat16 g_qh[(size_t)BATCH * NHEADS * SEQ * HDIM]; // [B,H,S,D]
__device__ __nv_bfloat16 g_ql[(size_t)BATCH * NHEADS * SEQ * HDIM];
__device__ __nv_bfloat16 g_kh[(size_t)BATCH * NHEADS * SEQ * HDIM];
__device__ __nv_bfloat16 g_kl[(size_t)BATCH * NHEADS * SEQ * HDIM];
__device__ __nv_bfloat16 g_vh[(size_t)BATCH * NHEADS * HDIM * SEQ]; // [B,H,D,S] !
__device__ __nv_bfloat16 g_vl[(size_t)BATCH * NHEADS * HDIM * SEQ];
__device__ __nv_bfloat16 g_xh[(size_t)NTOK * DIM];             // x hi/lo
__device__ __nv_bfloat16 g_xl[(size_t)NTOK * DIM];
__device__ __nv_bfloat16 g_wqh[(size_t)3 * DIM * DIM];         // w_qkv^T [n][k]
__device__ __nv_bfloat16 g_wql[(size_t)3 * DIM * DIM];
__device__ __nv_bfloat16 g_wph[(size_t)DIM * DIM];             // w_proj^T [n][k]
__device__ __nv_bfloat16 g_wpl[(size_t)DIM * DIM];
__device__ __nv_bfloat16 g_ah[(size_t)NTOK * DIM];             // attn out hi/lo
__device__ __nv_bfloat16 g_al[(size_t)NTOK * DIM];

// ============================================================
// helpers
// ============================================================
__device__ __forceinline__ uint32_t smem_to_u32(const void* p) {
    uint32_t a;
    asm("{ .reg .u64 t; cvta.to.shared.u64 t, %1; cvt.u32.u64 %0, t; }"
        : "=r"(a) : "l"(p));
    return a;
}

__device__ __forceinline__ void bf16split(float v, unsigned short& h, unsigned short& l) {
    __nv_bfloat16 hb = __float2bfloat16(v);
    h = __bfloat16_as_ushort(hb);
    l = __bfloat16_as_ushort(__float2bfloat16(v - __bfloat162float(hb)));
}

// pack 2 floats into bf16x2 hi + residual bf16x2 lo ({lo16=x, hi16=y})
__device__ __forceinline__ void packsplit2(float x, float y, uint32_t& hi, uint32_t& lo) {
    uint32_t h;
    asm("cvt.rn.bf16x2.f32 %0, %1, %2;" : "=r"(h) : "f"(y), "f"(x));
    float fx = __uint_as_float(h << 16);
    float fy = __uint_as_float(h & 0xFFFF0000u);
    uint32_t l;
    float rx = x - fx, ry = y - fy;
    asm("cvt.rn.bf16x2.f32 %0, %1, %2;" : "=r"(l) : "f"(ry), "f"(rx));
    hi = h; lo = l;
}

__device__ __forceinline__ float ex2(float x) {
    float y;
    asm("ex2.approx.f32 %0, %1;" : "=f"(y) : "f"(x));
    return y;
}

__device__ __forceinline__ void ldsm4(uint32_t r[4], uint32_t addr) {
    asm volatile("ldmatrix.sync.aligned.m8n8.x4.shared.b16 {%0,%1,%2,%3}, [%4];"
        : "=r"(r[0]), "=r"(r[1]), "=r"(r[2]), "=r"(r[3]) : "r"(addr));
}

__device__ __forceinline__ void mma_bf16(float d[4], const uint32_t a[4],
                                         uint32_t b0, uint32_t b1) {
    asm volatile(
        "mma.sync.aligned.m16n8k16.row.col.f32.bf16.bf16.f32 "
        "{%0,%1,%2,%3}, {%4,%5,%6,%7}, {%8,%9}, {%0,%1,%2,%3};"
        : "+f"(d[0]), "+f"(d[1]), "+f"(d[2]), "+f"(d[3])
        : "r"(a[0]), "r"(a[1]), "r"(a[2]), "r"(a[3]), "r"(b0), "r"(b1));
}

#define CP_ASYNC16(dst, src) \
    asm volatile("cp.async.cg.shared.global [%0], [%1], 16;" \
        :: "r"(dst), "l"(src) : "memory")
#define CP_COMMIT() asm volatile("cp.async.commit_group;" ::: "memory")
#define CP_WAIT(n)  asm volatile("cp.async.wait_group %0;" :: "n"(n) : "memory")

// ============================================================
// Preprocess kernels
// ============================================================
__global__ void convert_split_kernel(const float* __restrict__ in,
                                     __nv_bfloat16* __restrict__ hi,
                                     __nv_bfloat16* __restrict__ lo, int n4)
{
    const int i = blockIdx.x * blockDim.x + threadIdx.x;
    if (i >= n4) return;
    float4 v = ((const float4*)in)[i];
    unsigned short h[4], l[4];
    bf16split(v.x, h[0], l[0]); bf16split(v.y, h[1], l[1]);
    bf16split(v.z, h[2], l[2]); bf16split(v.w, h[3], l[3]);
    ((uint2*)hi)[i] = make_uint2((uint32_t)h[0] | ((uint32_t)h[1] << 16),
                                 (uint32_t)h[2] | ((uint32_t)h[3] << 16));
    ((uint2*)lo)[i] = make_uint2((uint32_t)l[0] | ((uint32_t)l[1] << 16),
                                 (uint32_t)l[2] | ((uint32_t)l[3] << 16));
}

// in [K][N] fp32 -> out hi/lo [N][K] bf16
__global__ void transpose_split_kernel(const float* __restrict__ in,
                                       __nv_bfloat16* __restrict__ hiT,
                                       __nv_bfloat16* __restrict__ loT,
                                       int K, int N)
{
    __shared__ float t[32][33];
    const int tx = threadIdx.x, ty = threadIdx.y;
    const int k0 = blockIdx.y * 32, n0 = blockIdx.x * 32;
    #pragma unroll
    for (int j = 0; j < 4; j++)
        t[ty + j * 8][tx] = in[(size_t)(k0 + ty + j * 8) * N + n0 + tx];
    __syncthreads();
    #pragma unroll
    for (int j = 0; j < 4; j++) {
        const int nn = n0 + ty + j * 8;
        const int kk = k0 + tx;
        unsigned short h, l;
        bf16split(t[tx][ty + j * 8], h, l);
        hiT[(size_t)nn * K + kk] = __ushort_as_bfloat16(h);
        loT[(size_t)nn * K + kk] = __ushort_as_bfloat16(l);
    }
}

// ============================================================
// bf16x3 mma.sync GEMM: CTA 128x128, 256 threads (8 warps, 64x32 each),
// K=1024 in 64 chunks of 16, cp.async 4-STAGE ring (hides L2 latency),
// 48B padded rows, ONE sync per chunk, 2 CTAs/SM.
// ============================================================
#define TILE16     6144             // 128 rows * 48 B (32B data + 16B pad)
#define STAGE16    (4 * TILE16)     // Ah, Al, Bh, Bl = 24576
#define NSTAGE     4
#define GEMM_SMEM  (NSTAGE * STAGE16)   // 98304
#define NCHUNK     64

__device__ __forceinline__ void gemm_issue_chunk(
    const __nv_bfloat16* const gb[4], uint32_t dstbuf, int tid, int c)
{
    #pragma unroll
    for (int i = 0; i < 4; i++) {
        const int s    = tid + i * 256;
        const int tile = s >> 8;          // 256 segments per tile
        const int t2   = s & 255;
        const int row  = t2 >> 1;
        const int kg   = t2 & 1;
        const __nv_bfloat16* src = gb[tile] + (size_t)row * DIM + c * 16 + kg * 8;
        const uint32_t dst = dstbuf + tile * TILE16 + row * 48 + kg * 16;
        CP_ASYNC16(dst, src);
    }
    CP_COMMIT();
}

__device__ __forceinline__ void gemm_mainloop(
    const __nv_bfloat16* __restrict__ Ah, const __nv_bfloat16* __restrict__ Al,
    const __nv_bfloat16* __restrict__ Bh, const __nv_bfloat16* __restrict__ Bl,
    float acc[4][4][4], char* smem)
{
    const uint32_t smem_base = smem_to_u32(smem);
    const int tid  = threadIdx.x;
    const int lane = tid & 31;
    const int wid  = tid >> 5;        // 0..7
    const int wr   = wid >> 2;        // 0..1 -> 64 rows each
    const int wc   = wid & 3;         // 0..3 -> 32 cols each
    const int m0   = blockIdx.y * 128;
    const int n0   = blockIdx.x * 128;

    const __nv_bfloat16* gb[4] = {
        Ah + (size_t)m0 * DIM, Al + (size_t)m0 * DIM,
        Bh + (size_t)n0 * DIM, Bl + (size_t)n0 * DIM };

    const int arow = (lane & 7) + ((lane >> 3) & 1) * 8;
    const int a_kbit = (lane >> 4) & 1;
    const int brow = (lane & 7) + ((lane >> 4) & 1) * 8;
    const int b_kbit = (lane >> 3) & 1;

    const uint32_t a_lane = (uint32_t)((wr * 64 + arow) * 48 + a_kbit * 16);
    const uint32_t b_lane = (uint32_t)(2 * TILE16 + (wc * 32 + brow) * 48 + b_kbit * 16);

    // prologue: 3 chunks in flight
    gemm_issue_chunk(gb, smem_base + 0 * STAGE16, tid, 0);
    gemm_issue_chunk(gb, smem_base + 1 * STAGE16, tid, 1);
    gemm_issue_chunk(gb, smem_base + 2 * STAGE16, tid, 2);

    for (int c = 0; c < NCHUNK; c++) {
        const uint32_t stg = smem_base + (uint32_t)(c & 3) * STAGE16;

        if (c <= NCHUNK - 3)      { CP_WAIT(2); }
        else if (c == NCHUNK - 2) { CP_WAIT(1); }
        else                      { CP_WAIT(0); }
        __syncthreads();
        // issue-after-barrier: stage (c+3)&3 == (c-1)&3 was fully read during
        // compute(c-1), which every warp finished before this sync.
        if (c + 3 < NCHUNK)
            gemm_issue_chunk(gb, smem_base + (uint32_t)((c + 3) & 3) * STAGE16,
                             tid, c + 3);

        uint32_t bh2[2][4], bl2[2][4];
        #pragma unroll
        for (int nt = 0; nt < 2; nt++) {
            const uint32_t baddr = stg + b_lane + nt * 16 * 48;
            ldsm4(bh2[nt], baddr);
            ldsm4(bl2[nt], baddr + TILE16);
        }
        #pragma unroll
        for (int mt = 0; mt < 4; mt++) {
            uint32_t ah[4], al[4];
            const uint32_t aaddr = stg + a_lane + mt * 16 * 48;
            ldsm4(ah, aaddr);
            ldsm4(al, aaddr + TILE16);
            #pragma unroll
            for (int nj = 0; nj < 4; nj++) {
                const uint32_t b0h = bh2[nj >> 1][(nj & 1) * 2];
                const uint32_t b1h = bh2[nj >> 1][(nj & 1) * 2 + 1];
                const uint32_t b0l = bl2[nj >> 1][(nj & 1) * 2];
                const uint32_t b1l = bl2[nj >> 1][(nj & 1) * 2 + 1];
                mma_bf16(acc[mt][nj], ah, b0h, b1h);
                mma_bf16(acc[mt][nj], ah, b0l, b1l);
                mma_bf16(acc[mt][nj], al, b0h, b1h);
            }
        }
    }
}

// ============================================================
// Kernel 1: qkv GEMM -> Q/K bf16 hi/lo [B,H,S,D] (Q pre-scaled),
//           V bf16 hi/lo TRANSPOSED [B,H,D,S].
// ============================================================
__global__ void __launch_bounds__(256, 2)
qkv_gemm_kernel()
{
    extern __shared__ __align__(16) char smem[];
    float acc[4][4][4] = {};
    gemm_mainloop(g_xh, g_xl, g_wqh, g_wql, acc, smem);

    const int lane = threadIdx.x & 31;
    const int wid  = threadIdx.x >> 5;
    const int wr   = wid >> 2, wc = wid & 3;
    const int m_base = blockIdx.y * 128 + wr * 64;
    const int n_base = blockIdx.x * 128 + wc * 32;

    #pragma unroll
    for (int mt = 0; mt < 4; mt++) {
        #pragma unroll
        for (int nj = 0; nj < 4; nj++) {
            const int n = n_base + nj * 8 + (lane & 3) * 2;
            const int three = n >> 10;
            const int h = (n >> 6) & 15;
            const int d = n & 63;
            #pragma unroll
            for (int rs = 0; rs < 2; rs++) {
                const int m = m_base + mt * 16 + (lane >> 2) + rs * 8;
                const int b = m >> 11;
                const int s = m & 2047;
                const float x0 = acc[mt][nj][rs * 2];
                const float x1 = acc[mt][nj][rs * 2 + 1];
                if (three == 2) {
                    unsigned short h0, l0, h1, l1;
                    bf16split(x0, h0, l0);
                    bf16split(x1, h1, l1);
                    const size_t tb = ((size_t)(b * NHEADS + h)) * HDIM * SEQ;
                    g_vh[tb + (size_t)d * SEQ + s]       = __ushort_as_bfloat16(h0);
                    g_vl[tb + (size_t)d * SEQ + s]       = __ushort_as_bfloat16(l0);
                    g_vh[tb + (size_t)(d + 1) * SEQ + s] = __ushort_as_bfloat16(h1);
                    g_vl[tb + (size_t)(d + 1) * SEQ + s] = __ushort_as_bfloat16(l1);
                } else {
                    __nv_bfloat16* dsth = (three == 0) ? g_qh : g_kh;
                    __nv_bfloat16* dstl = (three == 0) ? g_ql : g_kl;
                    const float sc = (three == 0) ? QSCALE : 1.0f;
                    uint32_t hi, lo;
                    packsplit2(x0 * sc, x1 * sc, hi, lo);
                    const size_t idx = (((size_t)(b * NHEADS + h)) * SEQ + s) * HDIM + d;
                    *(uint32_t*)&dsth[idx] = hi;
                    *(uint32_t*)&dstl[idx] = lo;
                }
            }
        }
    }
}

// ============================================================
// Kernel 3: out = attn @ w_proj + bias
// ============================================================
__global__ void __launch_bounds__(256, 2)
proj_gemm_kernel(const float* __restrict__ bias, float* __restrict__ out)
{
    extern __shared__ __align__(16) char smem[];
    float acc[4][4][4] = {};
    gemm_mainloop(g_ah, g_al, g_wph, g_wpl, acc, smem);

    const int lane = threadIdx.x & 31;
    const int wid  = threadIdx.x >> 5;
    const int wr   = wid >> 2, wc = wid & 3;
    const int m_base = blockIdx.y * 128 + wr * 64;
    const int n_base = blockIdx.x * 128 + wc * 32;

    #pragma unroll
    for (int mt = 0; mt < 4; mt++) {
        #pragma unroll
        for (int nj = 0; nj < 4; nj++) {
            const int n = n_base + nj * 8 + (lane & 3) * 2;
            const float2 bv = *(const float2*)&bias[n];
            #pragma unroll
            for (int rs = 0; rs < 2; rs++) {
                const int m = m_base + mt * 16 + (lane >> 2) + rs * 8;
                float2 v = make_float2(acc[mt][nj][rs * 2] + bv.x,
                                       acc[mt][nj][rs * 2 + 1] + bv.y);
                *(float2*)&out[(size_t)m * DIM + n] = v;
            }
        }
    }
}

// ============================================================
// Kernel 2: tensor-core causal flash attention, warp tile M=32,
// cp.async double-buffered K/V. (unchanged from round 9 pass)
// ============================================================
#define SROW     144                 // smem row stride (64 bf16 = 128B + 16 pad)
#define QH_OFF   0
#define QL_OFF   (128 * SROW)        // 18432
#define KV_BASE  (2 * 128 * SROW)    // 36864
#define T_OFF    (64 * SROW)         // 9216 per tile (kh, kl, vh, vl)
#define KV_STAGE (4 * T_OFF)         // 36864 per stage
#define ATT_SMEM (KV_BASE + 2 * KV_STAGE)   // 110592

__device__ __forceinline__ void attn_issue_kv(uint32_t dstbase, size_t bh,
                                              int kv0, int tid)
{
    #pragma unroll
    for (int j = 0; j < 16; j++) {
        const int i = tid + j * 128;
        const int arr = i >> 9;           // 0 kh, 1 kl, 2 vh, 3 vl
        const int t   = i & 511;
        const int row = t >> 3, ch = t & 7;
        const __nv_bfloat16* src;
        if      (arr == 0) src = &g_kh[bh + (size_t)(kv0 + row) * HDIM + ch * 8];
        else if (arr == 1) src = &g_kl[bh + (size_t)(kv0 + row) * HDIM + ch * 8];
        else if (arr == 2) src = &g_vh[bh + (size_t)row * SEQ + kv0 + ch * 8];
        else               src = &g_vl[bh + (size_t)row * SEQ + kv0 + ch * 8];
        const uint32_t dst = dstbase + arr * T_OFF + row * SROW + ch * 16;
        CP_ASYNC16(dst, src);
    }
    CP_COMMIT();
}

__global__ void __launch_bounds__(128, 2) attn_kernel()
{
    extern __shared__ __align__(16) char sm[];
    const uint32_t sbase = smem_to_u32(sm);

    const int tid  = threadIdx.x;
    const int lane = tid & 31;
    const int w    = tid >> 5;                     // 0..3
    const int qt   = gridDim.x - 1 - blockIdx.x;   // big tiles first
    const int h    = blockIdx.y;
    const int b    = blockIdx.z;
    const int q0   = qt * 128;
    const size_t bh = ((size_t)(b * NHEADS + h)) * SEQ * HDIM;

    const int nkv = 2 * qt + 2;

    attn_issue_kv(sbase + KV_BASE, bh, 0, tid);

    #pragma unroll
    for (int j = 0; j < 16; j++) {
        const int i = tid + j * 128;          // 0..2047
        const int arr = i >> 10;              // 0 hi, 1 lo
        const int t   = i & 1023;
        const int row = t >> 3, ch = t & 7;
        const __nv_bfloat16* g = arr ? g_ql : g_qh;
        uint4 v = *(const uint4*)&g[bh + (size_t)(q0 + row) * HDIM + ch * 8];
        *(uint4*)(sm + (arr ? QL_OFF : QH_OFF) + row * SROW + ch * 16) = v;
    }

    const int a_row  = (lane & 7) + ((lane >> 3) & 1) * 8;
    const int a_kbit = (lane >> 4) & 1;
    uint32_t q_lane[2];
    #pragma unroll
    for (int mt = 0; mt < 2; mt++)
        q_lane[mt] = sbase + QH_OFF + (w * 32 + mt * 16 + a_row) * SROW + a_kbit * 16;
    const int b_row  = (lane & 7) + ((lane >> 4) & 1) * 8;
    const int b_kbit = (lane >> 3) & 1;

    int rl[2];
    rl[0] = q0 + w * 32 + (lane >> 2);
    rl[1] = rl[0] + 16;
    const int warp_rmin = q0 + w * 32;
    const int warp_rmax = warp_rmin + 31;

    float o[2][8][4];
    #pragma unroll
    for (int mt = 0; mt < 2; mt++)
        #pragma unroll
        for (int i = 0; i < 8; i++)
            #pragma unroll
            for (int j = 0; j < 4; j++) o[mt][i][j] = 0.f;
    float m_lo[2] = {NEGBIG, NEGBIG}, m_hi[2] = {NEGBIG, NEGBIG};
    float l_lo[2] = {0.f, 0.f},       l_hi[2] = {0.f, 0.f};

    for (int kt = 0; kt < nkv; kt++) {
        const int kv0 = kt * 64;

        CP_WAIT(0);
        __syncthreads();

        if (kt + 1 < nkv)
            attn_issue_kv(sbase + KV_BASE + (uint32_t)((kt + 1) & 1) * KV_STAGE,
                          bh, kv0 + 64, tid);

        const uint32_t stg = sbase + KV_BASE + (uint32_t)(kt & 1) * KV_STAGE;

        if (kv0 <= warp_rmax) {
            float sc[2][8][4];
            #pragma unroll
            for (int mt = 0; mt < 2; mt++)
                #pragma unroll
                for (int i = 0; i < 8; i++)
                    #pragma unroll
                    for (int j = 0; j < 4; j++) sc[mt][i][j] = 0.f;

            #pragma unroll
            for (int ks = 0; ks < 4; ks++) {
                uint32_t qh[2][4], ql[2][4];
                #pragma unroll
                for (int mt = 0; mt < 2; mt++) {
                    ldsm4(qh[mt], q_lane[mt] + ks * 32);
                    ldsm4(ql[mt], q_lane[mt] + ks * 32 + (QL_OFF - QH_OFF));
                }
                #pragma unroll
                for (int kb = 0; kb < 4; kb++) {
                    uint32_t kh[4], kl[4];
                    const uint32_t kaddr = stg + (kb * 16 + b_row) * SROW +
                                           ks * 32 + b_kbit * 16;
                    ldsm4(kh, kaddr);
                    ldsm4(kl, kaddr + T_OFF);
                    #pragma unroll
                    for (int mt = 0; mt < 2; mt++) {
                        mma_bf16(sc[mt][2 * kb],     qh[mt], kh[0], kh[1]);
                        mma_bf16(sc[mt][2 * kb],     qh[mt], kl[0], kl[1]);
                        mma_bf16(sc[mt][2 * kb],     ql[mt], kh[0], kh[1]);
                        mma_bf16(sc[mt][2 * kb + 1], qh[mt], kh[2], kh[3]);
                        mma_bf16(sc[mt][2 * kb + 1], qh[mt], kl[2], kl[3]);
                        mma_bf16(sc[mt][2 * kb + 1], ql[mt], kh[2], kh[3]);
                    }
                }
            }

            if (kv0 + 63 > warp_rmin) {
                #pragma unroll
                for (int mt = 0; mt < 2; mt++)
                    #pragma unroll
                    for (int nj = 0; nj < 8; nj++) {
                        const int col = kv0 + nj * 8 + 2 * (lane & 3);
                        if (col     > rl[mt])     sc[mt][nj][0] = NEGBIG;
                        if (col + 1 > rl[mt])     sc[mt][nj][1] = NEGBIG;
                        if (col     > rl[mt] + 8) sc[mt][nj][2] = NEGBIG;
                        if (col + 1 > rl[mt] + 8) sc[mt][nj][3] = NEGBIG;
                    }
            }

            float mn0[2], mn1[2];
            #pragma unroll
            for (int mt = 0; mt < 2; mt++) {
                float mx0 = NEGBIG, mx1 = NEGBIG;
                #pragma unroll
                for (int nj = 0; nj < 8; nj++) {
                    mx0 = fmaxf(mx0, fmaxf(sc[mt][nj][0], sc[mt][nj][1]));
                    mx1 = fmaxf(mx1, fmaxf(sc[mt][nj][2], sc[mt][nj][3]));
                }
                mx0 = fmaxf(mx0, __shfl_xor_sync(0xffffffffu, mx0, 1));
                mx0 = fmaxf(mx0, __shfl_xor_sync(0xffffffffu, mx0, 2));
                mx1 = fmaxf(mx1, __shfl_xor_sync(0xffffffffu, mx1, 1));
                mx1 = fmaxf(mx1, __shfl_xor_sync(0xffffffffu, mx1, 2));

                mn0[mt] = fmaxf(m_lo[mt], mx0);
                mn1[mt] = fmaxf(m_hi[mt], mx1);
                const float al0 = ex2(m_lo[mt] - mn0[mt]);
                const float al1 = ex2(m_hi[mt] - mn1[mt]);
                m_lo[mt] = mn0[mt]; m_hi[mt] = mn1[mt];

                #pragma unroll
                for (int dt = 0; dt < 8; dt++) {
                    o[mt][dt][0] *= al0; o[mt][dt][1] *= al0;
                    o[mt][dt][2] *= al1; o[mt][dt][3] *= al1;
                }
                l_lo[mt] *= al0; l_hi[mt] *= al1;
            }

            #pragma unroll
            for (int ks = 0; ks < 4; ks++) {
                uint32_t pah[2][4], pal[2][4];
                #pragma unroll
                for (int mt = 0; mt < 2; mt++) {
                    float s0 = 0.f, s1 = 0.f;
                    #pragma unroll
                    for (int half = 0; half < 2; half++) {
                        const int nj = 2 * ks + half;
                        float p0 = ex2(sc[mt][nj][0] - mn0[mt]);
                        float p1 = ex2(sc[mt][nj][1] - mn0[mt]);
                        float p2 = ex2(sc[mt][nj][2] - mn1[mt]);
                        float p3 = ex2(sc[mt][nj][3] - mn1[mt]);
                        s0 += p0 + p1; s1 += p2 + p3;
                        packsplit2(p0, p1, pah[mt][half * 2],     pal[mt][half * 2]);
                        packsplit2(p2, p3, pah[mt][half * 2 + 1], pal[mt][half * 2 + 1]);
                    }
                    l_lo[mt] += s0; l_hi[mt] += s1;
                }

                #pragma unroll
                for (int db = 0; db < 4; db++) {
                    uint32_t vh[4], vl[4];
                    const uint32_t vaddr = stg + 2 * T_OFF + (db * 16 + b_row) * SROW +
                                           ks * 32 + b_kbit * 16;
                    ldsm4(vh, vaddr);
                    ldsm4(vl, vaddr + T_OFF);
                    #pragma unroll
                    for (int mt = 0; mt < 2; mt++) {
                        mma_bf16(o[mt][2 * db],     pah[mt], vh[0], vh[1]);
                        mma_bf16(o[mt][2 * db],     pal[mt], vh[0], vh[1]);
                        mma_bf16(o[mt][2 * db],     pah[mt], vl[0], vl[1]);
                        mma_bf16(o[mt][2 * db + 1], pah[mt], vh[2], vh[3]);
                        mma_bf16(o[mt][2 * db + 1], pal[mt], vh[2], vh[3]);
                        mma_bf16(o[mt][2 * db + 1], pah[mt], vl[2], vl[3]);
                    }
                }
            }
        }
    }

    #pragma unroll
    for (int mt = 0; mt < 2; mt++) {
        l_lo[mt] += __shfl_xor_sync(0xffffffffu, l_lo[mt], 1);
        l_lo[mt] += __shfl_xor_sync(0xffffffffu, l_lo[mt], 2);
        l_hi[mt] += __shfl_xor_sync(0xffffffffu, l_hi[mt], 1);
        l_hi[mt] += __shfl_xor_sync(0xffffffffu, l_hi[mt], 2);
    }

    #pragma unroll
    for (int mt = 0; mt < 2; mt++) {
        const float inv0 = 1.f / l_lo[mt];
        const float inv1 = 1.f / l_hi[mt];
        #pragma unroll
        for (int dt = 0; dt < 8; dt++) {
            const int c = h * HDIM + dt * 8 + 2 * (lane & 3);
            uint32_t hi, lo;
            packsplit2(o[mt][dt][0] * inv0, o[mt][dt][1] * inv0, hi, lo);
            size_t off = ((size_t)(b * SEQ + rl[mt])) * DIM + c;
            *(uint32_t*)&g_ah[off] = hi;
            *(uint32_t*)&g_al[off] = lo;
            packsplit2(o[mt][dt][2] * inv1, o[mt][dt][3] * inv1, hi, lo);
            off = ((size_t)(b * SEQ + rl[mt] + 8)) * DIM + c;
            *(uint32_t*)&g_ah[off] = hi;
            *(uint32_t*)&g_al[off] = lo;
        }
    }
}

// ============================================================
extern "C" void kernel_launch(void* const* d_in, const int* in_sizes, int n_in,
                              void* d_out, int out_size)
{
    const float* x      = (const float*)d_in[0];
    const float* w_qkv  = (const float*)d_in[1];
    const float* w_proj = (const float*)d_in[2];
    const float* b_proj = (const float*)d_in[3];
    float* out = (float*)d_out;

    // -- preprocess: split x; transpose+split weights --
    {
        __nv_bfloat16 *xh, *xl, *wqh, *wql, *wph, *wpl;
        cudaGetSymbolAddress((void**)&xh,  g_xh);
        cudaGetSymbolAddress((void**)&xl,  g_xl);
        cudaGetSymbolAddress((void**)&wqh, g_wqh);
        cudaGetSymbolAddress((void**)&wql, g_wql);
        cudaGetSymbolAddress((void**)&wph, g_wph);
        cudaGetSymbolAddress((void**)&wpl, g_wpl);

        const int n4 = NTOK * DIM / 4;
        convert_split_kernel<<<(n4 + 511) / 512, 512>>>(x, xh, xl, n4);

        dim3 blk(32, 8);
        transpose_split_kernel<<<dim3(3 * DIM / 32, DIM / 32), blk>>>(
            w_qkv, wqh, wql, DIM, 3 * DIM);
        transpose_split_kernel<<<dim3(DIM / 32, DIM / 32), blk>>>(
            w_proj, wph, wpl, DIM, DIM);
    }

    // -- QKV GEMM (bf16x3 mma.sync, 4-stage cp.async): M=8192, N=3072 --
    {
        cudaFuncSetAttribute(qkv_gemm_kernel,
                             cudaFuncAttributeMaxDynamicSharedMemorySize, GEMM_SMEM);
        dim3 grid(3 * DIM / 128, NTOK / 128);
        qkv_gemm_kernel<<<grid, 256, GEMM_SMEM>>>();
    }

    // -- attention (tensor-core bf16x3, cp.async double-buffered K/V) --
    {
        cudaFuncSetAttribute(attn_kernel,
                             cudaFuncAttributeMaxDynamicSharedMemorySize, ATT_SMEM);
        dim3 grid(SEQ / 128, NHEADS, BATCH);
        attn_kernel<<<grid, 128, ATT_SMEM>>>();
    }

    // -- projection GEMM (bf16x3 mma.sync, 4-stage cp.async): M=8192, N=1024 --
    {
        cudaFuncSetAttribute(proj_gemm_kernel,
                             cudaFuncAttributeMaxDynamicSharedMemorySize, GEMM_SMEM);
        dim3 grid(DIM / 128, NTOK / 128);
        proj_gemm_kernel<<<grid, 256, GEMM_SMEM>>>(b_proj, out);
    }
}

// round 11
// speedup vs baseline: 1.5159x; 1.5159x over previous
#include <cuda_runtime.h>
#include <cuda_fp16.h>
#include <cstdint>

#define DIM     1024
#define NHEADS  16
#define HDIM    64
#define SEQ     2048
#define BATCH   4
#define NTOK    (BATCH * SEQ)          // 8192
// SCALE * log2(e) folded into Q so softmax uses exp2
#define QSCALE  0.18033688011112042f
#define NEGBIG  -1e9f

// -------- scratch (device globals: allocation-free) --------
// A-operands are split fp16 hi/lo; B-operands single fp16.
__device__ __half g_qh[(size_t)BATCH * NHEADS * SEQ * HDIM]; // [B,H,S,D] hi
__device__ __half g_ql[(size_t)BATCH * NHEADS * SEQ * HDIM]; //            lo
__device__ __half g_kh[(size_t)BATCH * NHEADS * SEQ * HDIM]; // [B,H,S,D] single
__device__ __half g_vh[(size_t)BATCH * NHEADS * HDIM * SEQ]; // [B,H,D,S] single
__device__ __half g_xh[(size_t)NTOK * DIM];                  // x hi/lo
__device__ __half g_xl[(size_t)NTOK * DIM];
__device__ __half g_wqh[(size_t)3 * DIM * DIM];              // w_qkv^T [n][k] single
__device__ __half g_wph[(size_t)DIM * DIM];                  // w_proj^T [n][k] single
__device__ __half g_ah[(size_t)NTOK * DIM];                  // attn out hi/lo
__device__ __half g_al[(size_t)NTOK * DIM];

// ============================================================
// helpers
// ============================================================
__device__ __forceinline__ uint32_t smem_to_u32(const void* p) {
    uint32_t a;
    asm("{ .reg .u64 t; cvta.to.shared.u64 t, %1; cvt.u32.u64 %0, t; }"
        : "=r"(a) : "l"(p));
    return a;
}

__device__ __forceinline__ uint32_t h2pack(float x, float y) {
    __half2 h = __floats2half2_rn(x, y);
    return *reinterpret_cast<uint32_t*>(&h);
}

// pack 2 floats into fp16x2 hi + residual fp16x2 lo ({lo16=x, hi16=y})
__device__ __forceinline__ void h2split2(float x, float y, uint32_t& hi, uint32_t& lo) {
    __half2 h = __floats2half2_rn(x, y);
    float2 f = __half22float2(h);
    __half2 l = __floats2half2_rn(x - f.x, y - f.y);
    hi = *reinterpret_cast<uint32_t*>(&h);
    lo = *reinterpret_cast<uint32_t*>(&l);
}

__device__ __forceinline__ float ex2(float x) {
    float y;
    asm("ex2.approx.f32 %0, %1;" : "=f"(y) : "f"(x));
    return y;
}

__device__ __forceinline__ void ldsm4(uint32_t r[4], uint32_t addr) {
    asm volatile("ldmatrix.sync.aligned.m8n8.x4.shared.b16 {%0,%1,%2,%3}, [%4];"
        : "=r"(r[0]), "=r"(r[1]), "=r"(r[2]), "=r"(r[3]) : "r"(addr));
}

__device__ __forceinline__ void mma_fp16(float d[4], const uint32_t a[4],
                                         uint32_t b0, uint32_t b1) {
    asm volatile(
        "mma.sync.aligned.m16n8k16.row.col.f32.f16.f16.f32 "
        "{%0,%1,%2,%3}, {%4,%5,%6,%7}, {%8,%9}, {%0,%1,%2,%3};"
        : "+f"(d[0]), "+f"(d[1]), "+f"(d[2]), "+f"(d[3])
        : "r"(a[0]), "r"(a[1]), "r"(a[2]), "r"(a[3]), "r"(b0), "r"(b1));
}

#define CP_ASYNC16(dst, src) \
    asm volatile("cp.async.cg.shared.global [%0], [%1], 16;" \
        :: "r"(dst), "l"(src) : "memory")
#define CP_COMMIT() asm volatile("cp.async.commit_group;" ::: "memory")
#define CP_WAIT(n)  asm volatile("cp.async.wait_group %0;" :: "n"(n) : "memory")

// ============================================================
// Preprocess kernels
// ============================================================
__global__ void convert_split_kernel(const float* __restrict__ in,
                                     __half* __restrict__ hi,
                                     __half* __restrict__ lo, int n4)
{
    const int i = blockIdx.x * blockDim.x + threadIdx.x;
    if (i >= n4) return;
    float4 v = ((const float4*)in)[i];
    uint32_t h0, l0, h1, l1;
    h2split2(v.x, v.y, h0, l0);
    h2split2(v.z, v.w, h1, l1);
    ((uint2*)hi)[i] = make_uint2(h0, h1);
    ((uint2*)lo)[i] = make_uint2(l0, l1);
}

// in [K][N] fp32 -> out [N][K] single fp16
__global__ void transpose_h16_kernel(const float* __restrict__ in,
                                     __half* __restrict__ outT, int K, int N)
{
    __shared__ float t[32][33];
    const int tx = threadIdx.x, ty = threadIdx.y;
    const int k0 = blockIdx.y * 32, n0 = blockIdx.x * 32;
    #pragma unroll
    for (int j = 0; j < 4; j++)
        t[ty + j * 8][tx] = in[(size_t)(k0 + ty + j * 8) * N + n0 + tx];
    __syncthreads();
    #pragma unroll
    for (int j = 0; j < 4; j++) {
        const int nn = n0 + ty + j * 8;
        const int kk = k0 + tx;
        outT[(size_t)nn * K + kk] = __float2half(t[tx][ty + j * 8]);
    }
}

// ============================================================
// fp16x2 mma.sync GEMM: CTA 128x128, 256 threads (8 warps, 64x32 each),
// K=1024 in 32 chunks of 32, 2-stage cp.async, 80B rows, 2 CTAs/SM.
// Tiles per stage: Ah, Al, Bh (B single fp16).
// ============================================================
#define TILE_BYTES 10240            // 128 rows * 80 B
#define BUF_BYTES  (3 * TILE_BYTES) // Ah, Al, Bh = 30720
#define GEMM_SMEM  (2 * BUF_BYTES)  // 61440
#define NCHUNK     32

__device__ __forceinline__ void gemm_issue_chunk(
    const __half* const gb[3], uint32_t dstbuf, int tid, int c)
{
    #pragma unroll
    for (int i = 0; i < 6; i++) {
        const int s    = tid + i * 256;   // 0..1535
        const int tile = s >> 9;          // 512 segments per tile
        const int t2   = s & 511;
        const int row  = t2 >> 2;
        const int kg   = t2 & 3;
        const __half* src = gb[tile] + (size_t)row * DIM + c * 32 + kg * 8;
        const uint32_t dst = dstbuf + tile * TILE_BYTES + row * 80 + kg * 16;
        CP_ASYNC16(dst, src);
    }
    CP_COMMIT();
}

__device__ __forceinline__ void gemm_mainloop(
    const __half* __restrict__ Ah, const __half* __restrict__ Al,
    const __half* __restrict__ Bh,
    float acc[4][4][4], char* smem)
{
    const uint32_t smem_base = smem_to_u32(smem);
    const int tid  = threadIdx.x;
    const int lane = tid & 31;
    const int wid  = tid >> 5;        // 0..7
    const int wr   = wid >> 2;        // 0..1 -> 64 rows each
    const int wc   = wid & 3;         // 0..3 -> 32 cols each
    const int m0   = blockIdx.y * 128;
    const int n0   = blockIdx.x * 128;

    const __half* gb[3] = {
        Ah + (size_t)m0 * DIM, Al + (size_t)m0 * DIM, Bh + (size_t)n0 * DIM };

    const int arow = (lane & 7) + ((lane >> 3) & 1) * 8;
    const int acol = ((lane >> 4) & 1) * 16;
    const int brow = (lane & 7) + ((lane >> 4) & 1) * 8;
    const int bcol = ((lane >> 3) & 1) * 16;

    const uint32_t a_lane = (uint32_t)((wr * 64 + arow) * 80 + acol);
    const uint32_t b_lane = (uint32_t)(2 * TILE_BYTES + (wc * 32 + brow) * 80 + bcol);

    gemm_issue_chunk(gb, smem_base, tid, 0);

    for (int c = 0; c < NCHUNK; c++) {
        const uint32_t buf = smem_base + (uint32_t)(c & 1) * BUF_BYTES;

        if (c + 1 < NCHUNK) {
            gemm_issue_chunk(gb, smem_base + (uint32_t)((c + 1) & 1) * BUF_BYTES,
                             tid, c + 1);
            CP_WAIT(1);
        } else {
            CP_WAIT(0);
        }
        __syncthreads();

        #pragma unroll
        for (int ks = 0; ks < 2; ks++) {
            uint32_t bh2[2][4];
            #pragma unroll
            for (int nt = 0; nt < 2; nt++)
                ldsm4(bh2[nt], buf + b_lane + nt * 16 * 80 + ks * 32);
            #pragma unroll
            for (int mt = 0; mt < 4; mt++) {
                uint32_t ah[4], al[4];
                const uint32_t aaddr = buf + a_lane + mt * 16 * 80 + ks * 32;
                ldsm4(ah, aaddr);
                ldsm4(al, aaddr + TILE_BYTES);
                #pragma unroll
                for (int nj = 0; nj < 4; nj++) {
                    const uint32_t b0 = bh2[nj >> 1][(nj & 1) * 2];
                    const uint32_t b1 = bh2[nj >> 1][(nj & 1) * 2 + 1];
                    mma_fp16(acc[mt][nj], ah, b0, b1);
                    mma_fp16(acc[mt][nj], al, b0, b1);
                }
            }
        }
        __syncthreads();   // all warps done reading buf before it is refilled
    }
}

// ============================================================
// Kernel 1: qkv GEMM -> Q fp16 hi/lo (pre-scaled), K fp16 single [B,H,S,D],
//           V fp16 single TRANSPOSED [B,H,D,S].
// ============================================================
__global__ void __launch_bounds__(256, 2)
qkv_gemm_kernel()
{
    extern __shared__ __align__(16) char smem[];
    float acc[4][4][4] = {};
    gemm_mainloop(g_xh, g_xl, g_wqh, acc, smem);

    const int lane = threadIdx.x & 31;
    const int wid  = threadIdx.x >> 5;
    const int wr   = wid >> 2, wc = wid & 3;
    const int m_base = blockIdx.y * 128 + wr * 64;
    const int n_base = blockIdx.x * 128 + wc * 32;

    #pragma unroll
    for (int mt = 0; mt < 4; mt++) {
        #pragma unroll
        for (int nj = 0; nj < 4; nj++) {
            const int n = n_base + nj * 8 + (lane & 3) * 2;
            const int three = n >> 10;
            const int h = (n >> 6) & 15;
            const int d = n & 63;
            #pragma unroll
            for (int rs = 0; rs < 2; rs++) {
                const int m = m_base + mt * 16 + (lane >> 2) + rs * 8;
                const int b = m >> 11;
                const int s = m & 2047;
                const float x0 = acc[mt][nj][rs * 2];
                const float x1 = acc[mt][nj][rs * 2 + 1];
                if (three == 2) {
                    // V single fp16: scatter to [B,H,D,S]
                    const size_t tb = ((size_t)(b * NHEADS + h)) * HDIM * SEQ;
                    g_vh[tb + (size_t)d * SEQ + s]       = __float2half(x0);
                    g_vh[tb + (size_t)(d + 1) * SEQ + s] = __float2half(x1);
                } else if (three == 1) {
                    // K single fp16
                    const size_t idx = (((size_t)(b * NHEADS + h)) * SEQ + s) * HDIM + d;
                    *(uint32_t*)&g_kh[idx] = h2pack(x0, x1);
                } else {
                    // Q split hi/lo, pre-scaled
                    uint32_t hi, lo;
                    h2split2(x0 * QSCALE, x1 * QSCALE, hi, lo);
                    const size_t idx = (((size_t)(b * NHEADS + h)) * SEQ + s) * HDIM + d;
                    *(uint32_t*)&g_qh[idx] = hi;
                    *(uint32_t*)&g_ql[idx] = lo;
                }
            }
        }
    }
}

// ============================================================
// Kernel 3: out = attn @ w_proj + bias
// ============================================================
__global__ void __launch_bounds__(256, 2)
proj_gemm_kernel(const float* __restrict__ bias, float* __restrict__ out)
{
    extern __shared__ __align__(16) char smem[];
    float acc[4][4][4] = {};
    gemm_mainloop(g_ah, g_al, g_wph, acc, smem);

    const int lane = threadIdx.x & 31;
    const int wid  = threadIdx.x >> 5;
    const int wr   = wid >> 2, wc = wid & 3;
    const int m_base = blockIdx.y * 128 + wr * 64;
    const int n_base = blockIdx.x * 128 + wc * 32;

    #pragma unroll
    for (int mt = 0; mt < 4; mt++) {
        #pragma unroll
        for (int nj = 0; nj < 4; nj++) {
            const int n = n_base + nj * 8 + (lane & 3) * 2;
            const float2 bv = *(const float2*)&bias[n];
            #pragma unroll
            for (int rs = 0; rs < 2; rs++) {
                const int m = m_base + mt * 16 + (lane >> 2) + rs * 8;
                float2 v = make_float2(acc[mt][nj][rs * 2] + bv.x,
                                       acc[mt][nj][rs * 2 + 1] + bv.y);
                *(float2*)&out[(size_t)m * DIM + n] = v;
            }
        }
    }
}

// ============================================================
// Kernel 2: tensor-core causal flash attention, warp tile M=32,
// fp16x2 (Q/P split, K/V single), cp.async double-buffered K/V.
// CTA = 128 q-rows, kv tile 64, 4 warps, 2 CTAs/SM.
// ============================================================
#define SROW     144                 // smem row stride (64 fp16 = 128B + 16 pad)
#define QH_OFF   0
#define QL_OFF   (128 * SROW)        // 18432
#define KV_BASE  (2 * 128 * SROW)    // 36864
#define T_OFF    (64 * SROW)         // 9216 per tile (kh, vh)
#define KV_STAGE (2 * T_OFF)         // 18432 per stage
#define ATT_SMEM (KV_BASE + 2 * KV_STAGE)   // 73728

__device__ __forceinline__ void attn_issue_kv(uint32_t dstbase, size_t bh,
                                              int kv0, int tid)
{
    #pragma unroll
    for (int j = 0; j < 8; j++) {
        const int i = tid + j * 128;      // 0..1023
        const int arr = i >> 9;           // 0 kh, 1 vh
        const int t   = i & 511;
        const int row = t >> 3, ch = t & 7;
        const __half* src = (arr == 0)
            ? &g_kh[bh + (size_t)(kv0 + row) * HDIM + ch * 8]
            : &g_vh[bh + (size_t)row * SEQ + kv0 + ch * 8];
        const uint32_t dst = dstbase + arr * T_OFF + row * SROW + ch * 16;
        CP_ASYNC16(dst, src);
    }
    CP_COMMIT();
}

__global__ void __launch_bounds__(128, 2) attn_kernel()
{
    extern __shared__ __align__(16) char sm[];
    const uint32_t sbase = smem_to_u32(sm);

    const int tid  = threadIdx.x;
    const int lane = tid & 31;
    const int w    = tid >> 5;                     // 0..3
    const int qt   = gridDim.x - 1 - blockIdx.x;   // big tiles first
    const int h    = blockIdx.y;
    const int b    = blockIdx.z;
    const int q0   = qt * 128;
    const size_t bh = ((size_t)(b * NHEADS + h)) * SEQ * HDIM;

    const int nkv = 2 * qt + 2;

    attn_issue_kv(sbase + KV_BASE, bh, 0, tid);

    // ---- load Q hi/lo tile (plain; one-time) ----
    #pragma unroll
    for (int j = 0; j < 16; j++) {
        const int i = tid + j * 128;          // 0..2047
        const int arr = i >> 10;              // 0 hi, 1 lo
        const int t   = i & 1023;
        const int row = t >> 3, ch = t & 7;
        const __half* g = arr ? g_ql : g_qh;
        uint4 v = *(const uint4*)&g[bh + (size_t)(q0 + row) * HDIM + ch * 8];
        *(uint4*)(sm + (arr ? QL_OFF : QH_OFF) + row * SROW + ch * 16) = v;
    }

    const int a_row  = (lane & 7) + ((lane >> 3) & 1) * 8;
    const int a_kbit = (lane >> 4) & 1;
    uint32_t q_lane[2];
    #pragma unroll
    for (int mt = 0; mt < 2; mt++)
        q_lane[mt] = sbase + QH_OFF + (w * 32 + mt * 16 + a_row) * SROW + a_kbit * 16;
    const int b_row  = (lane & 7) + ((lane >> 4) & 1) * 8;   // B-operand row (n)
    const int b_kbit = (lane >> 3) & 1;                       // +8 k

    int rl[2];
    rl[0] = q0 + w * 32 + (lane >> 2);
    rl[1] = rl[0] + 16;
    const int warp_rmin = q0 + w * 32;
    const int warp_rmax = warp_rmin + 31;

    float o[2][8][4];
    #pragma unroll
    for (int mt = 0; mt < 2; mt++)
        #pragma unroll
        for (int i = 0; i < 8; i++)
            #pragma unroll
            for (int j = 0; j < 4; j++) o[mt][i][j] = 0.f;
    float m_lo[2] = {NEGBIG, NEGBIG}, m_hi[2] = {NEGBIG, NEGBIG};
    float l_lo[2] = {0.f, 0.f},       l_hi[2] = {0.f, 0.f};

    for (int kt = 0; kt < nkv; kt++) {
        const int kv0 = kt * 64;

        CP_WAIT(0);
        __syncthreads();

        if (kt + 1 < nkv)
            attn_issue_kv(sbase + KV_BASE + (uint32_t)((kt + 1) & 1) * KV_STAGE,
                          bh, kv0 + 64, tid);

        const uint32_t stg = sbase + KV_BASE + (uint32_t)(kt & 1) * KV_STAGE;

        if (kv0 <= warp_rmax) {
            // ---- S = Q K^T (fp16x2: Qh·K + Ql·K) ----
            float sc[2][8][4];
            #pragma unroll
            for (int mt = 0; mt < 2; mt++)
                #pragma unroll
                for (int i = 0; i < 8; i++)
                    #pragma unroll
                    for (int j = 0; j < 4; j++) sc[mt][i][j] = 0.f;

            #pragma unroll
            for (int ks = 0; ks < 4; ks++) {
                uint32_t qh[2][4], ql[2][4];
                #pragma unroll
                for (int mt = 0; mt < 2; mt++) {
                    ldsm4(qh[mt], q_lane[mt] + ks * 32);
                    ldsm4(ql[mt], q_lane[mt] + ks * 32 + (QL_OFF - QH_OFF));
                }
                #pragma unroll
                for (int kb = 0; kb < 4; kb++) {
                    uint32_t kh[4];
                    ldsm4(kh, stg + (kb * 16 + b_row) * SROW + ks * 32 + b_kbit * 16);
                    #pragma unroll
                    for (int mt = 0; mt < 2; mt++) {
                        mma_fp16(sc[mt][2 * kb],     qh[mt], kh[0], kh[1]);
                        mma_fp16(sc[mt][2 * kb],     ql[mt], kh[0], kh[1]);
                        mma_fp16(sc[mt][2 * kb + 1], qh[mt], kh[2], kh[3]);
                        mma_fp16(sc[mt][2 * kb + 1], ql[mt], kh[2], kh[3]);
                    }
                }
            }

            // ---- causal mask ----
            if (kv0 + 63 > warp_rmin) {
                #pragma unroll
                for (int mt = 0; mt < 2; mt++)
                    #pragma unroll
                    for (int nj = 0; nj < 8; nj++) {
                        const int col = kv0 + nj * 8 + 2 * (lane & 3);
                        if (col     > rl[mt])     sc[mt][nj][0] = NEGBIG;
                        if (col + 1 > rl[mt])     sc[mt][nj][1] = NEGBIG;
                        if (col     > rl[mt] + 8) sc[mt][nj][2] = NEGBIG;
                        if (col + 1 > rl[mt] + 8) sc[mt][nj][3] = NEGBIG;
                    }
            }

            // ---- row max (quad reduce), rescale o/l ----
            float mn0[2], mn1[2];
            #pragma unroll
            for (int mt = 0; mt < 2; mt++) {
                float mx0 = NEGBIG, mx1 = NEGBIG;
                #pragma unroll
                for (int nj = 0; nj < 8; nj++) {
                    mx0 = fmaxf(mx0, fmaxf(sc[mt][nj][0], sc[mt][nj][1]));
                    mx1 = fmaxf(mx1, fmaxf(sc[mt][nj][2], sc[mt][nj][3]));
                }
                mx0 = fmaxf(mx0, __shfl_xor_sync(0xffffffffu, mx0, 1));
                mx0 = fmaxf(mx0, __shfl_xor_sync(0xffffffffu, mx0, 2));
                mx1 = fmaxf(mx1, __shfl_xor_sync(0xffffffffu, mx1, 1));
                mx1 = fmaxf(mx1, __shfl_xor_sync(0xffffffffu, mx1, 2));

                mn0[mt] = fmaxf(m_lo[mt], mx0);
                mn1[mt] = fmaxf(m_hi[mt], mx1);
                const float al0 = ex2(m_lo[mt] - mn0[mt]);
                const float al1 = ex2(m_hi[mt] - mn1[mt]);
                m_lo[mt] = mn0[mt]; m_hi[mt] = mn1[mt];

                #pragma unroll
                for (int dt = 0; dt < 8; dt++) {
                    o[mt][dt][0] *= al0; o[mt][dt][1] *= al0;
                    o[mt][dt][2] *= al1; o[mt][dt][3] *= al1;
                }
                l_lo[mt] *= al0; l_hi[mt] *= al1;
            }

            // ---- p = exp2(s-m), split fp16 hi/lo, PV MMAs (V [d][kv]) ----
            #pragma unroll
            for (int ks = 0; ks < 4; ks++) {
                uint32_t pah[2][4], pal[2][4];
                #pragma unroll
                for (int mt = 0; mt < 2; mt++) {
                    float s0 = 0.f, s1 = 0.f;
                    #pragma unroll
                    for (int half = 0; half < 2; half++) {
                        const int nj = 2 * ks + half;
                        float p0 = ex2(sc[mt][nj][0] - mn0[mt]);
                        float p1 = ex2(sc[mt][nj][1] - mn0[mt]);
                        float p2 = ex2(sc[mt][nj][2] - mn1[mt]);
                        float p3 = ex2(sc[mt][nj][3] - mn1[mt]);
                        s0 += p0 + p1; s1 += p2 + p3;
                        h2split2(p0, p1, pah[mt][half * 2],     pal[mt][half * 2]);
                        h2split2(p2, p3, pah[mt][half * 2 + 1], pal[mt][half * 2 + 1]);
                    }
                    l_lo[mt] += s0; l_hi[mt] += s1;
                }

                #pragma unroll
                for (int db = 0; db < 4; db++) {
                    uint32_t vh[4];
                    ldsm4(vh, stg + T_OFF + (db * 16 + b_row) * SROW +
                              ks * 32 + b_kbit * 16);
                    #pragma unroll
                    for (int mt = 0; mt < 2; mt++) {
                        mma_fp16(o[mt][2 * db],     pah[mt], vh[0], vh[1]);
                        mma_fp16(o[mt][2 * db],     pal[mt], vh[0], vh[1]);
                        mma_fp16(o[mt][2 * db + 1], pah[mt], vh[2], vh[3]);
                        mma_fp16(o[mt][2 * db + 1], pal[mt], vh[2], vh[3]);
                    }
                }
            }
        }
    }

    // ---- l is per-thread partial over its columns; quad-reduce for the
    // full row sum (m/alpha already quad-uniform, so this is exact) ----
    #pragma unroll
    for (int mt = 0; mt < 2; mt++) {
        l_lo[mt] += __shfl_xor_sync(0xffffffffu, l_lo[mt], 1);
        l_lo[mt] += __shfl_xor_sync(0xffffffffu, l_lo[mt], 2);
        l_hi[mt] += __shfl_xor_sync(0xffffffffu, l_hi[mt], 1);
        l_hi[mt] += __shfl_xor_sync(0xffffffffu, l_hi[mt], 2);
    }

    // ---- epilogue: normalize, fp16 hi/lo split into g_ah/g_al ----
    #pragma unroll
    for (int mt = 0; mt < 2; mt++) {
        const float inv0 = 1.f / l_lo[mt];
        const float inv1 = 1.f / l_hi[mt];
        #pragma unroll
        for (int dt = 0; dt < 8; dt++) {
            const int c = h * HDIM + dt * 8 + 2 * (lane & 3);
            uint32_t hi, lo;
            h2split2(o[mt][dt][0] * inv0, o[mt][dt][1] * inv0, hi, lo);
            size_t off = ((size_t)(b * SEQ + rl[mt])) * DIM + c;
            *(uint32_t*)&g_ah[off] = hi;
            *(uint32_t*)&g_al[off] = lo;
            h2split2(o[mt][dt][2] * inv1, o[mt][dt][3] * inv1, hi, lo);
            off = ((size_t)(b * SEQ + rl[mt] + 8)) * DIM + c;
            *(uint32_t*)&g_ah[off] = hi;
            *(uint32_t*)&g_al[off] = lo;
        }
    }
}

// ============================================================
extern "C" void kernel_launch(void* const* d_in, const int* in_sizes, int n_in,
                              void* d_out, int out_size)
{
    const float* x      = (const float*)d_in[0];
    const float* w_qkv  = (const float*)d_in[1];
    const float* w_proj = (const float*)d_in[2];
    const float* b_proj = (const float*)d_in[3];
    float* out = (float*)d_out;

    // -- preprocess: split x (fp16 hi/lo); transpose weights (fp16 single) --
    {
        __half *xh, *xl, *wqh, *wph;
        cudaGetSymbolAddress((void**)&xh,  g_xh);
        cudaGetSymbolAddress((void**)&xl,  g_xl);
        cudaGetSymbolAddress((void**)&wqh, g_wqh);
        cudaGetSymbolAddress((void**)&wph, g_wph);

        const int n4 = NTOK * DIM / 4;
        convert_split_kernel<<<(n4 + 511) / 512, 512>>>(x, xh, xl, n4);

        dim3 blk(32, 8);
        transpose_h16_kernel<<<dim3(3 * DIM / 32, DIM / 32), blk>>>(
            w_qkv, wqh, DIM, 3 * DIM);
        transpose_h16_kernel<<<dim3(DIM / 32, DIM / 32), blk>>>(
            w_proj, wph, DIM, DIM);
    }

    // -- QKV GEMM (fp16x2 mma.sync, cp.async): M=8192, N=3072 --
    {
        cudaFuncSetAttribute(qkv_gemm_kernel,
                             cudaFuncAttributeMaxDynamicSharedMemorySize, GEMM_SMEM);
        dim3 grid(3 * DIM / 128, NTOK / 128);
        qkv_gemm_kernel<<<grid, 256, GEMM_SMEM>>>();
    }

    // -- attention (tensor-core fp16x2, cp.async double-buffered K/V) --
    {
        cudaFuncSetAttribute(attn_kernel,
                             cudaFuncAttributeMaxDynamicSharedMemorySize, ATT_SMEM);
        dim3 grid(SEQ / 128, NHEADS, BATCH);
        attn_kernel<<<grid, 128, ATT_SMEM>>>();
    }

    // -- projection GEMM (fp16x2 mma.sync, cp.async): M=8192, N=1024 --
    {
        cudaFuncSetAttribute(proj_gemm_kernel,
                             cudaFuncAttributeMaxDynamicSharedMemorySize, GEMM_SMEM);
        dim3 grid(DIM / 128, NTOK / 128);
        proj_gemm_kernel<<<grid, 256, GEMM_SMEM>>>(b_proj, out);
    }
}

// round 12
// speedup vs baseline: 1.6932x; 1.1170x over previous
#include <cuda_runtime.h>
#include <cuda_fp16.h>
#include <cstdint>

#define DIM     1024
#define NHEADS  16
#define HDIM    64
#define SEQ     2048
#define BATCH   4
#define NTOK    (BATCH * SEQ)          // 8192
// SCALE * log2(e) folded into Q so softmax uses exp2
#define QSCALE  0.18033688011112042f
#define NEGBIG  -1e9f

// -------- scratch (device globals: allocation-free) --------
// A-operands are split fp16 hi/lo; B-operands single fp16.
__device__ __half g_qh[(size_t)BATCH * NHEADS * SEQ * HDIM]; // [B,H,S,D] hi
__device__ __half g_ql[(size_t)BATCH * NHEADS * SEQ * HDIM]; //            lo
__device__ __half g_kh[(size_t)BATCH * NHEADS * SEQ * HDIM]; // [B,H,S,D] single
__device__ __half g_vh[(size_t)BATCH * NHEADS * HDIM * SEQ]; // [B,H,D,S] single
__device__ __half g_xh[(size_t)NTOK * DIM];                  // x hi/lo
__device__ __half g_xl[(size_t)NTOK * DIM];
__device__ __half g_wqh[(size_t)3 * DIM * DIM];              // w_qkv^T [n][k] single
__device__ __half g_wph[(size_t)DIM * DIM];                  // w_proj^T [n][k] single
__device__ __half g_ah[(size_t)NTOK * DIM];                  // attn out hi/lo
__device__ __half g_al[(size_t)NTOK * DIM];

// ============================================================
// helpers
// ============================================================
__device__ __forceinline__ uint32_t smem_to_u32(const void* p) {
    uint32_t a;
    asm("{ .reg .u64 t; cvta.to.shared.u64 t, %1; cvt.u32.u64 %0, t; }"
        : "=r"(a) : "l"(p));
    return a;
}

__device__ __forceinline__ uint32_t h2pack(float x, float y) {
    __half2 h = __floats2half2_rn(x, y);
    return *reinterpret_cast<uint32_t*>(&h);
}

// pack 2 floats into fp16x2 hi + residual fp16x2 lo ({lo16=x, hi16=y})
__device__ __forceinline__ void h2split2(float x, float y, uint32_t& hi, uint32_t& lo) {
    __half2 h = __floats2half2_rn(x, y);
    float2 f = __half22float2(h);
    __half2 l = __floats2half2_rn(x - f.x, y - f.y);
    hi = *reinterpret_cast<uint32_t*>(&h);
    lo = *reinterpret_cast<uint32_t*>(&l);
}

__device__ __forceinline__ float ex2(float x) {
    float y;
    asm("ex2.approx.f32 %0, %1;" : "=f"(y) : "f"(x));
    return y;
}

__device__ __forceinline__ void ldsm4(uint32_t r[4], uint32_t addr) {
    asm volatile("ldmatrix.sync.aligned.m8n8.x4.shared.b16 {%0,%1,%2,%3}, [%4];"
        : "=r"(r[0]), "=r"(r[1]), "=r"(r[2]), "=r"(r[3]) : "r"(addr));
}

__device__ __forceinline__ void mma_fp16(float d[4], const uint32_t a[4],
                                         uint32_t b0, uint32_t b1) {
    asm volatile(
        "mma.sync.aligned.m16n8k16.row.col.f32.f16.f16.f32 "
        "{%0,%1,%2,%3}, {%4,%5,%6,%7}, {%8,%9}, {%0,%1,%2,%3};"
        : "+f"(d[0]), "+f"(d[1]), "+f"(d[2]), "+f"(d[3])
        : "r"(a[0]), "r"(a[1]), "r"(a[2]), "r"(a[3]), "r"(b0), "r"(b1));
}

#define CP_ASYNC16(dst, src) \
    asm volatile("cp.async.cg.shared.global [%0], [%1], 16;" \
        :: "r"(dst), "l"(src) : "memory")
#define CP_COMMIT() asm volatile("cp.async.commit_group;" ::: "memory")
#define CP_WAIT(n)  asm volatile("cp.async.wait_group %0;" :: "n"(n) : "memory")

// ============================================================
// Preprocess kernels
// ============================================================
__global__ void convert_split_kernel(const float* __restrict__ in,
                                     __half* __restrict__ hi,
                                     __half* __restrict__ lo, int n4)
{
    const int i = blockIdx.x * blockDim.x + threadIdx.x;
    if (i >= n4) return;
    float4 v = ((const float4*)in)[i];
    uint32_t h0, l0, h1, l1;
    h2split2(v.x, v.y, h0, l0);
    h2split2(v.z, v.w, h1, l1);
    ((uint2*)hi)[i] = make_uint2(h0, h1);
    ((uint2*)lo)[i] = make_uint2(l0, l1);
}

// in [K][N] fp32 -> out [N][K] single fp16
__global__ void transpose_h16_kernel(const float* __restrict__ in,
                                     __half* __restrict__ outT, int K, int N)
{
    __shared__ float t[32][33];
    const int tx = threadIdx.x, ty = threadIdx.y;
    const int k0 = blockIdx.y * 32, n0 = blockIdx.x * 32;
    #pragma unroll
    for (int j = 0; j < 4; j++)
        t[ty + j * 8][tx] = in[(size_t)(k0 + ty + j * 8) * N + n0 + tx];
    __syncthreads();
    #pragma unroll
    for (int j = 0; j < 4; j++) {
        const int nn = n0 + ty + j * 8;
        const int kk = k0 + tx;
        outT[(size_t)nn * K + kk] = __float2half(t[tx][ty + j * 8]);
    }
}

// ============================================================
// fp16 mma.sync GEMM: CTA 128x128, 256 threads (8 warps, 64x32 each),
// K=1024 in 32 chunks of 32, 2-stage cp.async, 80B rows, 2 CTAs/SM.
// Tiles per stage: Ah, Al, Bh. USE_LO=false skips the Al tile + lo MMA
// (valid when the output is stored as single fp16 anyway: K and V).
// ============================================================
#define TILE_BYTES 10240            // 128 rows * 80 B
#define BUF_BYTES  (3 * TILE_BYTES) // Ah, Al, Bh = 30720
#define GEMM_SMEM  (2 * BUF_BYTES)  // 61440
#define NCHUNK     32

template<bool USE_LO>
__device__ __forceinline__ void gemm_issue_chunk(
    const __half* const gb[3], uint32_t dstbuf, int tid, int c)
{
    const int NSEG = USE_LO ? 6 : 4;
    #pragma unroll
    for (int i = 0; i < NSEG; i++) {
        const int s    = tid + i * 256;
        const int t0   = s >> 9;          // 512 segments per tile
        const int tile = USE_LO ? t0 : (t0 == 0 ? 0 : 2);   // skip Al slot
        const int t2   = s & 511;
        const int row  = t2 >> 2;
        const int kg   = t2 & 3;
        const __half* src = gb[tile] + (size_t)row * DIM + c * 32 + kg * 8;
        const uint32_t dst = dstbuf + tile * TILE_BYTES + row * 80 + kg * 16;
        CP_ASYNC16(dst, src);
    }
    CP_COMMIT();
}

template<bool USE_LO>
__device__ __forceinline__ void gemm_mainloop(
    const __half* __restrict__ Ah, const __half* __restrict__ Al,
    const __half* __restrict__ Bh,
    float acc[4][4][4], char* smem)
{
    const uint32_t smem_base = smem_to_u32(smem);
    const int tid  = threadIdx.x;
    const int lane = tid & 31;
    const int wid  = tid >> 5;        // 0..7
    const int wr   = wid >> 2;        // 0..1 -> 64 rows each
    const int wc   = wid & 3;         // 0..3 -> 32 cols each
    const int m0   = blockIdx.y * 128;
    const int n0   = blockIdx.x * 128;

    const __half* gb[3] = {
        Ah + (size_t)m0 * DIM, Al + (size_t)m0 * DIM, Bh + (size_t)n0 * DIM };

    const int arow = (lane & 7) + ((lane >> 3) & 1) * 8;
    const int acol = ((lane >> 4) & 1) * 16;
    const int brow = (lane & 7) + ((lane >> 4) & 1) * 8;
    const int bcol = ((lane >> 3) & 1) * 16;

    const uint32_t a_lane = (uint32_t)((wr * 64 + arow) * 80 + acol);
    const uint32_t b_lane = (uint32_t)(2 * TILE_BYTES + (wc * 32 + brow) * 80 + bcol);

    gemm_issue_chunk<USE_LO>(gb, smem_base, tid, 0);

    for (int c = 0; c < NCHUNK; c++) {
        const uint32_t buf = smem_base + (uint32_t)(c & 1) * BUF_BYTES;

        if (c + 1 < NCHUNK) {
            gemm_issue_chunk<USE_LO>(gb, smem_base + (uint32_t)((c + 1) & 1) * BUF_BYTES,
                                     tid, c + 1);
            CP_WAIT(1);
        } else {
            CP_WAIT(0);
        }
        __syncthreads();

        #pragma unroll
        for (int ks = 0; ks < 2; ks++) {
            uint32_t bh2[2][4];
            #pragma unroll
            for (int nt = 0; nt < 2; nt++)
                ldsm4(bh2[nt], buf + b_lane + nt * 16 * 80 + ks * 32);
            #pragma unroll
            for (int mt = 0; mt < 4; mt++) {
                uint32_t ah[4], al[4];
                const uint32_t aaddr = buf + a_lane + mt * 16 * 80 + ks * 32;
                ldsm4(ah, aaddr);
                if (USE_LO) ldsm4(al, aaddr + TILE_BYTES);
                #pragma unroll
                for (int nj = 0; nj < 4; nj++) {
                    const uint32_t b0 = bh2[nj >> 1][(nj & 1) * 2];
                    const uint32_t b1 = bh2[nj >> 1][(nj & 1) * 2 + 1];
                    mma_fp16(acc[mt][nj], ah, b0, b1);
                    if (USE_LO) mma_fp16(acc[mt][nj], al, b0, b1);
                }
            }
        }
        __syncthreads();   // all warps done reading buf before it is refilled
    }
}

// ============================================================
// Kernel 1: qkv GEMM -> Q fp16 hi/lo (pre-scaled), K fp16 single [B,H,S,D],
//           V fp16 single TRANSPOSED [B,H,D,S].
// bx 0..7 = Q (hi/lo A), bx 8..23 = K/V (single A: lo term below fp16
// storage precision of K/V, so it is skipped).
// ============================================================
__global__ void __launch_bounds__(256, 2)
qkv_gemm_kernel()
{
    extern __shared__ __align__(16) char smem[];
    float acc[4][4][4] = {};
    if (blockIdx.x < 8)
        gemm_mainloop<true>(g_xh, g_xl, g_wqh, acc, smem);
    else
        gemm_mainloop<false>(g_xh, g_xl, g_wqh, acc, smem);

    const int lane = threadIdx.x & 31;
    const int wid  = threadIdx.x >> 5;
    const int wr   = wid >> 2, wc = wid & 3;
    const int m_base = blockIdx.y * 128 + wr * 64;
    const int n_base = blockIdx.x * 128 + wc * 32;

    #pragma unroll
    for (int mt = 0; mt < 4; mt++) {
        #pragma unroll
        for (int nj = 0; nj < 4; nj++) {
            const int n = n_base + nj * 8 + (lane & 3) * 2;
            const int three = n >> 10;
            const int h = (n >> 6) & 15;
            const int d = n & 63;
            #pragma unroll
            for (int rs = 0; rs < 2; rs++) {
                const int m = m_base + mt * 16 + (lane >> 2) + rs * 8;
                const int b = m >> 11;
                const int s = m & 2047;
                const float x0 = acc[mt][nj][rs * 2];
                const float x1 = acc[mt][nj][rs * 2 + 1];
                if (three == 2) {
                    const size_t tb = ((size_t)(b * NHEADS + h)) * HDIM * SEQ;
                    g_vh[tb + (size_t)d * SEQ + s]       = __float2half(x0);
                    g_vh[tb + (size_t)(d + 1) * SEQ + s] = __float2half(x1);
                } else if (three == 1) {
                    const size_t idx = (((size_t)(b * NHEADS + h)) * SEQ + s) * HDIM + d;
                    *(uint32_t*)&g_kh[idx] = h2pack(x0, x1);
                } else {
                    uint32_t hi, lo;
                    h2split2(x0 * QSCALE, x1 * QSCALE, hi, lo);
                    const size_t idx = (((size_t)(b * NHEADS + h)) * SEQ + s) * HDIM + d;
                    *(uint32_t*)&g_qh[idx] = hi;
                    *(uint32_t*)&g_ql[idx] = lo;
                }
            }
        }
    }
}

// ============================================================
// Kernel 3: out = attn @ w_proj + bias (full hi/lo A path)
// ============================================================
__global__ void __launch_bounds__(256, 2)
proj_gemm_kernel(const float* __restrict__ bias, float* __restrict__ out)
{
    extern __shared__ __align__(16) char smem[];
    float acc[4][4][4] = {};
    gemm_mainloop<true>(g_ah, g_al, g_wph, acc, smem);

    const int lane = threadIdx.x & 31;
    const int wid  = threadIdx.x >> 5;
    const int wr   = wid >> 2, wc = wid & 3;
    const int m_base = blockIdx.y * 128 + wr * 64;
    const int n_base = blockIdx.x * 128 + wc * 32;

    #pragma unroll
    for (int mt = 0; mt < 4; mt++) {
        #pragma unroll
        for (int nj = 0; nj < 4; nj++) {
            const int n = n_base + nj * 8 + (lane & 3) * 2;
            const float2 bv = *(const float2*)&bias[n];
            #pragma unroll
            for (int rs = 0; rs < 2; rs++) {
                const int m = m_base + mt * 16 + (lane >> 2) + rs * 8;
                float2 v = make_float2(acc[mt][nj][rs * 2] + bv.x,
                                       acc[mt][nj][rs * 2 + 1] + bv.y);
                *(float2*)&out[(size_t)m * DIM + n] = v;
            }
        }
    }
}

// ============================================================
// Kernel 2: tensor-core causal flash attention, warp tile M=32,
// fp16x2 (Q/P split, K/V single), cp.async double-buffered K/V.
// (unchanged from round 11 pass)
// ============================================================
#define SROW     144                 // smem row stride (64 fp16 = 128B + 16 pad)
#define QH_OFF   0
#define QL_OFF   (128 * SROW)        // 18432
#define KV_BASE  (2 * 128 * SROW)    // 36864
#define T_OFF    (64 * SROW)         // 9216 per tile (kh, vh)
#define KV_STAGE (2 * T_OFF)         // 18432 per stage
#define ATT_SMEM (KV_BASE + 2 * KV_STAGE)   // 73728

__device__ __forceinline__ void attn_issue_kv(uint32_t dstbase, size_t bh,
                                              int kv0, int tid)
{
    #pragma unroll
    for (int j = 0; j < 8; j++) {
        const int i = tid + j * 128;      // 0..1023
        const int arr = i >> 9;           // 0 kh, 1 vh
        const int t   = i & 511;
        const int row = t >> 3, ch = t & 7;
        const __half* src = (arr == 0)
            ? &g_kh[bh + (size_t)(kv0 + row) * HDIM + ch * 8]
            : &g_vh[bh + (size_t)row * SEQ + kv0 + ch * 8];
        const uint32_t dst = dstbase + arr * T_OFF + row * SROW + ch * 16;
        CP_ASYNC16(dst, src);
    }
    CP_COMMIT();
}

__global__ void __launch_bounds__(128, 2) attn_kernel()
{
    extern __shared__ __align__(16) char sm[];
    const uint32_t sbase = smem_to_u32(sm);

    const int tid  = threadIdx.x;
    const int lane = tid & 31;
    const int w    = tid >> 5;                     // 0..3
    const int qt   = gridDim.x - 1 - blockIdx.x;   // big tiles first
    const int h    = blockIdx.y;
    const int b    = blockIdx.z;
    const int q0   = qt * 128;
    const size_t bh = ((size_t)(b * NHEADS + h)) * SEQ * HDIM;

    const int nkv = 2 * qt + 2;

    attn_issue_kv(sbase + KV_BASE, bh, 0, tid);

    #pragma unroll
    for (int j = 0; j < 16; j++) {
        const int i = tid + j * 128;          // 0..2047
        const int arr = i >> 10;              // 0 hi, 1 lo
        const int t   = i & 1023;
        const int row = t >> 3, ch = t & 7;
        const __half* g = arr ? g_ql : g_qh;
        uint4 v = *(const uint4*)&g[bh + (size_t)(q0 + row) * HDIM + ch * 8];
        *(uint4*)(sm + (arr ? QL_OFF : QH_OFF) + row * SROW + ch * 16) = v;
    }

    const int a_row  = (lane & 7) + ((lane >> 3) & 1) * 8;
    const int a_kbit = (lane >> 4) & 1;
    uint32_t q_lane[2];
    #pragma unroll
    for (int mt = 0; mt < 2; mt++)
        q_lane[mt] = sbase + QH_OFF + (w * 32 + mt * 16 + a_row) * SROW + a_kbit * 16;
    const int b_row  = (lane & 7) + ((lane >> 4) & 1) * 8;
    const int b_kbit = (lane >> 3) & 1;

    int rl[2];
    rl[0] = q0 + w * 32 + (lane >> 2);
    rl[1] = rl[0] + 16;
    const int warp_rmin = q0 + w * 32;
    const int warp_rmax = warp_rmin + 31;

    float o[2][8][4];
    #pragma unroll
    for (int mt = 0; mt < 2; mt++)
        #pragma unroll
        for (int i = 0; i < 8; i++)
            #pragma unroll
            for (int j = 0; j < 4; j++) o[mt][i][j] = 0.f;
    float m_lo[2] = {NEGBIG, NEGBIG}, m_hi[2] = {NEGBIG, NEGBIG};
    float l_lo[2] = {0.f, 0.f},       l_hi[2] = {0.f, 0.f};

    for (int kt = 0; kt < nkv; kt++) {
        const int kv0 = kt * 64;

        CP_WAIT(0);
        __syncthreads();

        if (kt + 1 < nkv)
            attn_issue_kv(sbase + KV_BASE + (uint32_t)((kt + 1) & 1) * KV_STAGE,
                          bh, kv0 + 64, tid);

        const uint32_t stg = sbase + KV_BASE + (uint32_t)(kt & 1) * KV_STAGE;

        if (kv0 <= warp_rmax) {
            float sc[2][8][4];
            #pragma unroll
            for (int mt = 0; mt < 2; mt++)
                #pragma unroll
                for (int i = 0; i < 8; i++)
                    #pragma unroll
                    for (int j = 0; j < 4; j++) sc[mt][i][j] = 0.f;

            #pragma unroll
            for (int ks = 0; ks < 4; ks++) {
                uint32_t qh[2][4], ql[2][4];
                #pragma unroll
                for (int mt = 0; mt < 2; mt++) {
                    ldsm4(qh[mt], q_lane[mt] + ks * 32);
                    ldsm4(ql[mt], q_lane[mt] + ks * 32 + (QL_OFF - QH_OFF));
                }
                #pragma unroll
                for (int kb = 0; kb < 4; kb++) {
                    uint32_t kh[4];
                    ldsm4(kh, stg + (kb * 16 + b_row) * SROW + ks * 32 + b_kbit * 16);
                    #pragma unroll
                    for (int mt = 0; mt < 2; mt++) {
                        mma_fp16(sc[mt][2 * kb],     qh[mt], kh[0], kh[1]);
                        mma_fp16(sc[mt][2 * kb],     ql[mt], kh[0], kh[1]);
                        mma_fp16(sc[mt][2 * kb + 1], qh[mt], kh[2], kh[3]);
                        mma_fp16(sc[mt][2 * kb + 1], ql[mt], kh[2], kh[3]);
                    }
                }
            }

            if (kv0 + 63 > warp_rmin) {
                #pragma unroll
                for (int mt = 0; mt < 2; mt++)
                    #pragma unroll
                    for (int nj = 0; nj < 8; nj++) {
                        const int col = kv0 + nj * 8 + 2 * (lane & 3);
                        if (col     > rl[mt])     sc[mt][nj][0] = NEGBIG;
                        if (col + 1 > rl[mt])     sc[mt][nj][1] = NEGBIG;
                        if (col     > rl[mt] + 8) sc[mt][nj][2] = NEGBIG;
                        if (col + 1 > rl[mt] + 8) sc[mt][nj][3] = NEGBIG;
                    }
            }

            float mn0[2], mn1[2];
            #pragma unroll
            for (int mt = 0; mt < 2; mt++) {
                float mx0 = NEGBIG, mx1 = NEGBIG;
                #pragma unroll
                for (int nj = 0; nj < 8; nj++) {
                    mx0 = fmaxf(mx0, fmaxf(sc[mt][nj][0], sc[mt][nj][1]));
                    mx1 = fmaxf(mx1, fmaxf(sc[mt][nj][2], sc[mt][nj][3]));
                }
                mx0 = fmaxf(mx0, __shfl_xor_sync(0xffffffffu, mx0, 1));
                mx0 = fmaxf(mx0, __shfl_xor_sync(0xffffffffu, mx0, 2));
                mx1 = fmaxf(mx1, __shfl_xor_sync(0xffffffffu, mx1, 1));
                mx1 = fmaxf(mx1, __shfl_xor_sync(0xffffffffu, mx1, 2));

                mn0[mt] = fmaxf(m_lo[mt], mx0);
                mn1[mt] = fmaxf(m_hi[mt], mx1);
                const float al0 = ex2(m_lo[mt] - mn0[mt]);
                const float al1 = ex2(m_hi[mt] - mn1[mt]);
                m_lo[mt] = mn0[mt]; m_hi[mt] = mn1[mt];

                #pragma unroll
                for (int dt = 0; dt < 8; dt++) {
                    o[mt][dt][0] *= al0; o[mt][dt][1] *= al0;
                    o[mt][dt][2] *= al1; o[mt][dt][3] *= al1;
                }
                l_lo[mt] *= al0; l_hi[mt] *= al1;
            }

            #pragma unroll
            for (int ks = 0; ks < 4; ks++) {
                uint32_t pah[2][4], pal[2][4];
                #pragma unroll
                for (int mt = 0; mt < 2; mt++) {
                    float s0 = 0.f, s1 = 0.f;
                    #pragma unroll
                    for (int half = 0; half < 2; half++) {
                        const int nj = 2 * ks + half;
                        float p0 = ex2(sc[mt][nj][0] - mn0[mt]);
                        float p1 = ex2(sc[mt][nj][1] - mn0[mt]);
                        float p2 = ex2(sc[mt][nj][2] - mn1[mt]);
                        float p3 = ex2(sc[mt][nj][3] - mn1[mt]);
                        s0 += p0 + p1; s1 += p2 + p3;
                        h2split2(p0, p1, pah[mt][half * 2],     pal[mt][half * 2]);
                        h2split2(p2, p3, pah[mt][half * 2 + 1], pal[mt][half * 2 + 1]);
                    }
                    l_lo[mt] += s0; l_hi[mt] += s1;
                }

                #pragma unroll
                for (int db = 0; db < 4; db++) {
                    uint32_t vh[4];
                    ldsm4(vh, stg + T_OFF + (db * 16 + b_row) * SROW +
                              ks * 32 + b_kbit * 16);
                    #pragma unroll
                    for (int mt = 0; mt < 2; mt++) {
                        mma_fp16(o[mt][2 * db],     pah[mt], vh[0], vh[1]);
                        mma_fp16(o[mt][2 * db],     pal[mt], vh[0], vh[1]);
                        mma_fp16(o[mt][2 * db + 1], pah[mt], vh[2], vh[3]);
                        mma_fp16(o[mt][2 * db + 1], pal[mt], vh[2], vh[3]);
                    }
                }
            }
        }
    }

    // ---- l is per-thread partial over its columns; quad-reduce for the
    // full row sum (m/alpha already quad-uniform, so this is exact) ----
    #pragma unroll
    for (int mt = 0; mt < 2; mt++) {
        l_lo[mt] += __shfl_xor_sync(0xffffffffu, l_lo[mt], 1);
        l_lo[mt] += __shfl_xor_sync(0xffffffffu, l_lo[mt], 2);
        l_hi[mt] += __shfl_xor_sync(0xffffffffu, l_hi[mt], 1);
        l_hi[mt] += __shfl_xor_sync(0xffffffffu, l_hi[mt], 2);
    }

    // ---- epilogue: normalize, fp16 hi/lo split into g_ah/g_al ----
    #pragma unroll
    for (int mt = 0; mt < 2; mt++) {
        const float inv0 = 1.f / l_lo[mt];
        const float inv1 = 1.f / l_hi[mt];
        #pragma unroll
        for (int dt = 0; dt < 8; dt++) {
            const int c = h * HDIM + dt * 8 + 2 * (lane & 3);
            uint32_t hi, lo;
            h2split2(o[mt][dt][0] * inv0, o[mt][dt][1] * inv0, hi, lo);
            size_t off = ((size_t)(b * SEQ + rl[mt])) * DIM + c;
            *(uint32_t*)&g_ah[off] = hi;
            *(uint32_t*)&g_al[off] = lo;
            h2split2(o[mt][dt][2] * inv1, o[mt][dt][3] * inv1, hi, lo);
            off = ((size_t)(b * SEQ + rl[mt] + 8)) * DIM + c;
            *(uint32_t*)&g_ah[off] = hi;
            *(uint32_t*)&g_al[off] = lo;
        }
    }
}

// ============================================================
extern "C" void kernel_launch(void* const* d_in, const int* in_sizes, int n_in,
                              void* d_out, int out_size)
{
    const float* x      = (const float*)d_in[0];
    const float* w_qkv  = (const float*)d_in[1];
    const float* w_proj = (const float*)d_in[2];
    const float* b_proj = (const float*)d_in[3];
    float* out = (float*)d_out;

    // -- preprocess: split x (fp16 hi/lo); transpose weights (fp16 single) --
    {
        __half *xh, *xl, *wqh, *wph;
        cudaGetSymbolAddress((void**)&xh,  g_xh);
        cudaGetSymbolAddress((void**)&xl,  g_xl);
        cudaGetSymbolAddress((void**)&wqh, g_wqh);
        cudaGetSymbolAddress((void**)&wph, g_wph);

        const int n4 = NTOK * DIM / 4;
        convert_split_kernel<<<(n4 + 511) / 512, 512>>>(x, xh, xl, n4);

        dim3 blk(32, 8);
        transpose_h16_kernel<<<dim3(3 * DIM / 32, DIM / 32), blk>>>(
            w_qkv, wqh, DIM, 3 * DIM);
        transpose_h16_kernel<<<dim3(DIM / 32, DIM / 32), blk>>>(
            w_proj, wph, DIM, DIM);
    }

    // -- QKV GEMM (fp16 mma.sync, cp.async; Q hi/lo, K/V single-A) --
    {
        cudaFuncSetAttribute(qkv_gemm_kernel,
                             cudaFuncAttributeMaxDynamicSharedMemorySize, GEMM_SMEM);
        dim3 grid(3 * DIM / 128, NTOK / 128);
        qkv_gemm_kernel<<<grid, 256, GEMM_SMEM>>>();
    }

    // -- attention (tensor-core fp16x2, cp.async double-buffered K/V) --
    {
        cudaFuncSetAttribute(attn_kernel,
                             cudaFuncAttributeMaxDynamicSharedMemorySize, ATT_SMEM);
        dim3 grid(SEQ / 128, NHEADS, BATCH);
        attn_kernel<<<grid, 128, ATT_SMEM>>>();
    }

    // -- projection GEMM (fp16x2 mma.sync, cp.async): M=8192, N=1024 --
    {
        cudaFuncSetAttribute(proj_gemm_kernel,
                             cudaFuncAttributeMaxDynamicSharedMemorySize, GEMM_SMEM);
        dim3 grid(DIM / 128, NTOK / 128);
        proj_gemm_kernel<<<grid, 256, GEMM_SMEM>>>(b_proj, out);
    }
}

// round 13
// speedup vs baseline: 1.7577x; 1.0381x over previous
#include <cuda_runtime.h>
#include <cuda_fp16.h>
#include <cstdint>

#define DIM     1024
#define NHEADS  16
#define HDIM    64
#define SEQ     2048
#define BATCH   4
#define NTOK    (BATCH * SEQ)          // 8192
// SCALE * log2(e) folded into Q so softmax uses exp2
#define QSCALE  0.18033688011112042f
#define NEGBIG  -1e9f

// -------- scratch (device globals: allocation-free) --------
// A-operands are split fp16 hi/lo; B-operands single fp16.
__device__ __half g_qh[(size_t)BATCH * NHEADS * SEQ * HDIM]; // [B,H,S,D] hi
__device__ __half g_ql[(size_t)BATCH * NHEADS * SEQ * HDIM]; //            lo
__device__ __half g_kh[(size_t)BATCH * NHEADS * SEQ * HDIM]; // [B,H,S,D] single
__device__ __half g_vh[(size_t)BATCH * NHEADS * HDIM * SEQ]; // [B,H,D,S] single
__device__ __half g_xh[(size_t)NTOK * DIM];                  // x hi/lo
__device__ __half g_xl[(size_t)NTOK * DIM];
__device__ __half g_wqh[(size_t)3 * DIM * DIM];              // w_qkv^T [n][k] single
__device__ __half g_wph[(size_t)DIM * DIM];                  // w_proj^T [n][k] single
__device__ __half g_ah[(size_t)NTOK * DIM];                  // attn out hi/lo
__device__ __half g_al[(size_t)NTOK * DIM];

// ============================================================
// helpers
// ============================================================
__device__ __forceinline__ uint32_t smem_to_u32(const void* p) {
    uint32_t a;
    asm("{ .reg .u64 t; cvta.to.shared.u64 t, %1; cvt.u32.u64 %0, t; }"
        : "=r"(a) : "l"(p));
    return a;
}

__device__ __forceinline__ uint32_t h2pack(float x, float y) {
    __half2 h = __floats2half2_rn(x, y);
    return *reinterpret_cast<uint32_t*>(&h);
}

// pack 2 floats into fp16x2 hi + residual fp16x2 lo ({lo16=x, hi16=y})
__device__ __forceinline__ void h2split2(float x, float y, uint32_t& hi, uint32_t& lo) {
    __half2 h = __floats2half2_rn(x, y);
    float2 f = __half22float2(h);
    __half2 l = __floats2half2_rn(x - f.x, y - f.y);
    hi = *reinterpret_cast<uint32_t*>(&h);
    lo = *reinterpret_cast<uint32_t*>(&l);
}

__device__ __forceinline__ float ex2(float x) {
    float y;
    asm("ex2.approx.f32 %0, %1;" : "=f"(y) : "f"(x));
    return y;
}

__device__ __forceinline__ void ldsm4(uint32_t r[4], uint32_t addr) {
    asm volatile("ldmatrix.sync.aligned.m8n8.x4.shared.b16 {%0,%1,%2,%3}, [%4];"
        : "=r"(r[0]), "=r"(r[1]), "=r"(r[2]), "=r"(r[3]) : "r"(addr));
}

__device__ __forceinline__ void mma_fp16(float d[4], const uint32_t a[4],
                                         uint32_t b0, uint32_t b1) {
    asm volatile(
        "mma.sync.aligned.m16n8k16.row.col.f32.f16.f16.f32 "
        "{%0,%1,%2,%3}, {%4,%5,%6,%7}, {%8,%9}, {%0,%1,%2,%3};"
        : "+f"(d[0]), "+f"(d[1]), "+f"(d[2]), "+f"(d[3])
        : "r"(a[0]), "r"(a[1]), "r"(a[2]), "r"(a[3]), "r"(b0), "r"(b1));
}

#define CP_ASYNC16(dst, src) \
    asm volatile("cp.async.cg.shared.global [%0], [%1], 16;" \
        :: "r"(dst), "l"(src) : "memory")
#define CP_COMMIT() asm volatile("cp.async.commit_group;" ::: "memory")
#define CP_WAIT(n)  asm volatile("cp.async.wait_group %0;" :: "n"(n) : "memory")

// ============================================================
// Preprocess kernels
// ============================================================
__global__ void convert_split_kernel(const float* __restrict__ in,
                                     __half* __restrict__ hi,
                                     __half* __restrict__ lo, int n4)
{
    const int i = blockIdx.x * blockDim.x + threadIdx.x;
    if (i >= n4) return;
    float4 v = ((const float4*)in)[i];
    uint32_t h0, l0, h1, l1;
    h2split2(v.x, v.y, h0, l0);
    h2split2(v.z, v.w, h1, l1);
    ((uint2*)hi)[i] = make_uint2(h0, h1);
    ((uint2*)lo)[i] = make_uint2(l0, l1);
}

// in [K][N] fp32 -> out [N][K] single fp16
__global__ void transpose_h16_kernel(const float* __restrict__ in,
                                     __half* __restrict__ outT, int K, int N)
{
    __shared__ float t[32][33];
    const int tx = threadIdx.x, ty = threadIdx.y;
    const int k0 = blockIdx.y * 32, n0 = blockIdx.x * 32;
    #pragma unroll
    for (int j = 0; j < 4; j++)
        t[ty + j * 8][tx] = in[(size_t)(k0 + ty + j * 8) * N + n0 + tx];
    __syncthreads();
    #pragma unroll
    for (int j = 0; j < 4; j++) {
        const int nn = n0 + ty + j * 8;
        const int kk = k0 + tx;
        outT[(size_t)nn * K + kk] = __float2half(t[tx][ty + j * 8]);
    }
}

// ============================================================
// fp16 mma.sync GEMM: CTA 128x128, 256 threads (8 warps, 64x32 each),
// K=1024 in 32 chunks of 32, 2-stage cp.async, 80B rows, 2 CTAs/SM.
// Tiles per stage: Ah, Al, Bh. USE_LO=false skips the Al tile + lo MMA.
// ============================================================
#define TILE_BYTES 10240            // 128 rows * 80 B
#define BUF_BYTES  (3 * TILE_BYTES) // Ah, Al, Bh = 30720
#define GEMM_SMEM  (2 * BUF_BYTES)  // 61440
#define NCHUNK     32

template<bool USE_LO>
__device__ __forceinline__ void gemm_issue_chunk(
    const __half* const gb[3], uint32_t dstbuf, int tid, int c)
{
    const int NSEG = USE_LO ? 6 : 4;
    #pragma unroll
    for (int i = 0; i < NSEG; i++) {
        const int s    = tid + i * 256;
        const int t0   = s >> 9;          // 512 segments per tile
        const int tile = USE_LO ? t0 : (t0 == 0 ? 0 : 2);   // skip Al slot
        const int t2   = s & 511;
        const int row  = t2 >> 2;
        const int kg   = t2 & 3;
        const __half* src = gb[tile] + (size_t)row * DIM + c * 32 + kg * 8;
        const uint32_t dst = dstbuf + tile * TILE_BYTES + row * 80 + kg * 16;
        CP_ASYNC16(dst, src);
    }
    CP_COMMIT();
}

template<bool USE_LO>
__device__ __forceinline__ void gemm_mainloop(
    const __half* __restrict__ Ah, const __half* __restrict__ Al,
    const __half* __restrict__ Bh,
    float acc[4][4][4], char* smem)
{
    const uint32_t smem_base = smem_to_u32(smem);
    const int tid  = threadIdx.x;
    const int lane = tid & 31;
    const int wid  = tid >> 5;        // 0..7
    const int wr   = wid >> 2;        // 0..1 -> 64 rows each
    const int wc   = wid & 3;         // 0..3 -> 32 cols each
    const int m0   = blockIdx.y * 128;
    const int n0   = blockIdx.x * 128;

    const __half* gb[3] = {
        Ah + (size_t)m0 * DIM, Al + (size_t)m0 * DIM, Bh + (size_t)n0 * DIM };

    const int arow = (lane & 7) + ((lane >> 3) & 1) * 8;
    const int acol = ((lane >> 4) & 1) * 16;
    const int brow = (lane & 7) + ((lane >> 4) & 1) * 8;
    const int bcol = ((lane >> 3) & 1) * 16;

    const uint32_t a_lane = (uint32_t)((wr * 64 + arow) * 80 + acol);
    const uint32_t b_lane = (uint32_t)(2 * TILE_BYTES + (wc * 32 + brow) * 80 + bcol);

    gemm_issue_chunk<USE_LO>(gb, smem_base, tid, 0);

    for (int c = 0; c < NCHUNK; c++) {
        const uint32_t buf = smem_base + (uint32_t)(c & 1) * BUF_BYTES;

        if (c + 1 < NCHUNK) {
            gemm_issue_chunk<USE_LO>(gb, smem_base + (uint32_t)((c + 1) & 1) * BUF_BYTES,
                                     tid, c + 1);
            CP_WAIT(1);
        } else {
            CP_WAIT(0);
        }
        __syncthreads();

        #pragma unroll
        for (int ks = 0; ks < 2; ks++) {
            uint32_t bh2[2][4];
            #pragma unroll
            for (int nt = 0; nt < 2; nt++)
                ldsm4(bh2[nt], buf + b_lane + nt * 16 * 80 + ks * 32);
            #pragma unroll
            for (int mt = 0; mt < 4; mt++) {
                uint32_t ah[4], al[4];
                const uint32_t aaddr = buf + a_lane + mt * 16 * 80 + ks * 32;
                ldsm4(ah, aaddr);
                if (USE_LO) ldsm4(al, aaddr + TILE_BYTES);
                #pragma unroll
                for (int nj = 0; nj < 4; nj++) {
                    const uint32_t b0 = bh2[nj >> 1][(nj & 1) * 2];
                    const uint32_t b1 = bh2[nj >> 1][(nj & 1) * 2 + 1];
                    mma_fp16(acc[mt][nj], ah, b0, b1);
                    if (USE_LO) mma_fp16(acc[mt][nj], al, b0, b1);
                }
            }
        }
        __syncthreads();   // all warps done reading buf before it is refilled
    }
}

// ============================================================
// Kernel 1: qkv GEMM -> Q fp16 hi/lo (pre-scaled), K fp16 single [B,H,S,D],
//           V fp16 single TRANSPOSED [B,H,D,S].
// ============================================================
__global__ void __launch_bounds__(256, 2)
qkv_gemm_kernel()
{
    extern __shared__ __align__(16) char smem[];
    float acc[4][4][4] = {};
    if (blockIdx.x < 8)
        gemm_mainloop<true>(g_xh, g_xl, g_wqh, acc, smem);
    else
        gemm_mainloop<false>(g_xh, g_xl, g_wqh, acc, smem);

    const int lane = threadIdx.x & 31;
    const int wid  = threadIdx.x >> 5;
    const int wr   = wid >> 2, wc = wid & 3;
    const int m_base = blockIdx.y * 128 + wr * 64;
    const int n_base = blockIdx.x * 128 + wc * 32;

    #pragma unroll
    for (int mt = 0; mt < 4; mt++) {
        #pragma unroll
        for (int nj = 0; nj < 4; nj++) {
            const int n = n_base + nj * 8 + (lane & 3) * 2;
            const int three = n >> 10;
            const int h = (n >> 6) & 15;
            const int d = n & 63;
            #pragma unroll
            for (int rs = 0; rs < 2; rs++) {
                const int m = m_base + mt * 16 + (lane >> 2) + rs * 8;
                const int b = m >> 11;
                const int s = m & 2047;
                const float x0 = acc[mt][nj][rs * 2];
                const float x1 = acc[mt][nj][rs * 2 + 1];
                if (three == 2) {
                    const size_t tb = ((size_t)(b * NHEADS + h)) * HDIM * SEQ;
                    g_vh[tb + (size_t)d * SEQ + s]       = __float2half(x0);
                    g_vh[tb + (size_t)(d + 1) * SEQ + s] = __float2half(x1);
                } else if (three == 1) {
                    const size_t idx = (((size_t)(b * NHEADS + h)) * SEQ + s) * HDIM + d;
                    *(uint32_t*)&g_kh[idx] = h2pack(x0, x1);
                } else {
                    uint32_t hi, lo;
                    h2split2(x0 * QSCALE, x1 * QSCALE, hi, lo);
                    const size_t idx = (((size_t)(b * NHEADS + h)) * SEQ + s) * HDIM + d;
                    *(uint32_t*)&g_qh[idx] = hi;
                    *(uint32_t*)&g_ql[idx] = lo;
                }
            }
        }
    }
}

// ============================================================
// Kernel 3: out = attn @ w_proj + bias (full hi/lo A path)
// ============================================================
__global__ void __launch_bounds__(256, 2)
proj_gemm_kernel(const float* __restrict__ bias, float* __restrict__ out)
{
    extern __shared__ __align__(16) char smem[];
    float acc[4][4][4] = {};
    gemm_mainloop<true>(g_ah, g_al, g_wph, acc, smem);

    const int lane = threadIdx.x & 31;
    const int wid  = threadIdx.x >> 5;
    const int wr   = wid >> 2, wc = wid & 3;
    const int m_base = blockIdx.y * 128 + wr * 64;
    const int n_base = blockIdx.x * 128 + wc * 32;

    #pragma unroll
    for (int mt = 0; mt < 4; mt++) {
        #pragma unroll
        for (int nj = 0; nj < 4; nj++) {
            const int n = n_base + nj * 8 + (lane & 3) * 2;
            const float2 bv = *(const float2*)&bias[n];
            #pragma unroll
            for (int rs = 0; rs < 2; rs++) {
                const int m = m_base + mt * 16 + (lane >> 2) + rs * 8;
                float2 v = make_float2(acc[mt][nj][rs * 2] + bv.x,
                                       acc[mt][nj][rs * 2 + 1] + bv.y);
                *(float2*)&out[(size_t)m * DIM + n] = v;
            }
        }
    }
}

// ============================================================
// Kernel 2: tensor-core causal flash attention, warp tile M=32,
// fp16 (Q split hi/lo for scores; P single fp16 for PV), cp.async
// double-buffered K/V. 3 CTAs/SM (221KB smem), 128 threads.
// ============================================================
#define SROW     144                 // smem row stride (64 fp16 = 128B + 16 pad)
#define QH_OFF   0
#define QL_OFF   (128 * SROW)        // 18432
#define KV_BASE  (2 * 128 * SROW)    // 36864
#define T_OFF    (64 * SROW)         // 9216 per tile (kh, vh)
#define KV_STAGE (2 * T_OFF)         // 18432 per stage
#define ATT_SMEM (KV_BASE + 2 * KV_STAGE)   // 73728

__device__ __forceinline__ void attn_issue_kv(uint32_t dstbase, size_t bh,
                                              int kv0, int tid)
{
    #pragma unroll
    for (int j = 0; j < 8; j++) {
        const int i = tid + j * 128;      // 0..1023
        const int arr = i >> 9;           // 0 kh, 1 vh
        const int t   = i & 511;
        const int row = t >> 3, ch = t & 7;
        const __half* src = (arr == 0)
            ? &g_kh[bh + (size_t)(kv0 + row) * HDIM + ch * 8]
            : &g_vh[bh + (size_t)row * SEQ + kv0 + ch * 8];
        const uint32_t dst = dstbase + arr * T_OFF + row * SROW + ch * 16;
        CP_ASYNC16(dst, src);
    }
    CP_COMMIT();
}

__global__ void __launch_bounds__(128, 3) attn_kernel()
{
    extern __shared__ __align__(16) char sm[];
    const uint32_t sbase = smem_to_u32(sm);

    const int tid  = threadIdx.x;
    const int lane = tid & 31;
    const int w    = tid >> 5;                     // 0..3
    const int qt   = gridDim.x - 1 - blockIdx.x;   // big tiles first
    const int h    = blockIdx.y;
    const int b    = blockIdx.z;
    const int q0   = qt * 128;
    const size_t bh = ((size_t)(b * NHEADS + h)) * SEQ * HDIM;

    const int nkv = 2 * qt + 2;

    attn_issue_kv(sbase + KV_BASE, bh, 0, tid);

    // ---- load Q hi/lo tile (plain; one-time) ----
    #pragma unroll
    for (int j = 0; j < 16; j++) {
        const int i = tid + j * 128;          // 0..2047
        const int arr = i >> 10;              // 0 hi, 1 lo
        const int t   = i & 1023;
        const int row = t >> 3, ch = t & 7;
        const __half* g = arr ? g_ql : g_qh;
        uint4 v = *(const uint4*)&g[bh + (size_t)(q0 + row) * HDIM + ch * 8];
        *(uint4*)(sm + (arr ? QL_OFF : QH_OFF) + row * SROW + ch * 16) = v;
    }

    const int a_row  = (lane & 7) + ((lane >> 3) & 1) * 8;
    const int a_kbit = (lane >> 4) & 1;
    uint32_t q_lane[2];
    #pragma unroll
    for (int mt = 0; mt < 2; mt++)
        q_lane[mt] = sbase + QH_OFF + (w * 32 + mt * 16 + a_row) * SROW + a_kbit * 16;
    const int b_row  = (lane & 7) + ((lane >> 4) & 1) * 8;
    const int b_kbit = (lane >> 3) & 1;

    int rl[2];
    rl[0] = q0 + w * 32 + (lane >> 2);
    rl[1] = rl[0] + 16;
    const int warp_rmin = q0 + w * 32;
    const int warp_rmax = warp_rmin + 31;

    float o[2][8][4];
    #pragma unroll
    for (int mt = 0; mt < 2; mt++)
        #pragma unroll
        for (int i = 0; i < 8; i++)
            #pragma unroll
            for (int j = 0; j < 4; j++) o[mt][i][j] = 0.f;
    float m_lo[2] = {NEGBIG, NEGBIG}, m_hi[2] = {NEGBIG, NEGBIG};
    float l_lo[2] = {0.f, 0.f},       l_hi[2] = {0.f, 0.f};

    for (int kt = 0; kt < nkv; kt++) {
        const int kv0 = kt * 64;

        CP_WAIT(0);
        __syncthreads();

        if (kt + 1 < nkv)
            attn_issue_kv(sbase + KV_BASE + (uint32_t)((kt + 1) & 1) * KV_STAGE,
                          bh, kv0 + 64, tid);

        const uint32_t stg = sbase + KV_BASE + (uint32_t)(kt & 1) * KV_STAGE;

        if (kv0 <= warp_rmax) {
            // ---- S = Q K^T (Qh·K + Ql·K) ----
            float sc[2][8][4];
            #pragma unroll
            for (int mt = 0; mt < 2; mt++)
                #pragma unroll
                for (int i = 0; i < 8; i++)
                    #pragma unroll
                    for (int j = 0; j < 4; j++) sc[mt][i][j] = 0.f;

            #pragma unroll
            for (int ks = 0; ks < 4; ks++) {
                uint32_t qh[2][4], ql[2][4];
                #pragma unroll
                for (int mt = 0; mt < 2; mt++) {
                    ldsm4(qh[mt], q_lane[mt] + ks * 32);
                    ldsm4(ql[mt], q_lane[mt] + ks * 32 + (QL_OFF - QH_OFF));
                }
                #pragma unroll
                for (int kb = 0; kb < 4; kb++) {
                    uint32_t kh[4];
                    ldsm4(kh, stg + (kb * 16 + b_row) * SROW + ks * 32 + b_kbit * 16);
                    #pragma unroll
                    for (int mt = 0; mt < 2; mt++) {
                        mma_fp16(sc[mt][2 * kb],     qh[mt], kh[0], kh[1]);
                        mma_fp16(sc[mt][2 * kb],     ql[mt], kh[0], kh[1]);
                        mma_fp16(sc[mt][2 * kb + 1], qh[mt], kh[2], kh[3]);
                        mma_fp16(sc[mt][2 * kb + 1], ql[mt], kh[2], kh[3]);
                    }
                }
            }

            // ---- causal mask ----
            if (kv0 + 63 > warp_rmin) {
                #pragma unroll
                for (int mt = 0; mt < 2; mt++)
                    #pragma unroll
                    for (int nj = 0; nj < 8; nj++) {
                        const int col = kv0 + nj * 8 + 2 * (lane & 3);
                        if (col     > rl[mt])     sc[mt][nj][0] = NEGBIG;
                        if (col + 1 > rl[mt])     sc[mt][nj][1] = NEGBIG;
                        if (col     > rl[mt] + 8) sc[mt][nj][2] = NEGBIG;
                        if (col + 1 > rl[mt] + 8) sc[mt][nj][3] = NEGBIG;
                    }
            }

            // ---- row max (quad reduce), rescale o/l ----
            float mn0[2], mn1[2];
            #pragma unroll
            for (int mt = 0; mt < 2; mt++) {
                float mx0 = NEGBIG, mx1 = NEGBIG;
                #pragma unroll
                for (int nj = 0; nj < 8; nj++) {
                    mx0 = fmaxf(mx0, fmaxf(sc[mt][nj][0], sc[mt][nj][1]));
                    mx1 = fmaxf(mx1, fmaxf(sc[mt][nj][2], sc[mt][nj][3]));
                }
                mx0 = fmaxf(mx0, __shfl_xor_sync(0xffffffffu, mx0, 1));
                mx0 = fmaxf(mx0, __shfl_xor_sync(0xffffffffu, mx0, 2));
                mx1 = fmaxf(mx1, __shfl_xor_sync(0xffffffffu, mx1, 1));
                mx1 = fmaxf(mx1, __shfl_xor_sync(0xffffffffu, mx1, 2));

                mn0[mt] = fmaxf(m_lo[mt], mx0);
                mn1[mt] = fmaxf(m_hi[mt], mx1);
                const float al0 = ex2(m_lo[mt] - mn0[mt]);
                const float al1 = ex2(m_hi[mt] - mn1[mt]);
                m_lo[mt] = mn0[mt]; m_hi[mt] = mn1[mt];

                #pragma unroll
                for (int dt = 0; dt < 8; dt++) {
                    o[mt][dt][0] *= al0; o[mt][dt][1] *= al0;
                    o[mt][dt][2] *= al1; o[mt][dt][3] *= al1;
                }
                l_lo[mt] *= al0; l_hi[mt] *= al1;
            }

            // ---- p = exp2(s-m) packed single fp16, PV MMAs (V [d][kv]) ----
            #pragma unroll
            for (int ks = 0; ks < 4; ks++) {
                uint32_t pah[2][4];
                #pragma unroll
                for (int mt = 0; mt < 2; mt++) {
                    float s0 = 0.f, s1 = 0.f;
                    #pragma unroll
                    for (int half = 0; half < 2; half++) {
                        const int nj = 2 * ks + half;
                        float p0 = ex2(sc[mt][nj][0] - mn0[mt]);
                        float p1 = ex2(sc[mt][nj][1] - mn0[mt]);
                        float p2 = ex2(sc[mt][nj][2] - mn1[mt]);
                        float p3 = ex2(sc[mt][nj][3] - mn1[mt]);
                        s0 += p0 + p1; s1 += p2 + p3;
                        pah[mt][half * 2]     = h2pack(p0, p1);
                        pah[mt][half * 2 + 1] = h2pack(p2, p3);
                    }
                    l_lo[mt] += s0; l_hi[mt] += s1;
                }

                #pragma unroll
                for (int db = 0; db < 4; db++) {
                    uint32_t vh[4];
                    ldsm4(vh, stg + T_OFF + (db * 16 + b_row) * SROW +
                              ks * 32 + b_kbit * 16);
                    #pragma unroll
                    for (int mt = 0; mt < 2; mt++) {
                        mma_fp16(o[mt][2 * db],     pah[mt], vh[0], vh[1]);
                        mma_fp16(o[mt][2 * db + 1], pah[mt], vh[2], vh[3]);
                    }
                }
            }
        }
    }

    // ---- l is per-thread partial over its columns; quad-reduce for the
    // full row sum (m/alpha already quad-uniform, so this is exact) ----
    #pragma unroll
    for (int mt = 0; mt < 2; mt++) {
        l_lo[mt] += __shfl_xor_sync(0xffffffffu, l_lo[mt], 1);
        l_lo[mt] += __shfl_xor_sync(0xffffffffu, l_lo[mt], 2);
        l_hi[mt] += __shfl_xor_sync(0xffffffffu, l_hi[mt], 1);
        l_hi[mt] += __shfl_xor_sync(0xffffffffu, l_hi[mt], 2);
    }

    // ---- epilogue: normalize, fp16 hi/lo split into g_ah/g_al ----
    #pragma unroll
    for (int mt = 0; mt < 2; mt++) {
        const float inv0 = 1.f / l_lo[mt];
        const float inv1 = 1.f / l_hi[mt];
        #pragma unroll
        for (int dt = 0; dt < 8; dt++) {
            const int c = h * HDIM + dt * 8 + 2 * (lane & 3);
            uint32_t hi, lo;
            h2split2(o[mt][dt][0] * inv0, o[mt][dt][1] * inv0, hi, lo);
            size_t off = ((size_t)(b * SEQ + rl[mt])) * DIM + c;
            *(uint32_t*)&g_ah[off] = hi;
            *(uint32_t*)&g_al[off] = lo;
            h2split2(o[mt][dt][2] * inv1, o[mt][dt][3] * inv1, hi, lo);
            off = ((size_t)(b * SEQ + rl[mt] + 8)) * DIM + c;
            *(uint32_t*)&g_ah[off] = hi;
            *(uint32_t*)&g_al[off] = lo;
        }
    }
}

// ============================================================
extern "C" void kernel_launch(void* const* d_in, const int* in_sizes, int n_in,
                              void* d_out, int out_size)
{
    const float* x      = (const float*)d_in[0];
    const float* w_qkv  = (const float*)d_in[1];
    const float* w_proj = (const float*)d_in[2];
    const float* b_proj = (const float*)d_in[3];
    float* out = (float*)d_out;

    // -- preprocess: split x (fp16 hi/lo); transpose weights (fp16 single) --
    {
        __half *xh, *xl, *wqh, *wph;
        cudaGetSymbolAddress((void**)&xh,  g_xh);
        cudaGetSymbolAddress((void**)&xl,  g_xl);
        cudaGetSymbolAddress((void**)&wqh, g_wqh);
        cudaGetSymbolAddress((void**)&wph, g_wph);

        const int n4 = NTOK * DIM / 4;
        convert_split_kernel<<<(n4 + 511) / 512, 512>>>(x, xh, xl, n4);

        dim3 blk(32, 8);
        transpose_h16_kernel<<<dim3(3 * DIM / 32, DIM / 32), blk>>>(
            w_qkv, wqh, DIM, 3 * DIM);
        transpose_h16_kernel<<<dim3(DIM / 32, DIM / 32), blk>>>(
            w_proj, wph, DIM, DIM);
    }

    // -- QKV GEMM (fp16 mma.sync, cp.async; Q hi/lo, K/V single-A) --
    {
        cudaFuncSetAttribute(qkv_gemm_kernel,
                             cudaFuncAttributeMaxDynamicSharedMemorySize, GEMM_SMEM);
        dim3 grid(3 * DIM / 128, NTOK / 128);
        qkv_gemm_kernel<<<grid, 256, GEMM_SMEM>>>();
    }

    // -- attention (fp16 tensor-core, P single, 3 CTAs/SM) --
    {
        cudaFuncSetAttribute(attn_kernel,
                             cudaFuncAttributeMaxDynamicSharedMemorySize, ATT_SMEM);
        dim3 grid(SEQ / 128, NHEADS, BATCH);
        attn_kernel<<<grid, 128, ATT_SMEM>>>();
    }

    // -- projection GEMM (fp16x2 mma.sync, cp.async): M=8192, N=1024 --
    {
        cudaFuncSetAttribute(proj_gemm_kernel,
                             cudaFuncAttributeMaxDynamicSharedMemorySize, GEMM_SMEM);
        dim3 grid(DIM / 128, NTOK / 128);
        proj_gemm_kernel<<<grid, 256, GEMM_SMEM>>>(b_proj, out);
    }
}

// round 14
// speedup vs baseline: 1.9568x; 1.1133x over previous
#include <cuda_runtime.h>
#include <cuda_fp16.h>
#include <cstdint>

#define DIM     1024
#define NHEADS  16
#define HDIM    64
#define SEQ     2048
#define BATCH   4
#define NTOK    (BATCH * SEQ)          // 8192
// SCALE * log2(e) folded into Q so softmax uses exp2
#define QSCALE  0.18033688011112042f
#define NEGBIG  -1e9f

// -------- scratch (device globals: allocation-free) --------
__device__ __half g_qh[(size_t)BATCH * NHEADS * SEQ * HDIM]; // [B,H,S,D] hi
__device__ __half g_ql[(size_t)BATCH * NHEADS * SEQ * HDIM]; //            lo
__device__ __half g_kh[(size_t)BATCH * NHEADS * SEQ * HDIM]; // [B,H,S,D] single
__device__ __half g_vh[(size_t)BATCH * NHEADS * HDIM * SEQ]; // [B,H,D,S] single
__device__ __half g_xh[(size_t)NTOK * DIM];                  // x hi/lo
__device__ __half g_xl[(size_t)NTOK * DIM];
__device__ __half g_wqh[(size_t)3 * DIM * DIM];              // w_qkv^T [n][k] single
__device__ __half g_wph[(size_t)DIM * DIM];                  // w_proj^T [n][k] single
__device__ __half g_ah[(size_t)NTOK * DIM];                  // attn out hi/lo
__device__ __half g_al[(size_t)NTOK * DIM];

// ============================================================
// helpers
// ============================================================
__device__ __forceinline__ uint32_t smem_to_u32(const void* p) {
    uint32_t a;
    asm("{ .reg .u64 t; cvta.to.shared.u64 t, %1; cvt.u32.u64 %0, t; }"
        : "=r"(a) : "l"(p));
    return a;
}

__device__ __forceinline__ uint32_t h2pack(float x, float y) {
    __half2 h = __floats2half2_rn(x, y);
    return *reinterpret_cast<uint32_t*>(&h);
}

// pack 2 floats into fp16x2 hi + residual fp16x2 lo ({lo16=x, hi16=y})
__device__ __forceinline__ void h2split2(float x, float y, uint32_t& hi, uint32_t& lo) {
    __half2 h = __floats2half2_rn(x, y);
    float2 f = __half22float2(h);
    __half2 l = __floats2half2_rn(x - f.x, y - f.y);
    hi = *reinterpret_cast<uint32_t*>(&h);
    lo = *reinterpret_cast<uint32_t*>(&l);
}

__device__ __forceinline__ float ex2(float x) {
    float y;
    asm("ex2.approx.f32 %0, %1;" : "=f"(y) : "f"(x));
    return y;
}

__device__ __forceinline__ void ldsm4(uint32_t r[4], uint32_t addr) {
    asm volatile("ldmatrix.sync.aligned.m8n8.x4.shared.b16 {%0,%1,%2,%3}, [%4];"
        : "=r"(r[0]), "=r"(r[1]), "=r"(r[2]), "=r"(r[3]) : "r"(addr));
}

__device__ __forceinline__ void mma_fp16(float d[4], const uint32_t a[4],
                                         uint32_t b0, uint32_t b1) {
    asm volatile(
        "mma.sync.aligned.m16n8k16.row.col.f32.f16.f16.f32 "
        "{%0,%1,%2,%3}, {%4,%5,%6,%7}, {%8,%9}, {%0,%1,%2,%3};"
        : "+f"(d[0]), "+f"(d[1]), "+f"(d[2]), "+f"(d[3])
        : "r"(a[0]), "r"(a[1]), "r"(a[2]), "r"(a[3]), "r"(b0), "r"(b1));
}

#define CP_ASYNC16(dst, src) \
    asm volatile("cp.async.cg.shared.global [%0], [%1], 16;" \
        :: "r"(dst), "l"(src) : "memory")
#define CP_COMMIT() asm volatile("cp.async.commit_group;" ::: "memory")
#define CP_WAIT(n)  asm volatile("cp.async.wait_group %0;" :: "n"(n) : "memory")

// ============================================================
// Preprocess kernels
// ============================================================
__global__ void convert_split_kernel(const float* __restrict__ in,
                                     __half* __restrict__ hi,
                                     __half* __restrict__ lo, int n4)
{
    const int i = blockIdx.x * blockDim.x + threadIdx.x;
    if (i >= n4) return;
    float4 v = ((const float4*)in)[i];
    uint32_t h0, l0, h1, l1;
    h2split2(v.x, v.y, h0, l0);
    h2split2(v.z, v.w, h1, l1);
    ((uint2*)hi)[i] = make_uint2(h0, h1);
    ((uint2*)lo)[i] = make_uint2(l0, l1);
}

// in [K][N] fp32 -> out [N][K] single fp16
__global__ void transpose_h16_kernel(const float* __restrict__ in,
                                     __half* __restrict__ outT, int K, int N)
{
    __shared__ float t[32][33];
    const int tx = threadIdx.x, ty = threadIdx.y;
    const int k0 = blockIdx.y * 32, n0 = blockIdx.x * 32;
    #pragma unroll
    for (int j = 0; j < 4; j++)
        t[ty + j * 8][tx] = in[(size_t)(k0 + ty + j * 8) * N + n0 + tx];
    __syncthreads();
    #pragma unroll
    for (int j = 0; j < 4; j++) {
        const int nn = n0 + ty + j * 8;
        const int kk = k0 + tx;
        outT[(size_t)nn * K + kk] = __float2half(t[tx][ty + j * 8]);
    }
}

// ============================================================
// fp16 mma.sync GEMM: CTA 128x128, 256 threads (8 warps, 64x32 each),
// K=1024 in 16 chunks of 64 (more MMA per barrier), 2-stage cp.async,
// 144B padded rows, 2 CTAs/SM.
// Tiles per stage: Ah, Al, Bh. USE_LO=false skips the Al tile + lo MMA.
// ============================================================
#define TILE_BYTES 18432            // 128 rows * 144 B (128B data + 16B pad)
#define BUF_BYTES  (3 * TILE_BYTES) // Ah, Al, Bh = 55296
#define GEMM_SMEM  (2 * BUF_BYTES)  // 110592
#define NCHUNK     16               // K-chunk = 64

template<bool USE_LO>
__device__ __forceinline__ void gemm_issue_chunk(
    const __half* const gb[3], uint32_t dstbuf, int tid, int c)
{
    const int NSEG = USE_LO ? 12 : 8;     // 1024 segs/tile, 256 threads
    #pragma unroll
    for (int i = 0; i < NSEG; i++) {
        const int s    = tid + i * 256;
        const int t0   = s >> 10;         // 1024 segments per tile
        const int tile = USE_LO ? t0 : (t0 == 0 ? 0 : 2);   // skip Al slot
        const int t2   = s & 1023;
        const int row  = t2 >> 3;
        const int kg   = t2 & 7;
        const __half* src = gb[tile] + (size_t)row * DIM + c * 64 + kg * 8;
        const uint32_t dst = dstbuf + tile * TILE_BYTES + row * 144 + kg * 16;
        CP_ASYNC16(dst, src);
    }
    CP_COMMIT();
}

template<bool USE_LO>
__device__ __forceinline__ void gemm_mainloop(
    const __half* __restrict__ Ah, const __half* __restrict__ Al,
    const __half* __restrict__ Bh,
    float acc[4][4][4], char* smem)
{
    const uint32_t smem_base = smem_to_u32(smem);
    const int tid  = threadIdx.x;
    const int lane = tid & 31;
    const int wid  = tid >> 5;        // 0..7
    const int wr   = wid >> 2;        // 0..1 -> 64 rows each
    const int wc   = wid & 3;         // 0..3 -> 32 cols each
    const int m0   = blockIdx.y * 128;
    const int n0   = blockIdx.x * 128;

    const __half* gb[3] = {
        Ah + (size_t)m0 * DIM, Al + (size_t)m0 * DIM, Bh + (size_t)n0 * DIM };

    const int arow = (lane & 7) + ((lane >> 3) & 1) * 8;
    const int acol = ((lane >> 4) & 1) * 16;
    const int brow = (lane & 7) + ((lane >> 4) & 1) * 8;
    const int bcol = ((lane >> 3) & 1) * 16;

    const uint32_t a_lane = (uint32_t)((wr * 64 + arow) * 144 + acol);
    const uint32_t b_lane = (uint32_t)(2 * TILE_BYTES + (wc * 32 + brow) * 144 + bcol);

    gemm_issue_chunk<USE_LO>(gb, smem_base, tid, 0);

    for (int c = 0; c < NCHUNK; c++) {
        const uint32_t buf = smem_base + (uint32_t)(c & 1) * BUF_BYTES;

        if (c + 1 < NCHUNK) {
            gemm_issue_chunk<USE_LO>(gb, smem_base + (uint32_t)((c + 1) & 1) * BUF_BYTES,
                                     tid, c + 1);
            CP_WAIT(1);
        } else {
            CP_WAIT(0);
        }
        __syncthreads();

        #pragma unroll
        for (int ks = 0; ks < 4; ks++) {
            uint32_t bh2[2][4];
            #pragma unroll
            for (int nt = 0; nt < 2; nt++)
                ldsm4(bh2[nt], buf + b_lane + nt * 16 * 144 + ks * 32);
            #pragma unroll
            for (int mt = 0; mt < 4; mt++) {
                uint32_t ah[4], al[4];
                const uint32_t aaddr = buf + a_lane + mt * 16 * 144 + ks * 32;
                ldsm4(ah, aaddr);
                if (USE_LO) ldsm4(al, aaddr + TILE_BYTES);
                #pragma unroll
                for (int nj = 0; nj < 4; nj++) {
                    const uint32_t b0 = bh2[nj >> 1][(nj & 1) * 2];
                    const uint32_t b1 = bh2[nj >> 1][(nj & 1) * 2 + 1];
                    mma_fp16(acc[mt][nj], ah, b0, b1);
                    if (USE_LO) mma_fp16(acc[mt][nj], al, b0, b1);
                }
            }
        }
        __syncthreads();   // all warps done reading buf before it is refilled
    }
}

// ============================================================
// Kernel 1: qkv GEMM -> Q fp16 hi/lo (pre-scaled), K fp16 single [B,H,S,D],
//           V fp16 single TRANSPOSED [B,H,D,S].
// ============================================================
__global__ void __launch_bounds__(256, 2)
qkv_gemm_kernel()
{
    extern __shared__ __align__(16) char smem[];
    float acc[4][4][4] = {};
    if (blockIdx.x < 8)
        gemm_mainloop<true>(g_xh, g_xl, g_wqh, acc, smem);
    else
        gemm_mainloop<false>(g_xh, g_xl, g_wqh, acc, smem);

    const int lane = threadIdx.x & 31;
    const int wid  = threadIdx.x >> 5;
    const int wr   = wid >> 2, wc = wid & 3;
    const int m_base = blockIdx.y * 128 + wr * 64;
    const int n_base = blockIdx.x * 128 + wc * 32;

    #pragma unroll
    for (int mt = 0; mt < 4; mt++) {
        #pragma unroll
        for (int nj = 0; nj < 4; nj++) {
            const int n = n_base + nj * 8 + (lane & 3) * 2;
            const int three = n >> 10;
            const int h = (n >> 6) & 15;
            const int d = n & 63;
            #pragma unroll
            for (int rs = 0; rs < 2; rs++) {
                const int m = m_base + mt * 16 + (lane >> 2) + rs * 8;
                const int b = m >> 11;
                const int s = m & 2047;
                const float x0 = acc[mt][nj][rs * 2];
                const float x1 = acc[mt][nj][rs * 2 + 1];
                if (three == 2) {
                    const size_t tb = ((size_t)(b * NHEADS + h)) * HDIM * SEQ;
                    g_vh[tb + (size_t)d * SEQ + s]       = __float2half(x0);
                    g_vh[tb + (size_t)(d + 1) * SEQ + s] = __float2half(x1);
                } else if (three == 1) {
                    const size_t idx = (((size_t)(b * NHEADS + h)) * SEQ + s) * HDIM + d;
                    *(uint32_t*)&g_kh[idx] = h2pack(x0, x1);
                } else {
                    uint32_t hi, lo;
                    h2split2(x0 * QSCALE, x1 * QSCALE, hi, lo);
                    const size_t idx = (((size_t)(b * NHEADS + h)) * SEQ + s) * HDIM + d;
                    *(uint32_t*)&g_qh[idx] = hi;
                    *(uint32_t*)&g_ql[idx] = lo;
                }
            }
        }
    }
}

// ============================================================
// Kernel 3: out = attn @ w_proj + bias (full hi/lo A path)
// ============================================================
__global__ void __launch_bounds__(256, 2)
proj_gemm_kernel(const float* __restrict__ bias, float* __restrict__ out)
{
    extern __shared__ __align__(16) char smem[];
    float acc[4][4][4] = {};
    gemm_mainloop<true>(g_ah, g_al, g_wph, acc, smem);

    const int lane = threadIdx.x & 31;
    const int wid  = threadIdx.x >> 5;
    const int wr   = wid >> 2, wc = wid & 3;
    const int m_base = blockIdx.y * 128 + wr * 64;
    const int n_base = blockIdx.x * 128 + wc * 32;

    #pragma unroll
    for (int mt = 0; mt < 4; mt++) {
        #pragma unroll
        for (int nj = 0; nj < 4; nj++) {
            const int n = n_base + nj * 8 + (lane & 3) * 2;
            const float2 bv = *(const float2*)&bias[n];
            #pragma unroll
            for (int rs = 0; rs < 2; rs++) {
                const int m = m_base + mt * 16 + (lane >> 2) + rs * 8;
                float2 v = make_float2(acc[mt][nj][rs * 2] + bv.x,
                                       acc[mt][nj][rs * 2 + 1] + bv.y);
                *(float2*)&out[(size_t)m * DIM + n] = v;
            }
        }
    }
}

// ============================================================
// Kernel 2: tensor-core causal flash attention, warp tile M=32,
// fp16 (Q split hi/lo for scores; P single fp16 for PV), cp.async
// double-buffered K/V. 3 CTAs/SM, 128 threads. (unchanged from R13 pass)
// ============================================================
#define SROW     144                 // smem row stride (64 fp16 = 128B + 16 pad)
#define QH_OFF   0
#define QL_OFF   (128 * SROW)        // 18432
#define KV_BASE  (2 * 128 * SROW)    // 36864
#define T_OFF    (64 * SROW)         // 9216 per tile (kh, vh)
#define KV_STAGE (2 * T_OFF)         // 18432 per stage
#define ATT_SMEM (KV_BASE + 2 * KV_STAGE)   // 73728

__device__ __forceinline__ void attn_issue_kv(uint32_t dstbase, size_t bh,
                                              int kv0, int tid)
{
    #pragma unroll
    for (int j = 0; j < 8; j++) {
        const int i = tid + j * 128;      // 0..1023
        const int arr = i >> 9;           // 0 kh, 1 vh
        const int t   = i & 511;
        const int row = t >> 3, ch = t & 7;
        const __half* src = (arr == 0)
            ? &g_kh[bh + (size_t)(kv0 + row) * HDIM + ch * 8]
            : &g_vh[bh + (size_t)row * SEQ + kv0 + ch * 8];
        const uint32_t dst = dstbase + arr * T_OFF + row * SROW + ch * 16;
        CP_ASYNC16(dst, src);
    }
    CP_COMMIT();
}

__global__ void __launch_bounds__(128, 3) attn_kernel()
{
    extern __shared__ __align__(16) char sm[];
    const uint32_t sbase = smem_to_u32(sm);

    const int tid  = threadIdx.x;
    const int lane = tid & 31;
    const int w    = tid >> 5;                     // 0..3
    const int qt   = gridDim.x - 1 - blockIdx.x;   // big tiles first
    const int h    = blockIdx.y;
    const int b    = blockIdx.z;
    const int q0   = qt * 128;
    const size_t bh = ((size_t)(b * NHEADS + h)) * SEQ * HDIM;

    const int nkv = 2 * qt + 2;

    attn_issue_kv(sbase + KV_BASE, bh, 0, tid);

    #pragma unroll
    for (int j = 0; j < 16; j++) {
        const int i = tid + j * 128;          // 0..2047
        const int arr = i >> 10;              // 0 hi, 1 lo
        const int t   = i & 1023;
        const int row = t >> 3, ch = t & 7;
        const __half* g = arr ? g_ql : g_qh;
        uint4 v = *(const uint4*)&g[bh + (size_t)(q0 + row) * HDIM + ch * 8];
        *(uint4*)(sm + (arr ? QL_OFF : QH_OFF) + row * SROW + ch * 16) = v;
    }

    const int a_row  = (lane & 7) + ((lane >> 3) & 1) * 8;
    const int a_kbit = (lane >> 4) & 1;
    uint32_t q_lane[2];
    #pragma unroll
    for (int mt = 0; mt < 2; mt++)
        q_lane[mt] = sbase + QH_OFF + (w * 32 + mt * 16 + a_row) * SROW + a_kbit * 16;
    const int b_row  = (lane & 7) + ((lane >> 4) & 1) * 8;
    const int b_kbit = (lane >> 3) & 1;

    int rl[2];
    rl[0] = q0 + w * 32 + (lane >> 2);
    rl[1] = rl[0] + 16;
    const int warp_rmin = q0 + w * 32;
    const int warp_rmax = warp_rmin + 31;

    float o[2][8][4];
    #pragma unroll
    for (int mt = 0; mt < 2; mt++)
        #pragma unroll
        for (int i = 0; i < 8; i++)
            #pragma unroll
            for (int j = 0; j < 4; j++) o[mt][i][j] = 0.f;
    float m_lo[2] = {NEGBIG, NEGBIG}, m_hi[2] = {NEGBIG, NEGBIG};
    float l_lo[2] = {0.f, 0.f},       l_hi[2] = {0.f, 0.f};

    for (int kt = 0; kt < nkv; kt++) {
        const int kv0 = kt * 64;

        CP_WAIT(0);
        __syncthreads();

        if (kt + 1 < nkv)
            attn_issue_kv(sbase + KV_BASE + (uint32_t)((kt + 1) & 1) * KV_STAGE,
                          bh, kv0 + 64, tid);

        const uint32_t stg = sbase + KV_BASE + (uint32_t)(kt & 1) * KV_STAGE;

        if (kv0 <= warp_rmax) {
            float sc[2][8][4];
            #pragma unroll
            for (int mt = 0; mt < 2; mt++)
                #pragma unroll
                for (int i = 0; i < 8; i++)
                    #pragma unroll
                    for (int j = 0; j < 4; j++) sc[mt][i][j] = 0.f;

            #pragma unroll
            for (int ks = 0; ks < 4; ks++) {
                uint32_t qh[2][4], ql[2][4];
                #pragma unroll
                for (int mt = 0; mt < 2; mt++) {
                    ldsm4(qh[mt], q_lane[mt] + ks * 32);
                    ldsm4(ql[mt], q_lane[mt] + ks * 32 + (QL_OFF - QH_OFF));
                }
                #pragma unroll
                for (int kb = 0; kb < 4; kb++) {
                    uint32_t kh[4];
                    ldsm4(kh, stg + (kb * 16 + b_row) * SROW + ks * 32 + b_kbit * 16);
                    #pragma unroll
                    for (int mt = 0; mt < 2; mt++) {
                        mma_fp16(sc[mt][2 * kb],     qh[mt], kh[0], kh[1]);
                        mma_fp16(sc[mt][2 * kb],     ql[mt], kh[0], kh[1]);
                        mma_fp16(sc[mt][2 * kb + 1], qh[mt], kh[2], kh[3]);
                        mma_fp16(sc[mt][2 * kb + 1], ql[mt], kh[2], kh[3]);
                    }
                }
            }

            if (kv0 + 63 > warp_rmin) {
                #pragma unroll
                for (int mt = 0; mt < 2; mt++)
                    #pragma unroll
                    for (int nj = 0; nj < 8; nj++) {
                        const int col = kv0 + nj * 8 + 2 * (lane & 3);
                        if (col     > rl[mt])     sc[mt][nj][0] = NEGBIG;
                        if (col + 1 > rl[mt])     sc[mt][nj][1] = NEGBIG;
                        if (col     > rl[mt] + 8) sc[mt][nj][2] = NEGBIG;
                        if (col + 1 > rl[mt] + 8) sc[mt][nj][3] = NEGBIG;
                    }
            }

            float mn0[2], mn1[2];
            #pragma unroll
            for (int mt = 0; mt < 2; mt++) {
                float mx0 = NEGBIG, mx1 = NEGBIG;
                #pragma unroll
                for (int nj = 0; nj < 8; nj++) {
                    mx0 = fmaxf(mx0, fmaxf(sc[mt][nj][0], sc[mt][nj][1]));
                    mx1 = fmaxf(mx1, fmaxf(sc[mt][nj][2], sc[mt][nj][3]));
                }
                mx0 = fmaxf(mx0, __shfl_xor_sync(0xffffffffu, mx0, 1));
                mx0 = fmaxf(mx0, __shfl_xor_sync(0xffffffffu, mx0, 2));
                mx1 = fmaxf(mx1, __shfl_xor_sync(0xffffffffu, mx1, 1));
                mx1 = fmaxf(mx1, __shfl_xor_sync(0xffffffffu, mx1, 2));

                mn0[mt] = fmaxf(m_lo[mt], mx0);
                mn1[mt] = fmaxf(m_hi[mt], mx1);
                const float al0 = ex2(m_lo[mt] - mn0[mt]);
                const float al1 = ex2(m_hi[mt] - mn1[mt]);
                m_lo[mt] = mn0[mt]; m_hi[mt] = mn1[mt];

                #pragma unroll
                for (int dt = 0; dt < 8; dt++) {
                    o[mt][dt][0] *= al0; o[mt][dt][1] *= al0;
                    o[mt][dt][2] *= al1; o[mt][dt][3] *= al1;
                }
                l_lo[mt] *= al0; l_hi[mt] *= al1;
            }

            #pragma unroll
            for (int ks = 0; ks < 4; ks++) {
                uint32_t pah[2][4];
                #pragma unroll
                for (int mt = 0; mt < 2; mt++) {
                    float s0 = 0.f, s1 = 0.f;
                    #pragma unroll
                    for (int half = 0; half < 2; half++) {
                        const int nj = 2 * ks + half;
                        float p0 = ex2(sc[mt][nj][0] - mn0[mt]);
                        float p1 = ex2(sc[mt][nj][1] - mn0[mt]);
                        float p2 = ex2(sc[mt][nj][2] - mn1[mt]);
                        float p3 = ex2(sc[mt][nj][3] - mn1[mt]);
                        s0 += p0 + p1; s1 += p2 + p3;
                        pah[mt][half * 2]     = h2pack(p0, p1);
                        pah[mt][half * 2 + 1] = h2pack(p2, p3);
                    }
                    l_lo[mt] += s0; l_hi[mt] += s1;
                }

                #pragma unroll
                for (int db = 0; db < 4; db++) {
                    uint32_t vh[4];
                    ldsm4(vh, stg + T_OFF + (db * 16 + b_row) * SROW +
                              ks * 32 + b_kbit * 16);
                    #pragma unroll
                    for (int mt = 0; mt < 2; mt++) {
                        mma_fp16(o[mt][2 * db],     pah[mt], vh[0], vh[1]);
                        mma_fp16(o[mt][2 * db + 1], pah[mt], vh[2], vh[3]);
                    }
                }
            }
        }
    }

    #pragma unroll
    for (int mt = 0; mt < 2; mt++) {
        l_lo[mt] += __shfl_xor_sync(0xffffffffu, l_lo[mt], 1);
        l_lo[mt] += __shfl_xor_sync(0xffffffffu, l_lo[mt], 2);
        l_hi[mt] += __shfl_xor_sync(0xffffffffu, l_hi[mt], 1);
        l_hi[mt] += __shfl_xor_sync(0xffffffffu, l_hi[mt], 2);
    }

    #pragma unroll
    for (int mt = 0; mt < 2; mt++) {
        const float inv0 = 1.f / l_lo[mt];
        const float inv1 = 1.f / l_hi[mt];
        #pragma unroll
        for (int dt = 0; dt < 8; dt++) {
            const int c = h * HDIM + dt * 8 + 2 * (lane & 3);
            uint32_t hi, lo;
            h2split2(o[mt][dt][0] * inv0, o[mt][dt][1] * inv0, hi, lo);
            size_t off = ((size_t)(b * SEQ + rl[mt])) * DIM + c;
            *(uint32_t*)&g_ah[off] = hi;
            *(uint32_t*)&g_al[off] = lo;
            h2split2(o[mt][dt][2] * inv1, o[mt][dt][3] * inv1, hi, lo);
            off = ((size_t)(b * SEQ + rl[mt] + 8)) * DIM + c;
            *(uint32_t*)&g_ah[off] = hi;
            *(uint32_t*)&g_al[off] = lo;
        }
    }
}

// ============================================================
extern "C" void kernel_launch(void* const* d_in, const int* in_sizes, int n_in,
                              void* d_out, int out_size)
{
    const float* x      = (const float*)d_in[0];
    const float* w_qkv  = (const float*)d_in[1];
    const float* w_proj = (const float*)d_in[2];
    const float* b_proj = (const float*)d_in[3];
    float* out = (float*)d_out;

    // -- preprocess: split x (fp16 hi/lo); transpose weights (fp16 single) --
    {
        __half *xh, *xl, *wqh, *wph;
        cudaGetSymbolAddress((void**)&xh,  g_xh);
        cudaGetSymbolAddress((void**)&xl,  g_xl);
        cudaGetSymbolAddress((void**)&wqh, g_wqh);
        cudaGetSymbolAddress((void**)&wph, g_wph);

        const int n4 = NTOK * DIM / 4;
        convert_split_kernel<<<(n4 + 511) / 512, 512>>>(x, xh, xl, n4);

        dim3 blk(32, 8);
        transpose_h16_kernel<<<dim3(3 * DIM / 32, DIM / 32), blk>>>(
            w_qkv, wqh, DIM, 3 * DIM);
        transpose_h16_kernel<<<dim3(DIM / 32, DIM / 32), blk>>>(
            w_proj, wph, DIM, DIM);
    }

    // -- QKV GEMM (fp16 mma.sync, K-chunk 64, cp.async) --
    {
        cudaFuncSetAttribute(qkv_gemm_kernel,
                             cudaFuncAttributeMaxDynamicSharedMemorySize, GEMM_SMEM);
        dim3 grid(3 * DIM / 128, NTOK / 128);
        qkv_gemm_kernel<<<grid, 256, GEMM_SMEM>>>();
    }

    // -- attention (fp16 tensor-core, P single, 3 CTAs/SM) --
    {
        cudaFuncSetAttribute(attn_kernel,
                             cudaFuncAttributeMaxDynamicSharedMemorySize, ATT_SMEM);
        dim3 grid(SEQ / 128, NHEADS, BATCH);
        attn_kernel<<<grid, 128, ATT_SMEM>>>();
    }

    // -- projection GEMM (fp16 mma.sync, K-chunk 64, cp.async) --
    {
        cudaFuncSetAttribute(proj_gemm_kernel,
                             cudaFuncAttributeMaxDynamicSharedMemorySize, GEMM_SMEM);
        dim3 grid(DIM / 128, NTOK / 128);
        proj_gemm_kernel<<<grid, 256, GEMM_SMEM>>>(b_proj, out);
    }
}

// round 15
// speedup vs baseline: 2.3223x; 1.1867x over previous
#include <cuda_runtime.h>
#include <cuda_fp16.h>
#include <cstdint>

#define DIM     1024
#define NHEADS  16
#define HDIM    64
#define SEQ     2048
#define BATCH   4
#define NTOK    (BATCH * SEQ)          // 8192
// SCALE * log2(e) folded into Q so softmax uses exp2
#define QSCALE  0.18033688011112042f
#define NEGBIG  -1e9f

// -------- scratch (device globals: allocation-free) --------
__device__ __half g_qh[(size_t)BATCH * NHEADS * SEQ * HDIM]; // [B,H,S,D] single
__device__ __half g_kh[(size_t)BATCH * NHEADS * SEQ * HDIM]; // [B,H,S,D] single
__device__ __half g_vh[(size_t)BATCH * NHEADS * HDIM * SEQ]; // [B,H,D,S] single
__device__ __half g_xh[(size_t)NTOK * DIM];                  // x hi/lo
__device__ __half g_xl[(size_t)NTOK * DIM];
__device__ __half g_wqh[(size_t)3 * DIM * DIM];              // w_qkv^T [n][k] single
__device__ __half g_wph[(size_t)DIM * DIM];                  // w_proj^T [n][k] single
__device__ __half g_ah[(size_t)NTOK * DIM];                  // attn out hi/lo
__device__ __half g_al[(size_t)NTOK * DIM];

// ============================================================
// helpers
// ============================================================
__device__ __forceinline__ uint32_t smem_to_u32(const void* p) {
    uint32_t a;
    asm("{ .reg .u64 t; cvta.to.shared.u64 t, %1; cvt.u32.u64 %0, t; }"
        : "=r"(a) : "l"(p));
    return a;
}

__device__ __forceinline__ uint32_t h2pack(float x, float y) {
    __half2 h = __floats2half2_rn(x, y);
    return *reinterpret_cast<uint32_t*>(&h);
}

// pack 2 floats into fp16x2 hi + residual fp16x2 lo ({lo16=x, hi16=y})
__device__ __forceinline__ void h2split2(float x, float y, uint32_t& hi, uint32_t& lo) {
    __half2 h = __floats2half2_rn(x, y);
    float2 f = __half22float2(h);
    __half2 l = __floats2half2_rn(x - f.x, y - f.y);
    hi = *reinterpret_cast<uint32_t*>(&h);
    lo = *reinterpret_cast<uint32_t*>(&l);
}

__device__ __forceinline__ float ex2(float x) {
    float y;
    asm("ex2.approx.f32 %0, %1;" : "=f"(y) : "f"(x));
    return y;
}

__device__ __forceinline__ void ldsm4(uint32_t r[4], uint32_t addr) {
    asm volatile("ldmatrix.sync.aligned.m8n8.x4.shared.b16 {%0,%1,%2,%3}, [%4];"
        : "=r"(r[0]), "=r"(r[1]), "=r"(r[2]), "=r"(r[3]) : "r"(addr));
}

__device__ __forceinline__ void mma_fp16(float d[4], const uint32_t a[4],
                                         uint32_t b0, uint32_t b1) {
    asm volatile(
        "mma.sync.aligned.m16n8k16.row.col.f32.f16.f16.f32 "
        "{%0,%1,%2,%3}, {%4,%5,%6,%7}, {%8,%9}, {%0,%1,%2,%3};"
        : "+f"(d[0]), "+f"(d[1]), "+f"(d[2]), "+f"(d[3])
        : "r"(a[0]), "r"(a[1]), "r"(a[2]), "r"(a[3]), "r"(b0), "r"(b1));
}

#define CP_ASYNC16(dst, src) \
    asm volatile("cp.async.cg.shared.global [%0], [%1], 16;" \
        :: "r"(dst), "l"(src) : "memory")
#define CP_COMMIT() asm volatile("cp.async.commit_group;" ::: "memory")
#define CP_WAIT(n)  asm volatile("cp.async.wait_group %0;" :: "n"(n) : "memory")

// ============================================================
// Preprocess kernels
// ============================================================
__global__ void convert_split_kernel(const float* __restrict__ in,
                                     __half* __restrict__ hi,
                                     __half* __restrict__ lo, int n4)
{
    const int i = blockIdx.x * blockDim.x + threadIdx.x;
    if (i >= n4) return;
    float4 v = ((const float4*)in)[i];
    uint32_t h0, l0, h1, l1;
    h2split2(v.x, v.y, h0, l0);
    h2split2(v.z, v.w, h1, l1);
    ((uint2*)hi)[i] = make_uint2(h0, h1);
    ((uint2*)lo)[i] = make_uint2(l0, l1);
}

// in [K][N] fp32 -> out [N][K] single fp16
__global__ void transpose_h16_kernel(const float* __restrict__ in,
                                     __half* __restrict__ outT, int K, int N)
{
    __shared__ float t[32][33];
    const int tx = threadIdx.x, ty = threadIdx.y;
    const int k0 = blockIdx.y * 32, n0 = blockIdx.x * 32;
    #pragma unroll
    for (int j = 0; j < 4; j++)
        t[ty + j * 8][tx] = in[(size_t)(k0 + ty + j * 8) * N + n0 + tx];
    __syncthreads();
    #pragma unroll
    for (int j = 0; j < 4; j++) {
        const int nn = n0 + ty + j * 8;
        const int kk = k0 + tx;
        outT[(size_t)nn * K + kk] = __float2half(t[tx][ty + j * 8]);
    }
}

// ============================================================
// fp16 mma.sync GEMM: CTA 128x128, 256 threads (8 warps, 64x32 each),
// K=1024 in 16 chunks of 64, 2-stage cp.async, 144B padded rows,
// 2 CTAs/SM. Tiles per stage: Ah, Al, Bh. USE_LO=false: 1-term.
// ============================================================
#define TILE_BYTES 18432            // 128 rows * 144 B (128B data + 16B pad)
#define BUF_BYTES  (3 * TILE_BYTES) // Ah, Al, Bh = 55296
#define GEMM_SMEM  (2 * BUF_BYTES)  // 110592
#define NCHUNK     16               // K-chunk = 64

template<bool USE_LO>
__device__ __forceinline__ void gemm_issue_chunk(
    const __half* const gb[3], uint32_t dstbuf, int tid, int c)
{
    const int NSEG = USE_LO ? 12 : 8;     // 1024 segs/tile, 256 threads
    #pragma unroll
    for (int i = 0; i < NSEG; i++) {
        const int s    = tid + i * 256;
        const int t0   = s >> 10;         // 1024 segments per tile
        const int tile = USE_LO ? t0 : (t0 == 0 ? 0 : 2);   // skip Al slot
        const int t2   = s & 1023;
        const int row  = t2 >> 3;
        const int kg   = t2 & 7;
        const __half* src = gb[tile] + (size_t)row * DIM + c * 64 + kg * 8;
        const uint32_t dst = dstbuf + tile * TILE_BYTES + row * 144 + kg * 16;
        CP_ASYNC16(dst, src);
    }
    CP_COMMIT();
}

template<bool USE_LO>
__device__ __forceinline__ void gemm_mainloop(
    const __half* __restrict__ Ah, const __half* __restrict__ Al,
    const __half* __restrict__ Bh,
    float acc[4][4][4], char* smem)
{
    const uint32_t smem_base = smem_to_u32(smem);
    const int tid  = threadIdx.x;
    const int lane = tid & 31;
    const int wid  = tid >> 5;        // 0..7
    const int wr   = wid >> 2;        // 0..1 -> 64 rows each
    const int wc   = wid & 3;         // 0..3 -> 32 cols each
    const int m0   = blockIdx.y * 128;
    const int n0   = blockIdx.x * 128;

    const __half* gb[3] = {
        Ah + (size_t)m0 * DIM, Al + (size_t)m0 * DIM, Bh + (size_t)n0 * DIM };

    const int arow = (lane & 7) + ((lane >> 3) & 1) * 8;
    const int acol = ((lane >> 4) & 1) * 16;
    const int brow = (lane & 7) + ((lane >> 4) & 1) * 8;
    const int bcol = ((lane >> 3) & 1) * 16;

    const uint32_t a_lane = (uint32_t)((wr * 64 + arow) * 144 + acol);
    const uint32_t b_lane = (uint32_t)(2 * TILE_BYTES + (wc * 32 + brow) * 144 + bcol);

    gemm_issue_chunk<USE_LO>(gb, smem_base, tid, 0);

    for (int c = 0; c < NCHUNK; c++) {
        const uint32_t buf = smem_base + (uint32_t)(c & 1) * BUF_BYTES;

        if (c + 1 < NCHUNK) {
            gemm_issue_chunk<USE_LO>(gb, smem_base + (uint32_t)((c + 1) & 1) * BUF_BYTES,
                                     tid, c + 1);
            CP_WAIT(1);
        } else {
            CP_WAIT(0);
        }
        __syncthreads();

        #pragma unroll
        for (int ks = 0; ks < 4; ks++) {
            uint32_t bh2[2][4];
            #pragma unroll
            for (int nt = 0; nt < 2; nt++)
                ldsm4(bh2[nt], buf + b_lane + nt * 16 * 144 + ks * 32);
            #pragma unroll
            for (int mt = 0; mt < 4; mt++) {
                uint32_t ah[4], al[4];
                const uint32_t aaddr = buf + a_lane + mt * 16 * 144 + ks * 32;
                ldsm4(ah, aaddr);
                if (USE_LO) ldsm4(al, aaddr + TILE_BYTES);
                #pragma unroll
                for (int nj = 0; nj < 4; nj++) {
                    const uint32_t b0 = bh2[nj >> 1][(nj & 1) * 2];
                    const uint32_t b1 = bh2[nj >> 1][(nj & 1) * 2 + 1];
                    mma_fp16(acc[mt][nj], ah, b0, b1);
                    if (USE_LO) mma_fp16(acc[mt][nj], al, b0, b1);
                }
            }
        }
        __syncthreads();   // all warps done reading buf before it is refilled
    }
}

// ============================================================
// Kernel 1: qkv GEMM (1-term everywhere) -> Q/K single fp16 [B,H,S,D]
//           (Q pre-scaled), V single fp16 TRANSPOSED [B,H,D,S].
// ============================================================
__global__ void __launch_bounds__(256, 2)
qkv_gemm_kernel()
{
    extern __shared__ __align__(16) char smem[];
    float acc[4][4][4] = {};
    gemm_mainloop<false>(g_xh, g_xl, g_wqh, acc, smem);

    const int lane = threadIdx.x & 31;
    const int wid  = threadIdx.x >> 5;
    const int wr   = wid >> 2, wc = wid & 3;
    const int m_base = blockIdx.y * 128 + wr * 64;
    const int n_base = blockIdx.x * 128 + wc * 32;

    #pragma unroll
    for (int mt = 0; mt < 4; mt++) {
        #pragma unroll
        for (int nj = 0; nj < 4; nj++) {
            const int n = n_base + nj * 8 + (lane & 3) * 2;
            const int three = n >> 10;
            const int h = (n >> 6) & 15;
            const int d = n & 63;
            #pragma unroll
            for (int rs = 0; rs < 2; rs++) {
                const int m = m_base + mt * 16 + (lane >> 2) + rs * 8;
                const int b = m >> 11;
                const int s = m & 2047;
                const float x0 = acc[mt][nj][rs * 2];
                const float x1 = acc[mt][nj][rs * 2 + 1];
                if (three == 2) {
                    const size_t tb = ((size_t)(b * NHEADS + h)) * HDIM * SEQ;
                    g_vh[tb + (size_t)d * SEQ + s]       = __float2half(x0);
                    g_vh[tb + (size_t)(d + 1) * SEQ + s] = __float2half(x1);
                } else {
                    __half* dst = (three == 0) ? g_qh : g_kh;
                    const float sc = (three == 0) ? QSCALE : 1.0f;
                    const size_t idx = (((size_t)(b * NHEADS + h)) * SEQ + s) * HDIM + d;
                    *(uint32_t*)&dst[idx] = h2pack(x0 * sc, x1 * sc);
                }
            }
        }
    }
}

// ============================================================
// Kernel 3: out = attn @ w_proj + bias (keeps 2-term hi/lo A path)
// ============================================================
__global__ void __launch_bounds__(256, 2)
proj_gemm_kernel(const float* __restrict__ bias, float* __restrict__ out)
{
    extern __shared__ __align__(16) char smem[];
    float acc[4][4][4] = {};
    gemm_mainloop<true>(g_ah, g_al, g_wph, acc, smem);

    const int lane = threadIdx.x & 31;
    const int wid  = threadIdx.x >> 5;
    const int wr   = wid >> 2, wc = wid & 3;
    const int m_base = blockIdx.y * 128 + wr * 64;
    const int n_base = blockIdx.x * 128 + wc * 32;

    #pragma unroll
    for (int mt = 0; mt < 4; mt++) {
        #pragma unroll
        for (int nj = 0; nj < 4; nj++) {
            const int n = n_base + nj * 8 + (lane & 3) * 2;
            const float2 bv = *(const float2*)&bias[n];
            #pragma unroll
            for (int rs = 0; rs < 2; rs++) {
                const int m = m_base + mt * 16 + (lane >> 2) + rs * 8;
                float2 v = make_float2(acc[mt][nj][rs * 2] + bv.x,
                                       acc[mt][nj][rs * 2 + 1] + bv.y);
                *(float2*)&out[(size_t)m * DIM + n] = v;
            }
        }
    }
}

// ============================================================
// Kernel 2: tensor-core causal flash attention, warp tile M=32,
// all operands single fp16 (Q/K/V/P), cp.async double-buffered K/V.
// 3 CTAs/SM, 128 threads.
// ============================================================
#define SROW     144                 // smem row stride (64 fp16 = 128B + 16 pad)
#define QH_OFF   0
#define KV_BASE  (128 * SROW)        // 18432
#define T_OFF    (64 * SROW)         // 9216 per tile (kh, vh)
#define KV_STAGE (2 * T_OFF)         // 18432 per stage
#define ATT_SMEM (KV_BASE + 2 * KV_STAGE)   // 55296

__device__ __forceinline__ void attn_issue_kv(uint32_t dstbase, size_t bh,
                                              int kv0, int tid)
{
    #pragma unroll
    for (int j = 0; j < 8; j++) {
        const int i = tid + j * 128;      // 0..1023
        const int arr = i >> 9;           // 0 kh, 1 vh
        const int t   = i & 511;
        const int row = t >> 3, ch = t & 7;
        const __half* src = (arr == 0)
            ? &g_kh[bh + (size_t)(kv0 + row) * HDIM + ch * 8]
            : &g_vh[bh + (size_t)row * SEQ + kv0 + ch * 8];
        const uint32_t dst = dstbase + arr * T_OFF + row * SROW + ch * 16;
        CP_ASYNC16(dst, src);
    }
    CP_COMMIT();
}

__global__ void __launch_bounds__(128, 3) attn_kernel()
{
    extern __shared__ __align__(16) char sm[];
    const uint32_t sbase = smem_to_u32(sm);

    const int tid  = threadIdx.x;
    const int lane = tid & 31;
    const int w    = tid >> 5;                     // 0..3
    const int qt   = gridDim.x - 1 - blockIdx.x;   // big tiles first
    const int h    = blockIdx.y;
    const int b    = blockIdx.z;
    const int q0   = qt * 128;
    const size_t bh = ((size_t)(b * NHEADS + h)) * SEQ * HDIM;

    const int nkv = 2 * qt + 2;

    attn_issue_kv(sbase + KV_BASE, bh, 0, tid);

    // ---- load Q tile (single fp16; one-time) ----
    #pragma unroll
    for (int j = 0; j < 8; j++) {
        const int i = tid + j * 128;          // 0..1023
        const int row = i >> 3, ch = i & 7;
        uint4 v = *(const uint4*)&g_qh[bh + (size_t)(q0 + row) * HDIM + ch * 8];
        *(uint4*)(sm + QH_OFF + row * SROW + ch * 16) = v;
    }

    const int a_row  = (lane & 7) + ((lane >> 3) & 1) * 8;
    const int a_kbit = (lane >> 4) & 1;
    uint32_t q_lane[2];
    #pragma unroll
    for (int mt = 0; mt < 2; mt++)
        q_lane[mt] = sbase + QH_OFF + (w * 32 + mt * 16 + a_row) * SROW + a_kbit * 16;
    const int b_row  = (lane & 7) + ((lane >> 4) & 1) * 8;
    const int b_kbit = (lane >> 3) & 1;

    int rl[2];
    rl[0] = q0 + w * 32 + (lane >> 2);
    rl[1] = rl[0] + 16;
    const int warp_rmin = q0 + w * 32;
    const int warp_rmax = warp_rmin + 31;

    float o[2][8][4];
    #pragma unroll
    for (int mt = 0; mt < 2; mt++)
        #pragma unroll
        for (int i = 0; i < 8; i++)
            #pragma unroll
            for (int j = 0; j < 4; j++) o[mt][i][j] = 0.f;
    float m_lo[2] = {NEGBIG, NEGBIG}, m_hi[2] = {NEGBIG, NEGBIG};
    float l_lo[2] = {0.f, 0.f},       l_hi[2] = {0.f, 0.f};

    for (int kt = 0; kt < nkv; kt++) {
        const int kv0 = kt * 64;

        CP_WAIT(0);
        __syncthreads();

        if (kt + 1 < nkv)
            attn_issue_kv(sbase + KV_BASE + (uint32_t)((kt + 1) & 1) * KV_STAGE,
                          bh, kv0 + 64, tid);

        const uint32_t stg = sbase + KV_BASE + (uint32_t)(kt & 1) * KV_STAGE;

        if (kv0 <= warp_rmax) {
            // ---- S = Q K^T (single fp16) ----
            float sc[2][8][4];
            #pragma unroll
            for (int mt = 0; mt < 2; mt++)
                #pragma unroll
                for (int i = 0; i < 8; i++)
                    #pragma unroll
                    for (int j = 0; j < 4; j++) sc[mt][i][j] = 0.f;

            #pragma unroll
            for (int ks = 0; ks < 4; ks++) {
                uint32_t qh[2][4];
                #pragma unroll
                for (int mt = 0; mt < 2; mt++)
                    ldsm4(qh[mt], q_lane[mt] + ks * 32);
                #pragma unroll
                for (int kb = 0; kb < 4; kb++) {
                    uint32_t kh[4];
                    ldsm4(kh, stg + (kb * 16 + b_row) * SROW + ks * 32 + b_kbit * 16);
                    #pragma unroll
                    for (int mt = 0; mt < 2; mt++) {
                        mma_fp16(sc[mt][2 * kb],     qh[mt], kh[0], kh[1]);
                        mma_fp16(sc[mt][2 * kb + 1], qh[mt], kh[2], kh[3]);
                    }
                }
            }

            // ---- causal mask ----
            if (kv0 + 63 > warp_rmin) {
                #pragma unroll
                for (int mt = 0; mt < 2; mt++)
                    #pragma unroll
                    for (int nj = 0; nj < 8; nj++) {
                        const int col = kv0 + nj * 8 + 2 * (lane & 3);
                        if (col     > rl[mt])     sc[mt][nj][0] = NEGBIG;
                        if (col + 1 > rl[mt])     sc[mt][nj][1] = NEGBIG;
                        if (col     > rl[mt] + 8) sc[mt][nj][2] = NEGBIG;
                        if (col + 1 > rl[mt] + 8) sc[mt][nj][3] = NEGBIG;
                    }
            }

            // ---- row max (quad reduce), rescale o/l ----
            float mn0[2], mn1[2];
            #pragma unroll
            for (int mt = 0; mt < 2; mt++) {
                float mx0 = NEGBIG, mx1 = NEGBIG;
                #pragma unroll
                for (int nj = 0; nj < 8; nj++) {
                    mx0 = fmaxf(mx0, fmaxf(sc[mt][nj][0], sc[mt][nj][1]));
                    mx1 = fmaxf(mx1, fmaxf(sc[mt][nj][2], sc[mt][nj][3]));
                }
                mx0 = fmaxf(mx0, __shfl_xor_sync(0xffffffffu, mx0, 1));
                mx0 = fmaxf(mx0, __shfl_xor_sync(0xffffffffu, mx0, 2));
                mx1 = fmaxf(mx1, __shfl_xor_sync(0xffffffffu, mx1, 1));
                mx1 = fmaxf(mx1, __shfl_xor_sync(0xffffffffu, mx1, 2));

                mn0[mt] = fmaxf(m_lo[mt], mx0);
                mn1[mt] = fmaxf(m_hi[mt], mx1);
                const float al0 = ex2(m_lo[mt] - mn0[mt]);
                const float al1 = ex2(m_hi[mt] - mn1[mt]);
                m_lo[mt] = mn0[mt]; m_hi[mt] = mn1[mt];

                #pragma unroll
                for (int dt = 0; dt < 8; dt++) {
                    o[mt][dt][0] *= al0; o[mt][dt][1] *= al0;
                    o[mt][dt][2] *= al1; o[mt][dt][3] *= al1;
                }
                l_lo[mt] *= al0; l_hi[mt] *= al1;
            }

            // ---- p = exp2(s-m) packed single fp16, PV MMAs (V [d][kv]) ----
            #pragma unroll
            for (int ks = 0; ks < 4; ks++) {
                uint32_t pah[2][4];
                #pragma unroll
                for (int mt = 0; mt < 2; mt++) {
                    float s0 = 0.f, s1 = 0.f;
                    #pragma unroll
                    for (int half = 0; half < 2; half++) {
                        const int nj = 2 * ks + half;
                        float p0 = ex2(sc[mt][nj][0] - mn0[mt]);
                        float p1 = ex2(sc[mt][nj][1] - mn0[mt]);
                        float p2 = ex2(sc[mt][nj][2] - mn1[mt]);
                        float p3 = ex2(sc[mt][nj][3] - mn1[mt]);
                        s0 += p0 + p1; s1 += p2 + p3;
                        pah[mt][half * 2]     = h2pack(p0, p1);
                        pah[mt][half * 2 + 1] = h2pack(p2, p3);
                    }
                    l_lo[mt] += s0; l_hi[mt] += s1;
                }

                #pragma unroll
                for (int db = 0; db < 4; db++) {
                    uint32_t vh[4];
                    ldsm4(vh, stg + T_OFF + (db * 16 + b_row) * SROW +
                              ks * 32 + b_kbit * 16);
                    #pragma unroll
                    for (int mt = 0; mt < 2; mt++) {
                        mma_fp16(o[mt][2 * db],     pah[mt], vh[0], vh[1]);
                        mma_fp16(o[mt][2 * db + 1], pah[mt], vh[2], vh[3]);
                    }
                }
            }
        }
    }

    // ---- l is per-thread partial over its columns; quad-reduce for the
    // full row sum (m/alpha already quad-uniform, so this is exact) ----
    #pragma unroll
    for (int mt = 0; mt < 2; mt++) {
        l_lo[mt] += __shfl_xor_sync(0xffffffffu, l_lo[mt], 1);
        l_lo[mt] += __shfl_xor_sync(0xffffffffu, l_lo[mt], 2);
        l_hi[mt] += __shfl_xor_sync(0xffffffffu, l_hi[mt], 1);
        l_hi[mt] += __shfl_xor_sync(0xffffffffu, l_hi[mt], 2);
    }

    // ---- epilogue: normalize, fp16 hi/lo split into g_ah/g_al ----
    #pragma unroll
    for (int mt = 0; mt < 2; mt++) {
        const float inv0 = 1.f / l_lo[mt];
        const float inv1 = 1.f / l_hi[mt];
        #pragma unroll
        for (int dt = 0; dt < 8; dt++) {
            const int c = h * HDIM + dt * 8 + 2 * (lane & 3);
            uint32_t hi, lo;
            h2split2(o[mt][dt][0] * inv0, o[mt][dt][1] * inv0, hi, lo);
            size_t off = ((size_t)(b * SEQ + rl[mt])) * DIM + c;
            *(uint32_t*)&g_ah[off] = hi;
            *(uint32_t*)&g_al[off] = lo;
            h2split2(o[mt][dt][2] * inv1, o[mt][dt][3] * inv1, hi, lo);
            off = ((size_t)(b * SEQ + rl[mt] + 8)) * DIM + c;
            *(uint32_t*)&g_ah[off] = hi;
            *(uint32_t*)&g_al[off] = lo;
        }
    }
}

// ============================================================
extern "C" void kernel_launch(void* const* d_in, const int* in_sizes, int n_in,
                              void* d_out, int out_size)
{
    const float* x      = (const float*)d_in[0];
    const float* w_qkv  = (const float*)d_in[1];
    const float* w_proj = (const float*)d_in[2];
    const float* b_proj = (const float*)d_in[3];
    float* out = (float*)d_out;

    // -- preprocess: split x (fp16 hi/lo); transpose weights (fp16 single) --
    {
        __half *xh, *xl, *wqh, *wph;
        cudaGetSymbolAddress((void**)&xh,  g_xh);
        cudaGetSymbolAddress((void**)&xl,  g_xl);
        cudaGetSymbolAddress((void**)&wqh, g_wqh);
        cudaGetSymbolAddress((void**)&wph, g_wph);

        const int n4 = NTOK * DIM / 4;
        convert_split_kernel<<<(n4 + 511) / 512, 512>>>(x, xh, xl, n4);

        dim3 blk(32, 8);
        transpose_h16_kernel<<<dim3(3 * DIM / 32, DIM / 32), blk>>>(
            w_qkv, wqh, DIM, 3 * DIM);
        transpose_h16_kernel<<<dim3(DIM / 32, DIM / 32), blk>>>(
            w_proj, wph, DIM, DIM);
    }

    // -- QKV GEMM (fp16 mma.sync, 1-term, K-chunk 64, cp.async) --
    {
        cudaFuncSetAttribute(qkv_gemm_kernel,
                             cudaFuncAttributeMaxDynamicSharedMemorySize, GEMM_SMEM);
        dim3 grid(3 * DIM / 128, NTOK / 128);
        qkv_gemm_kernel<<<grid, 256, GEMM_SMEM>>>();
    }

    // -- attention (fp16 tensor-core, all-single operands, 3 CTAs/SM) --
    {
        cudaFuncSetAttribute(attn_kernel,
                             cudaFuncAttributeMaxDynamicSharedMemorySize, ATT_SMEM);
        dim3 grid(SEQ / 128, NHEADS, BATCH);
        attn_kernel<<<grid, 128, ATT_SMEM>>>();
    }

    // -- projection GEMM (fp16 2-term, K-chunk 64, cp.async) --
    {
        cudaFuncSetAttribute(proj_gemm_kernel,
                             cudaFuncAttributeMaxDynamicSharedMemorySize, GEMM_SMEM);
        dim3 grid(DIM / 128, NTOK / 128);
        proj_gemm_kernel<<<grid, 256, GEMM_SMEM>>>(b_proj, out);
    }
}

// round 16
// speedup vs baseline: 2.6106x; 1.1242x over previous
#include <cuda_runtime.h>
#include <cuda_fp16.h>
#include <cstdint>

#define DIM     1024
#define NHEADS  16
#define HDIM    64
#define SEQ     2048
#define BATCH   4
#define NTOK    (BATCH * SEQ)          // 8192
// SCALE * log2(e) folded into Q so softmax uses exp2
#define QSCALE  0.18033688011112042f
#define NEGBIG  -1e9f

// -------- scratch (device globals: allocation-free) --------
__device__ __half g_qh[(size_t)BATCH * NHEADS * SEQ * HDIM]; // [B,H,S,D] single
__device__ __half g_kh[(size_t)BATCH * NHEADS * SEQ * HDIM]; // [B,H,S,D] single
__device__ __half g_vh[(size_t)BATCH * NHEADS * HDIM * SEQ]; // [B,H,D,S] single
__device__ __half g_xh[(size_t)NTOK * DIM];                  // x single fp16
__device__ __half g_wqh[(size_t)3 * DIM * DIM];              // w_qkv^T [n][k] single
__device__ __half g_wph[(size_t)DIM * DIM];                  // w_proj^T [n][k] single
__device__ __half g_ah[(size_t)NTOK * DIM];                  // attn out single fp16

// ============================================================
// helpers
// ============================================================
__device__ __forceinline__ uint32_t smem_to_u32(const void* p) {
    uint32_t a;
    asm("{ .reg .u64 t; cvta.to.shared.u64 t, %1; cvt.u32.u64 %0, t; }"
        : "=r"(a) : "l"(p));
    return a;
}

__device__ __forceinline__ uint32_t h2pack(float x, float y) {
    __half2 h = __floats2half2_rn(x, y);
    return *reinterpret_cast<uint32_t*>(&h);
}

__device__ __forceinline__ float ex2(float x) {
    float y;
    asm("ex2.approx.f32 %0, %1;" : "=f"(y) : "f"(x));
    return y;
}

__device__ __forceinline__ void ldsm4(uint32_t r[4], uint32_t addr) {
    asm volatile("ldmatrix.sync.aligned.m8n8.x4.shared.b16 {%0,%1,%2,%3}, [%4];"
        : "=r"(r[0]), "=r"(r[1]), "=r"(r[2]), "=r"(r[3]) : "r"(addr));
}

__device__ __forceinline__ void mma_fp16(float d[4], const uint32_t a[4],
                                         uint32_t b0, uint32_t b1) {
    asm volatile(
        "mma.sync.aligned.m16n8k16.row.col.f32.f16.f16.f32 "
        "{%0,%1,%2,%3}, {%4,%5,%6,%7}, {%8,%9}, {%0,%1,%2,%3};"
        : "+f"(d[0]), "+f"(d[1]), "+f"(d[2]), "+f"(d[3])
        : "r"(a[0]), "r"(a[1]), "r"(a[2]), "r"(a[3]), "r"(b0), "r"(b1));
}

#define CP_ASYNC16(dst, src) \
    asm volatile("cp.async.cg.shared.global [%0], [%1], 16;" \
        :: "r"(dst), "l"(src) : "memory")
#define CP_COMMIT() asm volatile("cp.async.commit_group;" ::: "memory")
#define CP_WAIT(n)  asm volatile("cp.async.wait_group %0;" :: "n"(n) : "memory")

// ============================================================
// Preprocess kernels
// ============================================================
__global__ void convert_h16_kernel(const float* __restrict__ in,
                                   __half* __restrict__ out, int n4)
{
    const int i = blockIdx.x * blockDim.x + threadIdx.x;
    if (i >= n4) return;
    float4 v = ((const float4*)in)[i];
    ((uint2*)out)[i] = make_uint2(h2pack(v.x, v.y), h2pack(v.z, v.w));
}

// in [K][N] fp32 -> out [N][K] single fp16
__global__ void transpose_h16_kernel(const float* __restrict__ in,
                                     __half* __restrict__ outT, int K, int N)
{
    __shared__ float t[32][33];
    const int tx = threadIdx.x, ty = threadIdx.y;
    const int k0 = blockIdx.y * 32, n0 = blockIdx.x * 32;
    #pragma unroll
    for (int j = 0; j < 4; j++)
        t[ty + j * 8][tx] = in[(size_t)(k0 + ty + j * 8) * N + n0 + tx];
    __syncthreads();
    #pragma unroll
    for (int j = 0; j < 4; j++) {
        const int nn = n0 + ty + j * 8;
        const int kk = k0 + tx;
        outT[(size_t)nn * K + kk] = __float2half(t[tx][ty + j * 8]);
    }
}

// ============================================================
// fp16 mma.sync GEMM (1-term): CTA 128x128, 256 threads (8 warps, 64x32),
// K=1024 in 16 chunks of 64, 2-stage cp.async, 144B padded rows, 2 CTAs/SM.
// Tiles per stage: A, B.
// ============================================================
#define TILE_BYTES 18432            // 128 rows * 144 B (128B data + 16B pad)
#define BUF_BYTES  (2 * TILE_BYTES) // A, B = 36864
#define GEMM_SMEM  (2 * BUF_BYTES)  // 73728
#define NCHUNK     16               // K-chunk = 64

__device__ __forceinline__ void gemm_issue_chunk(
    const __half* const gb[2], uint32_t dstbuf, int tid, int c)
{
    #pragma unroll
    for (int i = 0; i < 8; i++) {
        const int s    = tid + i * 256;
        const int tile = s >> 10;         // 1024 segments per tile
        const int t2   = s & 1023;
        const int row  = t2 >> 3;
        const int kg   = t2 & 7;
        const __half* src = gb[tile] + (size_t)row * DIM + c * 64 + kg * 8;
        const uint32_t dst = dstbuf + tile * TILE_BYTES + row * 144 + kg * 16;
        CP_ASYNC16(dst, src);
    }
    CP_COMMIT();
}

__device__ __forceinline__ void gemm_mainloop(
    const __half* __restrict__ A, const __half* __restrict__ B,
    float acc[4][4][4], char* smem)
{
    const uint32_t smem_base = smem_to_u32(smem);
    const int tid  = threadIdx.x;
    const int lane = tid & 31;
    const int wid  = tid >> 5;        // 0..7
    const int wr   = wid >> 2;        // 0..1 -> 64 rows each
    const int wc   = wid & 3;         // 0..3 -> 32 cols each
    const int m0   = blockIdx.y * 128;
    const int n0   = blockIdx.x * 128;

    const __half* gb[2] = { A + (size_t)m0 * DIM, B + (size_t)n0 * DIM };

    const int arow = (lane & 7) + ((lane >> 3) & 1) * 8;
    const int acol = ((lane >> 4) & 1) * 16;
    const int brow = (lane & 7) + ((lane >> 4) & 1) * 8;
    const int bcol = ((lane >> 3) & 1) * 16;

    const uint32_t a_lane = (uint32_t)((wr * 64 + arow) * 144 + acol);
    const uint32_t b_lane = (uint32_t)(TILE_BYTES + (wc * 32 + brow) * 144 + bcol);

    gemm_issue_chunk(gb, smem_base, tid, 0);

    for (int c = 0; c < NCHUNK; c++) {
        const uint32_t buf = smem_base + (uint32_t)(c & 1) * BUF_BYTES;

        if (c + 1 < NCHUNK) {
            gemm_issue_chunk(gb, smem_base + (uint32_t)((c + 1) & 1) * BUF_BYTES,
                             tid, c + 1);
            CP_WAIT(1);
        } else {
            CP_WAIT(0);
        }
        __syncthreads();

        #pragma unroll
        for (int ks = 0; ks < 4; ks++) {
            uint32_t bh2[2][4];
            #pragma unroll
            for (int nt = 0; nt < 2; nt++)
                ldsm4(bh2[nt], buf + b_lane + nt * 16 * 144 + ks * 32);
            #pragma unroll
            for (int mt = 0; mt < 4; mt++) {
                uint32_t ah[4];
                ldsm4(ah, buf + a_lane + mt * 16 * 144 + ks * 32);
                #pragma unroll
                for (int nj = 0; nj < 4; nj++) {
                    const uint32_t b0 = bh2[nj >> 1][(nj & 1) * 2];
                    const uint32_t b1 = bh2[nj >> 1][(nj & 1) * 2 + 1];
                    mma_fp16(acc[mt][nj], ah, b0, b1);
                }
            }
        }
        __syncthreads();   // all warps done reading buf before it is refilled
    }
}

// ============================================================
// Kernel 1: qkv GEMM -> Q/K single fp16 [B,H,S,D] (Q pre-scaled),
//           V single fp16 TRANSPOSED [B,H,D,S].
// ============================================================
__global__ void __launch_bounds__(256, 2)
qkv_gemm_kernel()
{
    extern __shared__ __align__(16) char smem[];
    float acc[4][4][4] = {};
    gemm_mainloop(g_xh, g_wqh, acc, smem);

    const int lane = threadIdx.x & 31;
    const int wid  = threadIdx.x >> 5;
    const int wr   = wid >> 2, wc = wid & 3;
    const int m_base = blockIdx.y * 128 + wr * 64;
    const int n_base = blockIdx.x * 128 + wc * 32;

    #pragma unroll
    for (int mt = 0; mt < 4; mt++) {
        #pragma unroll
        for (int nj = 0; nj < 4; nj++) {
            const int n = n_base + nj * 8 + (lane & 3) * 2;
            const int three = n >> 10;
            const int h = (n >> 6) & 15;
            const int d = n & 63;
            #pragma unroll
            for (int rs = 0; rs < 2; rs++) {
                const int m = m_base + mt * 16 + (lane >> 2) + rs * 8;
                const int b = m >> 11;
                const int s = m & 2047;
                const float x0 = acc[mt][nj][rs * 2];
                const float x1 = acc[mt][nj][rs * 2 + 1];
                if (three == 2) {
                    const size_t tb = ((size_t)(b * NHEADS + h)) * HDIM * SEQ;
                    g_vh[tb + (size_t)d * SEQ + s]       = __float2half(x0);
                    g_vh[tb + (size_t)(d + 1) * SEQ + s] = __float2half(x1);
                } else {
                    __half* dst = (three == 0) ? g_qh : g_kh;
                    const float sc = (three == 0) ? QSCALE : 1.0f;
                    const size_t idx = (((size_t)(b * NHEADS + h)) * SEQ + s) * HDIM + d;
                    *(uint32_t*)&dst[idx] = h2pack(x0 * sc, x1 * sc);
                }
            }
        }
    }
}

// ============================================================
// Kernel 3: out = attn @ w_proj + bias (1-term)
// ============================================================
__global__ void __launch_bounds__(256, 2)
proj_gemm_kernel(const float* __restrict__ bias, float* __restrict__ out)
{
    extern __shared__ __align__(16) char smem[];
    float acc[4][4][4] = {};
    gemm_mainloop(g_ah, g_wph, acc, smem);

    const int lane = threadIdx.x & 31;
    const int wid  = threadIdx.x >> 5;
    const int wr   = wid >> 2, wc = wid & 3;
    const int m_base = blockIdx.y * 128 + wr * 64;
    const int n_base = blockIdx.x * 128 + wc * 32;

    #pragma unroll
    for (int mt = 0; mt < 4; mt++) {
        #pragma unroll
        for (int nj = 0; nj < 4; nj++) {
            const int n = n_base + nj * 8 + (lane & 3) * 2;
            const float2 bv = *(const float2*)&bias[n];
            #pragma unroll
            for (int rs = 0; rs < 2; rs++) {
                const int m = m_base + mt * 16 + (lane >> 2) + rs * 8;
                float2 v = make_float2(acc[mt][nj][rs * 2] + bv.x,
                                       acc[mt][nj][rs * 2 + 1] + bv.y);
                *(float2*)&out[(size_t)m * DIM + n] = v;
            }
        }
    }
}

// ============================================================
// Kernel 2: tensor-core causal flash attention, warp tile M=32,
// all operands single fp16, cp.async double-buffered K/V.
// 3 CTAs/SM, 128 threads. Epilogue writes single fp16.
// ============================================================
#define SROW     144                 // smem row stride (64 fp16 = 128B + 16 pad)
#define QH_OFF   0
#define KV_BASE  (128 * SROW)        // 18432
#define T_OFF    (64 * SROW)         // 9216 per tile (kh, vh)
#define KV_STAGE (2 * T_OFF)         // 18432 per stage
#define ATT_SMEM (KV_BASE + 2 * KV_STAGE)   // 55296

__device__ __forceinline__ void attn_issue_kv(uint32_t dstbase, size_t bh,
                                              int kv0, int tid)
{
    #pragma unroll
    for (int j = 0; j < 8; j++) {
        const int i = tid + j * 128;      // 0..1023
        const int arr = i >> 9;           // 0 kh, 1 vh
        const int t   = i & 511;
        const int row = t >> 3, ch = t & 7;
        const __half* src = (arr == 0)
            ? &g_kh[bh + (size_t)(kv0 + row) * HDIM + ch * 8]
            : &g_vh[bh + (size_t)row * SEQ + kv0 + ch * 8];
        const uint32_t dst = dstbase + arr * T_OFF + row * SROW + ch * 16;
        CP_ASYNC16(dst, src);
    }
    CP_COMMIT();
}

__global__ void __launch_bounds__(128, 3) attn_kernel()
{
    extern __shared__ __align__(16) char sm[];
    const uint32_t sbase = smem_to_u32(sm);

    const int tid  = threadIdx.x;
    const int lane = tid & 31;
    const int w    = tid >> 5;                     // 0..3
    const int qt   = gridDim.x - 1 - blockIdx.x;   // big tiles first
    const int h    = blockIdx.y;
    const int b    = blockIdx.z;
    const int q0   = qt * 128;
    const size_t bh = ((size_t)(b * NHEADS + h)) * SEQ * HDIM;

    const int nkv = 2 * qt + 2;

    attn_issue_kv(sbase + KV_BASE, bh, 0, tid);

    // ---- load Q tile (single fp16; one-time) ----
    #pragma unroll
    for (int j = 0; j < 8; j++) {
        const int i = tid + j * 128;          // 0..1023
        const int row = i >> 3, ch = i & 7;
        uint4 v = *(const uint4*)&g_qh[bh + (size_t)(q0 + row) * HDIM + ch * 8];
        *(uint4*)(sm + QH_OFF + row * SROW + ch * 16) = v;
    }

    const int a_row  = (lane & 7) + ((lane >> 3) & 1) * 8;
    const int a_kbit = (lane >> 4) & 1;
    uint32_t q_lane[2];
    #pragma unroll
    for (int mt = 0; mt < 2; mt++)
        q_lane[mt] = sbase + QH_OFF + (w * 32 + mt * 16 + a_row) * SROW + a_kbit * 16;
    const int b_row  = (lane & 7) + ((lane >> 4) & 1) * 8;
    const int b_kbit = (lane >> 3) & 1;

    int rl[2];
    rl[0] = q0 + w * 32 + (lane >> 2);
    rl[1] = rl[0] + 16;
    const int warp_rmin = q0 + w * 32;
    const int warp_rmax = warp_rmin + 31;

    float o[2][8][4];
    #pragma unroll
    for (int mt = 0; mt < 2; mt++)
        #pragma unroll
        for (int i = 0; i < 8; i++)
            #pragma unroll
            for (int j = 0; j < 4; j++) o[mt][i][j] = 0.f;
    float m_lo[2] = {NEGBIG, NEGBIG}, m_hi[2] = {NEGBIG, NEGBIG};
    float l_lo[2] = {0.f, 0.f},       l_hi[2] = {0.f, 0.f};

    for (int kt = 0; kt < nkv; kt++) {
        const int kv0 = kt * 64;

        CP_WAIT(0);
        __syncthreads();

        if (kt + 1 < nkv)
            attn_issue_kv(sbase + KV_BASE + (uint32_t)((kt + 1) & 1) * KV_STAGE,
                          bh, kv0 + 64, tid);

        const uint32_t stg = sbase + KV_BASE + (uint32_t)(kt & 1) * KV_STAGE;

        if (kv0 <= warp_rmax) {
            // ---- S = Q K^T ----
            float sc[2][8][4];
            #pragma unroll
            for (int mt = 0; mt < 2; mt++)
                #pragma unroll
                for (int i = 0; i < 8; i++)
                    #pragma unroll
                    for (int j = 0; j < 4; j++) sc[mt][i][j] = 0.f;

            #pragma unroll
            for (int ks = 0; ks < 4; ks++) {
                uint32_t qh[2][4];
                #pragma unroll
                for (int mt = 0; mt < 2; mt++)
                    ldsm4(qh[mt], q_lane[mt] + ks * 32);
                #pragma unroll
                for (int kb = 0; kb < 4; kb++) {
                    uint32_t kh[4];
                    ldsm4(kh, stg + (kb * 16 + b_row) * SROW + ks * 32 + b_kbit * 16);
                    #pragma unroll
                    for (int mt = 0; mt < 2; mt++) {
                        mma_fp16(sc[mt][2 * kb],     qh[mt], kh[0], kh[1]);
                        mma_fp16(sc[mt][2 * kb + 1], qh[mt], kh[2], kh[3]);
                    }
                }
            }

            // ---- causal mask ----
            if (kv0 + 63 > warp_rmin) {
                #pragma unroll
                for (int mt = 0; mt < 2; mt++)
                    #pragma unroll
                    for (int nj = 0; nj < 8; nj++) {
                        const int col = kv0 + nj * 8 + 2 * (lane & 3);
                        if (col     > rl[mt])     sc[mt][nj][0] = NEGBIG;
                        if (col + 1 > rl[mt])     sc[mt][nj][1] = NEGBIG;
                        if (col     > rl[mt] + 8) sc[mt][nj][2] = NEGBIG;
                        if (col + 1 > rl[mt] + 8) sc[mt][nj][3] = NEGBIG;
                    }
            }

            // ---- row max (quad reduce), rescale o/l ----
            float mn0[2], mn1[2];
            #pragma unroll
            for (int mt = 0; mt < 2; mt++) {
                float mx0 = NEGBIG, mx1 = NEGBIG;
                #pragma unroll
                for (int nj = 0; nj < 8; nj++) {
                    mx0 = fmaxf(mx0, fmaxf(sc[mt][nj][0], sc[mt][nj][1]));
                    mx1 = fmaxf(mx1, fmaxf(sc[mt][nj][2], sc[mt][nj][3]));
                }
                mx0 = fmaxf(mx0, __shfl_xor_sync(0xffffffffu, mx0, 1));
                mx0 = fmaxf(mx0, __shfl_xor_sync(0xffffffffu, mx0, 2));
                mx1 = fmaxf(mx1, __shfl_xor_sync(0xffffffffu, mx1, 1));
                mx1 = fmaxf(mx1, __shfl_xor_sync(0xffffffffu, mx1, 2));

                mn0[mt] = fmaxf(m_lo[mt], mx0);
                mn1[mt] = fmaxf(m_hi[mt], mx1);
                const float al0 = ex2(m_lo[mt] - mn0[mt]);
                const float al1 = ex2(m_hi[mt] - mn1[mt]);
                m_lo[mt] = mn0[mt]; m_hi[mt] = mn1[mt];

                #pragma unroll
                for (int dt = 0; dt < 8; dt++) {
                    o[mt][dt][0] *= al0; o[mt][dt][1] *= al0;
                    o[mt][dt][2] *= al1; o[mt][dt][3] *= al1;
                }
                l_lo[mt] *= al0; l_hi[mt] *= al1;
            }

            // ---- p = exp2(s-m) packed single fp16, PV MMAs (V [d][kv]) ----
            #pragma unroll
            for (int ks = 0; ks < 4; ks++) {
                uint32_t pah[2][4];
                #pragma unroll
                for (int mt = 0; mt < 2; mt++) {
                    float s0 = 0.f, s1 = 0.f;
                    #pragma unroll
                    for (int half = 0; half < 2; half++) {
                        const int nj = 2 * ks + half;
                        float p0 = ex2(sc[mt][nj][0] - mn0[mt]);
                        float p1 = ex2(sc[mt][nj][1] - mn0[mt]);
                        float p2 = ex2(sc[mt][nj][2] - mn1[mt]);
                        float p3 = ex2(sc[mt][nj][3] - mn1[mt]);
                        s0 += p0 + p1; s1 += p2 + p3;
                        pah[mt][half * 2]     = h2pack(p0, p1);
                        pah[mt][half * 2 + 1] = h2pack(p2, p3);
                    }
                    l_lo[mt] += s0; l_hi[mt] += s1;
                }

                #pragma unroll
                for (int db = 0; db < 4; db++) {
                    uint32_t vh[4];
                    ldsm4(vh, stg + T_OFF + (db * 16 + b_row) * SROW +
                              ks * 32 + b_kbit * 16);
                    #pragma unroll
                    for (int mt = 0; mt < 2; mt++) {
                        mma_fp16(o[mt][2 * db],     pah[mt], vh[0], vh[1]);
                        mma_fp16(o[mt][2 * db + 1], pah[mt], vh[2], vh[3]);
                    }
                }
            }
        }
    }

    // ---- l is per-thread partial over its columns; quad-reduce for the
    // full row sum (m/alpha already quad-uniform, so this is exact) ----
    #pragma unroll
    for (int mt = 0; mt < 2; mt++) {
        l_lo[mt] += __shfl_xor_sync(0xffffffffu, l_lo[mt], 1);
        l_lo[mt] += __shfl_xor_sync(0xffffffffu, l_lo[mt], 2);
        l_hi[mt] += __shfl_xor_sync(0xffffffffu, l_hi[mt], 1);
        l_hi[mt] += __shfl_xor_sync(0xffffffffu, l_hi[mt], 2);
    }

    // ---- epilogue: normalize, single fp16 into g_ah ----
    #pragma unroll
    for (int mt = 0; mt < 2; mt++) {
        const float inv0 = 1.f / l_lo[mt];
        const float inv1 = 1.f / l_hi[mt];
        #pragma unroll
        for (int dt = 0; dt < 8; dt++) {
            const int c = h * HDIM + dt * 8 + 2 * (lane & 3);
            size_t off = ((size_t)(b * SEQ + rl[mt])) * DIM + c;
            *(uint32_t*)&g_ah[off] =
                h2pack(o[mt][dt][0] * inv0, o[mt][dt][1] * inv0);
            off = ((size_t)(b * SEQ + rl[mt] + 8)) * DIM + c;
            *(uint32_t*)&g_ah[off] =
                h2pack(o[mt][dt][2] * inv1, o[mt][dt][3] * inv1);
        }
    }
}

// ============================================================
extern "C" void kernel_launch(void* const* d_in, const int* in_sizes, int n_in,
                              void* d_out, int out_size)
{
    const float* x      = (const float*)d_in[0];
    const float* w_qkv  = (const float*)d_in[1];
    const float* w_proj = (const float*)d_in[2];
    const float* b_proj = (const float*)d_in[3];
    float* out = (float*)d_out;

    // -- preprocess: x -> single fp16; transpose weights (fp16 single) --
    {
        __half *xh, *wqh, *wph;
        cudaGetSymbolAddress((void**)&xh,  g_xh);
        cudaGetSymbolAddress((void**)&wqh, g_wqh);
        cudaGetSymbolAddress((void**)&wph, g_wph);

        const int n4 = NTOK * DIM / 4;
        convert_h16_kernel<<<(n4 + 511) / 512, 512>>>(x, xh, n4);

        dim3 blk(32, 8);
        transpose_h16_kernel<<<dim3(3 * DIM / 32, DIM / 32), blk>>>(
            w_qkv, wqh, DIM, 3 * DIM);
        transpose_h16_kernel<<<dim3(DIM / 32, DIM / 32), blk>>>(
            w_proj, wph, DIM, DIM);
    }

    // -- QKV GEMM (fp16 mma.sync, 1-term, K-chunk 64, cp.async) --
    {
        cudaFuncSetAttribute(qkv_gemm_kernel,
                             cudaFuncAttributeMaxDynamicSharedMemorySize, GEMM_SMEM);
        dim3 grid(3 * DIM / 128, NTOK / 128);
        qkv_gemm_kernel<<<grid, 256, GEMM_SMEM>>>();
    }

    // -- attention (fp16 tensor-core, all-single operands, 3 CTAs/SM) --
    {
        cudaFuncSetAttribute(attn_kernel,
                             cudaFuncAttributeMaxDynamicSharedMemorySize, ATT_SMEM);
        dim3 grid(SEQ / 128, NHEADS, BATCH);
        attn_kernel<<<grid, 128, ATT_SMEM>>>();
    }

    // -- projection GEMM (fp16 1-term, K-chunk 64, cp.async) --
    {
        cudaFuncSetAttribute(proj_gemm_kernel,
                             cudaFuncAttributeMaxDynamicSharedMemorySize, GEMM_SMEM);
        dim3 grid(DIM / 128, NTOK / 128);
        proj_gemm_kernel<<<grid, 256, GEMM_SMEM>>>(b_proj, out);
    }
}

// round 17
// speedup vs baseline: 2.6944x; 1.0321x over previous
#include <cuda_runtime.h>
#include <cuda_fp16.h>
#include <cstdint>

#define DIM     1024
#define NHEADS  16
#define HDIM    64
#define SEQ     2048
#define BATCH   4
#define NTOK    (BATCH * SEQ)          // 8192
// SCALE * log2(e) folded into Q so softmax uses exp2
#define QSCALE  0.18033688011112042f
#define NEGBIG  -1e9f

// -------- scratch (device globals: allocation-free) --------
__device__ __half g_qh[(size_t)BATCH * NHEADS * SEQ * HDIM]; // [B,H,S,D] single
__device__ __half g_kh[(size_t)BATCH * NHEADS * SEQ * HDIM]; // [B,H,S,D] single
__device__ __half g_vh[(size_t)BATCH * NHEADS * HDIM * SEQ]; // [B,H,D,S] single
__device__ __half g_xh[(size_t)NTOK * DIM];                  // x single fp16
__device__ __half g_wqh[(size_t)3 * DIM * DIM];              // w_qkv^T [n][k] single
__device__ __half g_wph[(size_t)DIM * DIM];                  // w_proj^T [n][k] single
__device__ __half g_ah[(size_t)NTOK * DIM];                  // attn out single fp16

// ============================================================
// helpers
// ============================================================
__device__ __forceinline__ uint32_t smem_to_u32(const void* p) {
    uint32_t a;
    asm("{ .reg .u64 t; cvta.to.shared.u64 t, %1; cvt.u32.u64 %0, t; }"
        : "=r"(a) : "l"(p));
    return a;
}

__device__ __forceinline__ uint32_t h2pack(float x, float y) {
    __half2 h = __floats2half2_rn(x, y);
    return *reinterpret_cast<uint32_t*>(&h);
}

__device__ __forceinline__ float ex2(float x) {
    float y;
    asm("ex2.approx.f32 %0, %1;" : "=f"(y) : "f"(x));
    return y;
}

// packed fp16x2 exp2 (one MUFU op for two lanes)
__device__ __forceinline__ uint32_t h2exp2(uint32_t x) {
    uint32_t y;
    asm("ex2.approx.f16x2 %0, %1;" : "=r"(y) : "r"(x));
    return y;
}

__device__ __forceinline__ void ldsm4(uint32_t r[4], uint32_t addr) {
    asm volatile("ldmatrix.sync.aligned.m8n8.x4.shared.b16 {%0,%1,%2,%3}, [%4];"
        : "=r"(r[0]), "=r"(r[1]), "=r"(r[2]), "=r"(r[3]) : "r"(addr));
}

__device__ __forceinline__ void mma_fp16(float d[4], const uint32_t a[4],
                                         uint32_t b0, uint32_t b1) {
    asm volatile(
        "mma.sync.aligned.m16n8k16.row.col.f32.f16.f16.f32 "
        "{%0,%1,%2,%3}, {%4,%5,%6,%7}, {%8,%9}, {%0,%1,%2,%3};"
        : "+f"(d[0]), "+f"(d[1]), "+f"(d[2]), "+f"(d[3])
        : "r"(a[0]), "r"(a[1]), "r"(a[2]), "r"(a[3]), "r"(b0), "r"(b1));
}

#define CP_ASYNC16(dst, src) \
    asm volatile("cp.async.cg.shared.global [%0], [%1], 16;" \
        :: "r"(dst), "l"(src) : "memory")
#define CP_COMMIT() asm volatile("cp.async.commit_group;" ::: "memory")
#define CP_WAIT(n)  asm volatile("cp.async.wait_group %0;" :: "n"(n) : "memory")

// ============================================================
// Preprocess kernels
// ============================================================
__global__ void convert_h16_kernel(const float* __restrict__ in,
                                   __half* __restrict__ out, int n4)
{
    const int i = blockIdx.x * blockDim.x + threadIdx.x;
    if (i >= n4) return;
    float4 v = ((const float4*)in)[i];
    ((uint2*)out)[i] = make_uint2(h2pack(v.x, v.y), h2pack(v.z, v.w));
}

// in [K][N] fp32 -> out [N][K] single fp16
__global__ void transpose_h16_kernel(const float* __restrict__ in,
                                     __half* __restrict__ outT, int K, int N)
{
    __shared__ float t[32][33];
    const int tx = threadIdx.x, ty = threadIdx.y;
    const int k0 = blockIdx.y * 32, n0 = blockIdx.x * 32;
    #pragma unroll
    for (int j = 0; j < 4; j++)
        t[ty + j * 8][tx] = in[(size_t)(k0 + ty + j * 8) * N + n0 + tx];
    __syncthreads();
    #pragma unroll
    for (int j = 0; j < 4; j++) {
        const int nn = n0 + ty + j * 8;
        const int kk = k0 + tx;
        outT[(size_t)nn * K + kk] = __float2half(t[tx][ty + j * 8]);
    }
}

// ============================================================
// fp16 mma.sync GEMM (1-term): CTA 128x128, 256 threads (8 warps, 64x32),
// K=1024 in 16 chunks of 64, 2-stage cp.async, 144B padded rows, 2 CTAs/SM.
// ============================================================
#define TILE_BYTES 18432            // 128 rows * 144 B (128B data + 16B pad)
#define BUF_BYTES  (2 * TILE_BYTES) // A, B = 36864
#define GEMM_SMEM  (2 * BUF_BYTES)  // 73728
#define NCHUNK     16               // K-chunk = 64

__device__ __forceinline__ void gemm_issue_chunk(
    const __half* const gb[2], uint32_t dstbuf, int tid, int c)
{
    #pragma unroll
    for (int i = 0; i < 8; i++) {
        const int s    = tid + i * 256;
        const int tile = s >> 10;         // 1024 segments per tile
        const int t2   = s & 1023;
        const int row  = t2 >> 3;
        const int kg   = t2 & 7;
        const __half* src = gb[tile] + (size_t)row * DIM + c * 64 + kg * 8;
        const uint32_t dst = dstbuf + tile * TILE_BYTES + row * 144 + kg * 16;
        CP_ASYNC16(dst, src);
    }
    CP_COMMIT();
}

__device__ __forceinline__ void gemm_mainloop(
    const __half* __restrict__ A, const __half* __restrict__ B,
    float acc[4][4][4], char* smem)
{
    const uint32_t smem_base = smem_to_u32(smem);
    const int tid  = threadIdx.x;
    const int lane = tid & 31;
    const int wid  = tid >> 5;        // 0..7
    const int wr   = wid >> 2;        // 0..1 -> 64 rows each
    const int wc   = wid & 3;         // 0..3 -> 32 cols each
    const int m0   = blockIdx.y * 128;
    const int n0   = blockIdx.x * 128;

    const __half* gb[2] = { A + (size_t)m0 * DIM, B + (size_t)n0 * DIM };

    const int arow = (lane & 7) + ((lane >> 3) & 1) * 8;
    const int acol = ((lane >> 4) & 1) * 16;
    const int brow = (lane & 7) + ((lane >> 4) & 1) * 8;
    const int bcol = ((lane >> 3) & 1) * 16;

    const uint32_t a_lane = (uint32_t)((wr * 64 + arow) * 144 + acol);
    const uint32_t b_lane = (uint32_t)(TILE_BYTES + (wc * 32 + brow) * 144 + bcol);

    gemm_issue_chunk(gb, smem_base, tid, 0);

    for (int c = 0; c < NCHUNK; c++) {
        const uint32_t buf = smem_base + (uint32_t)(c & 1) * BUF_BYTES;

        if (c + 1 < NCHUNK) {
            gemm_issue_chunk(gb, smem_base + (uint32_t)((c + 1) & 1) * BUF_BYTES,
                             tid, c + 1);
            CP_WAIT(1);
        } else {
            CP_WAIT(0);
        }
        __syncthreads();

        #pragma unroll
        for (int ks = 0; ks < 4; ks++) {
            uint32_t bh2[2][4];
            #pragma unroll
            for (int nt = 0; nt < 2; nt++)
                ldsm4(bh2[nt], buf + b_lane + nt * 16 * 144 + ks * 32);
            #pragma unroll
            for (int mt = 0; mt < 4; mt++) {
                uint32_t ah[4];
                ldsm4(ah, buf + a_lane + mt * 16 * 144 + ks * 32);
                #pragma unroll
                for (int nj = 0; nj < 4; nj++) {
                    const uint32_t b0 = bh2[nj >> 1][(nj & 1) * 2];
                    const uint32_t b1 = bh2[nj >> 1][(nj & 1) * 2 + 1];
                    mma_fp16(acc[mt][nj], ah, b0, b1);
                }
            }
        }
        __syncthreads();   // all warps done reading buf before it is refilled
    }
}

// ============================================================
// Kernel 1: qkv GEMM -> Q/K single fp16 [B,H,S,D] (Q pre-scaled),
//           V single fp16 TRANSPOSED [B,H,D,S].
// ============================================================
__global__ void __launch_bounds__(256, 2)
qkv_gemm_kernel()
{
    extern __shared__ __align__(16) char smem[];
    float acc[4][4][4] = {};
    gemm_mainloop(g_xh, g_wqh, acc, smem);

    const int lane = threadIdx.x & 31;
    const int wid  = threadIdx.x >> 5;
    const int wr   = wid >> 2, wc = wid & 3;
    const int m_base = blockIdx.y * 128 + wr * 64;
    const int n_base = blockIdx.x * 128 + wc * 32;

    #pragma unroll
    for (int mt = 0; mt < 4; mt++) {
        #pragma unroll
        for (int nj = 0; nj < 4; nj++) {
            const int n = n_base + nj * 8 + (lane & 3) * 2;
            const int three = n >> 10;
            const int h = (n >> 6) & 15;
            const int d = n & 63;
            #pragma unroll
            for (int rs = 0; rs < 2; rs++) {
                const int m = m_base + mt * 16 + (lane >> 2) + rs * 8;
                const int b = m >> 11;
                const int s = m & 2047;
                const float x0 = acc[mt][nj][rs * 2];
                const float x1 = acc[mt][nj][rs * 2 + 1];
                if (three == 2) {
                    const size_t tb = ((size_t)(b * NHEADS + h)) * HDIM * SEQ;
                    g_vh[tb + (size_t)d * SEQ + s]       = __float2half(x0);
                    g_vh[tb + (size_t)(d + 1) * SEQ + s] = __float2half(x1);
                } else {
                    __half* dst = (three == 0) ? g_qh : g_kh;
                    const float sc = (three == 0) ? QSCALE : 1.0f;
                    const size_t idx = (((size_t)(b * NHEADS + h)) * SEQ + s) * HDIM + d;
                    *(uint32_t*)&dst[idx] = h2pack(x0 * sc, x1 * sc);
                }
            }
        }
    }
}

// ============================================================
// Kernel 3: out = attn @ w_proj + bias (1-term)
// ============================================================
__global__ void __launch_bounds__(256, 2)
proj_gemm_kernel(const float* __restrict__ bias, float* __restrict__ out)
{
    extern __shared__ __align__(16) char smem[];
    float acc[4][4][4] = {};
    gemm_mainloop(g_ah, g_wph, acc, smem);

    const int lane = threadIdx.x & 31;
    const int wid  = threadIdx.x >> 5;
    const int wr   = wid >> 2, wc = wid & 3;
    const int m_base = blockIdx.y * 128 + wr * 64;
    const int n_base = blockIdx.x * 128 + wc * 32;

    #pragma unroll
    for (int mt = 0; mt < 4; mt++) {
        #pragma unroll
        for (int nj = 0; nj < 4; nj++) {
            const int n = n_base + nj * 8 + (lane & 3) * 2;
            const float2 bv = *(const float2*)&bias[n];
            #pragma unroll
            for (int rs = 0; rs < 2; rs++) {
                const int m = m_base + mt * 16 + (lane >> 2) + rs * 8;
                float2 v = make_float2(acc[mt][nj][rs * 2] + bv.x,
                                       acc[mt][nj][rs * 2 + 1] + bv.y);
                *(float2*)&out[(size_t)m * DIM + n] = v;
            }
        }
    }
}

// ============================================================
// Kernel 2: tensor-core causal flash attention, warp tile M=32,
// all operands single fp16, softmax via ex2.approx.f16x2 (halved MUFU),
// cp.async double-buffered K/V. 3 CTAs/SM, 128 threads.
// ============================================================
#define SROW     144                 // smem row stride (64 fp16 = 128B + 16 pad)
#define QH_OFF   0
#define KV_BASE  (128 * SROW)        // 18432
#define T_OFF    (64 * SROW)         // 9216 per tile (kh, vh)
#define KV_STAGE (2 * T_OFF)         // 18432 per stage
#define ATT_SMEM (KV_BASE + 2 * KV_STAGE)   // 55296

__device__ __forceinline__ void attn_issue_kv(uint32_t dstbase, size_t bh,
                                              int kv0, int tid)
{
    #pragma unroll
    for (int j = 0; j < 8; j++) {
        const int i = tid + j * 128;      // 0..1023
        const int arr = i >> 9;           // 0 kh, 1 vh
        const int t   = i & 511;
        const int row = t >> 3, ch = t & 7;
        const __half* src = (arr == 0)
            ? &g_kh[bh + (size_t)(kv0 + row) * HDIM + ch * 8]
            : &g_vh[bh + (size_t)row * SEQ + kv0 + ch * 8];
        const uint32_t dst = dstbase + arr * T_OFF + row * SROW + ch * 16;
        CP_ASYNC16(dst, src);
    }
    CP_COMMIT();
}

__global__ void __launch_bounds__(128, 3) attn_kernel()
{
    extern __shared__ __align__(16) char sm[];
    const uint32_t sbase = smem_to_u32(sm);

    const int tid  = threadIdx.x;
    const int lane = tid & 31;
    const int w    = tid >> 5;                     // 0..3
    const int qt   = gridDim.x - 1 - blockIdx.x;   // big tiles first
    const int h    = blockIdx.y;
    const int b    = blockIdx.z;
    const int q0   = qt * 128;
    const size_t bh = ((size_t)(b * NHEADS + h)) * SEQ * HDIM;

    const int nkv = 2 * qt + 2;

    attn_issue_kv(sbase + KV_BASE, bh, 0, tid);

    // ---- load Q tile (single fp16; one-time) ----
    #pragma unroll
    for (int j = 0; j < 8; j++) {
        const int i = tid + j * 128;          // 0..1023
        const int row = i >> 3, ch = i & 7;
        uint4 v = *(const uint4*)&g_qh[bh + (size_t)(q0 + row) * HDIM + ch * 8];
        *(uint4*)(sm + QH_OFF + row * SROW + ch * 16) = v;
    }

    const int a_row  = (lane & 7) + ((lane >> 3) & 1) * 8;
    const int a_kbit = (lane >> 4) & 1;
    uint32_t q_lane[2];
    #pragma unroll
    for (int mt = 0; mt < 2; mt++)
        q_lane[mt] = sbase + QH_OFF + (w * 32 + mt * 16 + a_row) * SROW + a_kbit * 16;
    const int b_row  = (lane & 7) + ((lane >> 4) & 1) * 8;
    const int b_kbit = (lane >> 3) & 1;

    int rl[2];
    rl[0] = q0 + w * 32 + (lane >> 2);
    rl[1] = rl[0] + 16;
    const int warp_rmin = q0 + w * 32;
    const int warp_rmax = warp_rmin + 31;

    float o[2][8][4];
    #pragma unroll
    for (int mt = 0; mt < 2; mt++)
        #pragma unroll
        for (int i = 0; i < 8; i++)
            #pragma unroll
            for (int j = 0; j < 4; j++) o[mt][i][j] = 0.f;
    float m_lo[2] = {NEGBIG, NEGBIG}, m_hi[2] = {NEGBIG, NEGBIG};
    float l_lo[2] = {0.f, 0.f},       l_hi[2] = {0.f, 0.f};

    for (int kt = 0; kt < nkv; kt++) {
        const int kv0 = kt * 64;

        CP_WAIT(0);
        __syncthreads();

        if (kt + 1 < nkv)
            attn_issue_kv(sbase + KV_BASE + (uint32_t)((kt + 1) & 1) * KV_STAGE,
                          bh, kv0 + 64, tid);

        const uint32_t stg = sbase + KV_BASE + (uint32_t)(kt & 1) * KV_STAGE;

        if (kv0 <= warp_rmax) {
            // ---- S = Q K^T ----
            float sc[2][8][4];
            #pragma unroll
            for (int mt = 0; mt < 2; mt++)
                #pragma unroll
                for (int i = 0; i < 8; i++)
                    #pragma unroll
                    for (int j = 0; j < 4; j++) sc[mt][i][j] = 0.f;

            #pragma unroll
            for (int ks = 0; ks < 4; ks++) {
                uint32_t qh[2][4];
                #pragma unroll
                for (int mt = 0; mt < 2; mt++)
                    ldsm4(qh[mt], q_lane[mt] + ks * 32);
                #pragma unroll
                for (int kb = 0; kb < 4; kb++) {
                    uint32_t kh[4];
                    ldsm4(kh, stg + (kb * 16 + b_row) * SROW + ks * 32 + b_kbit * 16);
                    #pragma unroll
                    for (int mt = 0; mt < 2; mt++) {
                        mma_fp16(sc[mt][2 * kb],     qh[mt], kh[0], kh[1]);
                        mma_fp16(sc[mt][2 * kb + 1], qh[mt], kh[2], kh[3]);
                    }
                }
            }

            // ---- causal mask ----
            if (kv0 + 63 > warp_rmin) {
                #pragma unroll
                for (int mt = 0; mt < 2; mt++)
                    #pragma unroll
                    for (int nj = 0; nj < 8; nj++) {
                        const int col = kv0 + nj * 8 + 2 * (lane & 3);
                        if (col     > rl[mt])     sc[mt][nj][0] = NEGBIG;
                        if (col + 1 > rl[mt])     sc[mt][nj][1] = NEGBIG;
                        if (col     > rl[mt] + 8) sc[mt][nj][2] = NEGBIG;
                        if (col + 1 > rl[mt] + 8) sc[mt][nj][3] = NEGBIG;
                    }
            }

            // ---- row max (quad reduce), rescale o/l ----
            float mn0[2], mn1[2];
            #pragma unroll
            for (int mt = 0; mt < 2; mt++) {
                float mx0 = NEGBIG, mx1 = NEGBIG;
                #pragma unroll
                for (int nj = 0; nj < 8; nj++) {
                    mx0 = fmaxf(mx0, fmaxf(sc[mt][nj][0], sc[mt][nj][1]));
                    mx1 = fmaxf(mx1, fmaxf(sc[mt][nj][2], sc[mt][nj][3]));
                }
                mx0 = fmaxf(mx0, __shfl_xor_sync(0xffffffffu, mx0, 1));
                mx0 = fmaxf(mx0, __shfl_xor_sync(0xffffffffu, mx0, 2));
                mx1 = fmaxf(mx1, __shfl_xor_sync(0xffffffffu, mx1, 1));
                mx1 = fmaxf(mx1, __shfl_xor_sync(0xffffffffu, mx1, 2));

                mn0[mt] = fmaxf(m_lo[mt], mx0);
                mn1[mt] = fmaxf(m_hi[mt], mx1);
                const float al0 = ex2(m_lo[mt] - mn0[mt]);
                const float al1 = ex2(m_hi[mt] - mn1[mt]);
                m_lo[mt] = mn0[mt]; m_hi[mt] = mn1[mt];

                #pragma unroll
                for (int dt = 0; dt < 8; dt++) {
                    o[mt][dt][0] *= al0; o[mt][dt][1] *= al0;
                    o[mt][dt][2] *= al1; o[mt][dt][3] *= al1;
                }
                l_lo[mt] *= al0; l_hi[mt] *= al1;
            }

            // ---- p = exp2(s-m) via f16x2 MUFU; PV MMAs (V [d][kv]) ----
            #pragma unroll
            for (int ks = 0; ks < 4; ks++) {
                uint32_t pah[2][4];
                #pragma unroll
                for (int mt = 0; mt < 2; mt++) {
                    float s0 = 0.f, s1 = 0.f;
                    #pragma unroll
                    for (int half = 0; half < 2; half++) {
                        const int nj = 2 * ks + half;
                        const uint32_t d0 = h2pack(sc[mt][nj][0] - mn0[mt],
                                                   sc[mt][nj][1] - mn0[mt]);
                        const uint32_t d1 = h2pack(sc[mt][nj][2] - mn1[mt],
                                                   sc[mt][nj][3] - mn1[mt]);
                        const uint32_t p0 = h2exp2(d0);
                        const uint32_t p1 = h2exp2(d1);
                        pah[mt][half * 2]     = p0;
                        pah[mt][half * 2 + 1] = p1;
                        float2 f0 = __half22float2(*(const __half2*)&p0);
                        float2 f1 = __half22float2(*(const __half2*)&p1);
                        s0 += f0.x + f0.y;
                        s1 += f1.x + f1.y;
                    }
                    l_lo[mt] += s0; l_hi[mt] += s1;
                }

                #pragma unroll
                for (int db = 0; db < 4; db++) {
                    uint32_t vh[4];
                    ldsm4(vh, stg + T_OFF + (db * 16 + b_row) * SROW +
                              ks * 32 + b_kbit * 16);
                    #pragma unroll
                    for (int mt = 0; mt < 2; mt++) {
                        mma_fp16(o[mt][2 * db],     pah[mt], vh[0], vh[1]);
                        mma_fp16(o[mt][2 * db + 1], pah[mt], vh[2], vh[3]);
                    }
                }
            }
        }
    }

    // ---- l is per-thread partial over its columns; quad-reduce for the
    // full row sum (m/alpha already quad-uniform, so this is exact) ----
    #pragma unroll
    for (int mt = 0; mt < 2; mt++) {
        l_lo[mt] += __shfl_xor_sync(0xffffffffu, l_lo[mt], 1);
        l_lo[mt] += __shfl_xor_sync(0xffffffffu, l_lo[mt], 2);
        l_hi[mt] += __shfl_xor_sync(0xffffffffu, l_hi[mt], 1);
        l_hi[mt] += __shfl_xor_sync(0xffffffffu, l_hi[mt], 2);
    }

    // ---- epilogue: normalize, single fp16 into g_ah ----
    #pragma unroll
    for (int mt = 0; mt < 2; mt++) {
        const float inv0 = 1.f / l_lo[mt];
        const float inv1 = 1.f / l_hi[mt];
        #pragma unroll
        for (int dt = 0; dt < 8; dt++) {
            const int c = h * HDIM + dt * 8 + 2 * (lane & 3);
            size_t off = ((size_t)(b * SEQ + rl[mt])) * DIM + c;
            *(uint32_t*)&g_ah[off] =
                h2pack(o[mt][dt][0] * inv0, o[mt][dt][1] * inv0);
            off = ((size_t)(b * SEQ + rl[mt] + 8)) * DIM + c;
            *(uint32_t*)&g_ah[off] =
                h2pack(o[mt][dt][2] * inv1, o[mt][dt][3] * inv1);
        }
    }
}

// ============================================================
extern "C" void kernel_launch(void* const* d_in, const int* in_sizes, int n_in,
                              void* d_out, int out_size)
{
    const float* x      = (const float*)d_in[0];
    const float* w_qkv  = (const float*)d_in[1];
    const float* w_proj = (const float*)d_in[2];
    const float* b_proj = (const float*)d_in[3];
    float* out = (float*)d_out;

    // -- preprocess: x -> single fp16; transpose weights (fp16 single) --
    {
        __half *xh, *wqh, *wph;
        cudaGetSymbolAddress((void**)&xh,  g_xh);
        cudaGetSymbolAddress((void**)&wqh, g_wqh);
        cudaGetSymbolAddress((void**)&wph, g_wph);

        const int n4 = NTOK * DIM / 4;
        convert_h16_kernel<<<(n4 + 511) / 512, 512>>>(x, xh, n4);

        dim3 blk(32, 8);
        transpose_h16_kernel<<<dim3(3 * DIM / 32, DIM / 32), blk>>>(
            w_qkv, wqh, DIM, 3 * DIM);
        transpose_h16_kernel<<<dim3(DIM / 32, DIM / 32), blk>>>(
            w_proj, wph, DIM, DIM);
    }

    // -- QKV GEMM (fp16 mma.sync, 1-term, K-chunk 64, cp.async) --
    {
        cudaFuncSetAttribute(qkv_gemm_kernel,
                             cudaFuncAttributeMaxDynamicSharedMemorySize, GEMM_SMEM);
        dim3 grid(3 * DIM / 128, NTOK / 128);
        qkv_gemm_kernel<<<grid, 256, GEMM_SMEM>>>();
    }

    // -- attention (fp16 tensor-core, f16x2 softmax, 3 CTAs/SM) --
    {
        cudaFuncSetAttribute(attn_kernel,
                             cudaFuncAttributeMaxDynamicSharedMemorySize, ATT_SMEM);
        dim3 grid(SEQ / 128, NHEADS, BATCH);
        attn_kernel<<<grid, 128, ATT_SMEM>>>();
    }

    // -- projection GEMM (fp16 1-term, K-chunk 64, cp.async) --
    {
        cudaFuncSetAttribute(proj_gemm_kernel,
                             cudaFuncAttributeMaxDynamicSharedMemorySize, GEMM_SMEM);
        dim3 grid(DIM / 128, NTOK / 128);
        proj_gemm_kernel<<<grid, 256, GEMM_SMEM>>>(b_proj, out);
    }
}